// round 10
// baseline (speedup 1.0000x reference)
#include <cuda_runtime.h>
#include <math.h>

#define B_  2
#define T_  1024
#define D_  1024
#define H_  16
#define HD_ 64
#define FF_ 4096
#define L_  6
#define V_  50257
#define M_  (B_*T_)        // 2048 rows
#define VP_ 50304          // V padded to 128

// ---------------- scratch (static device globals; no allocation) -------------
__device__ float g_h   [M_*D_];
__device__ float g_ln  [M_*D_];
__device__ float g_q   [M_*D_];
__device__ float g_k   [M_*D_];
__device__ float g_v   [M_*D_];
__device__ float g_attn[M_*D_];
__device__ float g_mid [M_*FF_];
// tf32-preconverted weights (row-major [K][N])
__device__ float g_cwq [L_*D_*D_];
__device__ float g_cwk [L_*D_*D_];
__device__ float g_cwv [L_*D_*D_];
__device__ float g_cwo [L_*D_*D_];
__device__ float g_cw1 [L_*D_*FF_];
__device__ float g_cw2 [L_*FF_*D_];
__device__ float g_cpj [(size_t)D_*VP_];

__device__ __forceinline__ float f2tf(float x) {
    unsigned u;
    asm("cvt.rna.tf32.f32 %0, %1;" : "=r"(u) : "f"(x));
    return __uint_as_float(u);
}

// ---------------- single fused weight conversion -------------------------------
// Segments: 0..3 = wq/wk/wv/wo (L*D*D), 4 = ffn_w1 (L*D*FF), 5 = ffn_w2,
// 6 = proj (padded to VP_). blockIdx.y = segment.
__global__ void conv_all(const float4* __restrict__ wq, const float4* __restrict__ wk,
                         const float4* __restrict__ wv, const float4* __restrict__ wo,
                         const float4* __restrict__ w1, const float4* __restrict__ w2,
                         const float*  __restrict__ pj,
                         float4* __restrict__ cwq, float4* __restrict__ cwk,
                         float4* __restrict__ cwv, float4* __restrict__ cwo,
                         float4* __restrict__ cw1, float4* __restrict__ cw2,
                         float*  __restrict__ cpj) {
    const int seg = blockIdx.y;
    if (seg < 6) {
        const float4* s; float4* d; int n4;
        switch (seg) {
            case 0: s = wq; d = cwq; n4 = L_*D_*D_/4;  break;
            case 1: s = wk; d = cwk; n4 = L_*D_*D_/4;  break;
            case 2: s = wv; d = cwv; n4 = L_*D_*D_/4;  break;
            case 3: s = wo; d = cwo; n4 = L_*D_*D_/4;  break;
            case 4: s = w1; d = cw1; n4 = L_*D_*FF_/4; break;
            default:s = w2; d = cw2; n4 = L_*D_*FF_/4; break;
        }
        for (int i = blockIdx.x * blockDim.x + threadIdx.x; i < n4;
             i += gridDim.x * blockDim.x) {
            float4 v = s[i];
            d[i] = make_float4(f2tf(v.x), f2tf(v.y), f2tf(v.z), f2tf(v.w));
        }
    } else {
        const long long total = (long long)D_ * VP_;
        for (long long i = (long long)blockIdx.x * blockDim.x + threadIdx.x; i < total;
             i += (long long)gridDim.x * blockDim.x) {
            int row = (int)(i / VP_), col = (int)(i - (long long)row * VP_);
            cpj[i] = (col < V_) ? f2tf(pj[(size_t)row * V_ + col]) : 0.f;
        }
    }
}

// ---------------- embedding --------------------------------------------------
__global__ void embed_kernel(const int* __restrict__ x,
                             const float* __restrict__ tok,
                             const float* __restrict__ pos,
                             float* __restrict__ h) {
    int row = blockIdx.x;
    int t   = row % T_;
    int id  = x[row];
    const float* te = tok + (size_t)id * D_;
    const float* pe = pos + (size_t)t  * D_;
    float* o = h + (size_t)row * D_;
    for (int d = threadIdx.x; d < D_; d += blockDim.x)
        o[d] = te[d] + pe[d];
}

// ---------------- layernorm (shuffle reduce, tf32-rounded output) -------------
__global__ void ln_kernel(const float* __restrict__ in,
                          const float* __restrict__ w,
                          const float* __restrict__ b,
                          float* __restrict__ out) {
    const int row  = blockIdx.x;
    const int tid  = threadIdx.x;
    const int lane = tid & 31;
    const int warp = tid >> 5;
    const float* xr = in + (size_t)row * D_;

    float s = 0.f, sq = 0.f;
    #pragma unroll
    for (int d4 = 0; d4 < 4; d4++) {
        float4 v = *(const float4*)&xr[(tid + d4 * 256) * 4 - 3 * (tid + d4 * 256)];
        // NOTE: replaced below; keep simple strided float loads
    }
    s = 0.f; sq = 0.f;
    for (int d = tid; d < D_; d += 256) {
        float v = xr[d];
        s += v; sq += v * v;
    }
    #pragma unroll
    for (int off = 16; off > 0; off >>= 1) {
        s  += __shfl_xor_sync(0xffffffffu, s,  off);
        sq += __shfl_xor_sync(0xffffffffu, sq, off);
    }
    __shared__ float ws[8], wq2[8];
    if (lane == 0) { ws[warp] = s; wq2[warp] = sq; }
    __syncthreads();
    if (warp == 0) {
        float a = (lane < 8) ? ws[lane]  : 0.f;
        float c = (lane < 8) ? wq2[lane] : 0.f;
        #pragma unroll
        for (int off = 4; off > 0; off >>= 1) {
            a += __shfl_xor_sync(0xffffffffu, a, off);
            c += __shfl_xor_sync(0xffffffffu, c, off);
        }
        if (lane == 0) { ws[0] = a; wq2[0] = c; }
    }
    __syncthreads();
    float mu  = ws[0] * (1.f / D_);
    float var = wq2[0] * (1.f / D_) - mu * mu;
    float inv = rsqrtf(var + 1e-5f);
    float* o = out + (size_t)row * D_;
    for (int d = tid; d < D_; d += 256)
        o[d] = f2tf((xr[d] - mu) * inv * w[d] + b[d]);
}

// ---------------- common GEMM helpers ------------------------------------------
#define CPA16(dst_u32, src_ptr) \
    asm volatile("cp.async.cg.shared.global [%0], [%1], 16;" :: "r"(dst_u32), "l"(src_ptr))

__device__ __forceinline__ unsigned smem_u32(const void* p) {
    return (unsigned)__cvta_generic_to_shared(p);
}

__device__ __forceinline__ void mma8(float c[4], const unsigned a[4], const unsigned b[2]) {
    asm volatile(
        "mma.sync.aligned.m16n8k8.row.col.f32.tf32.tf32.f32 "
        "{%0,%1,%2,%3}, {%4,%5,%6,%7}, {%8,%9}, {%0,%1,%2,%3};\n"
        : "+f"(c[0]), "+f"(c[1]), "+f"(c[2]), "+f"(c[3])
        : "r"(a[0]), "r"(a[1]), "r"(a[2]), "r"(a[3]), "r"(b[0]), "r"(b[1]));
}

// ---------------- standard GEMM: 128 x BN_, 3-stage cp.async (proven) ---------
// MODE 0: +bias   MODE 1: f2tf(relu(+bias))   MODE 2: +bias + residual R
// GUARD 1: col<N guard on bias read + store (vocab tail)
template <int BN_>
__device__ __forceinline__ void issue_stage(
    float* As, float* Bs, const float* A, const float* W,
    int K, int Npad, int bm0, int bn0, int k0, int tid)
{
    constexpr int SB = BN_ + 8;
    #pragma unroll
    for (int j = 0; j < 4; j++) {
        int f = tid + j * 256;
        int row = f >> 3, c4 = (f & 7) << 2;
        CPA16(smem_u32(As + row * 36 + c4), A + (size_t)(bm0 + row) * K + k0 + c4);
    }
    #pragma unroll
    for (int j = 0; j < BN_ / 32; j++) {
        int f = tid + j * 256;
        int row = (BN_ == 128) ? (f >> 5) : (f >> 4);
        int c4  = (BN_ == 128) ? ((f & 31) << 2) : ((f & 15) << 2);
        CPA16(smem_u32(Bs + row * SB + c4), W + (size_t)(k0 + row) * Npad + bn0 + c4);
    }
    asm volatile("cp.async.commit_group;");
}

template <int MODE, int BN_, int GUARD>
__device__ __forceinline__ void tgemm_body(
    const float* __restrict__ A, const float* __restrict__ W,
    const float* __restrict__ bias, const float* __restrict__ R,
    float* __restrict__ C, int K, int N, int Npad, int bm0, int bn0)
{
    constexpr int SB  = BN_ + 8;
    constexpr int ASZ = 128 * 36;
    constexpr int BSZ = 32 * SB;
    constexpr int NI  = BN_ / 32;

    extern __shared__ float sm[];
    float* As = sm;
    float* Bs = sm + 3 * ASZ;

    const int tid  = threadIdx.x;
    const int lane = tid & 31;
    const int warp = tid >> 5;
    const int g    = lane >> 2;
    const int tg   = lane & 3;
    const int wm0  = (warp >> 2) * 64;
    const int wn0  = (warp & 3) * (BN_ / 4);

    float acc[4][NI][4];
    #pragma unroll
    for (int mi = 0; mi < 4; mi++)
        #pragma unroll
        for (int ni = 0; ni < NI; ni++)
            #pragma unroll
            for (int r = 0; r < 4; r++) acc[mi][ni][r] = 0.f;

    const int nIter = K / 32;
    issue_stage<BN_>(As, Bs, A, W, K, Npad, bm0, bn0, 0, tid);
    issue_stage<BN_>(As + ASZ, Bs + BSZ, A, W, K, Npad, bm0, bn0, 32, tid);

    int st = 0, stw = 2;
    for (int t = 0; t < nIter; t++) {
        if (t + 1 < nIter) asm volatile("cp.async.wait_group 1;");
        else               asm volatile("cp.async.wait_group 0;");
        __syncthreads();

        const float* Ast = As + st * ASZ;
        const float* Bst = Bs + st * BSZ;
        #pragma unroll
        for (int kk = 0; kk < 32; kk += 8) {
            unsigned a[4][4], b[NI][2];
            #pragma unroll
            for (int mi = 0; mi < 4; mi++) {
                int r0 = wm0 + mi * 16 + g;
                a[mi][0] = __float_as_uint(Ast[(r0    ) * 36 + kk + tg]);
                a[mi][1] = __float_as_uint(Ast[(r0 + 8) * 36 + kk + tg]);
                a[mi][2] = __float_as_uint(Ast[(r0    ) * 36 + kk + tg + 4]);
                a[mi][3] = __float_as_uint(Ast[(r0 + 8) * 36 + kk + tg + 4]);
            }
            #pragma unroll
            for (int ni = 0; ni < NI; ni++) {
                int c = wn0 + ni * 8 + g;
                b[ni][0] = __float_as_uint(Bst[(kk + tg    ) * SB + c]);
                b[ni][1] = __float_as_uint(Bst[(kk + tg + 4) * SB + c]);
            }
            #pragma unroll
            for (int mi = 0; mi < 4; mi++)
                #pragma unroll
                for (int ni = 0; ni < NI; ni++)
                    mma8(acc[mi][ni], a[mi], b[ni]);
        }

        if (t + 2 < nIter) {
            issue_stage<BN_>(As + stw * ASZ, Bs + stw * BSZ, A, W, K, Npad, bm0, bn0,
                             (t + 2) * 32, tid);
            stw = (stw == 2) ? 0 : stw + 1;
        }
        st = (st == 2) ? 0 : st + 1;
    }

    #pragma unroll
    for (int mi = 0; mi < 4; mi++) {
        #pragma unroll
        for (int ni = 0; ni < NI; ni++) {
            int row0 = bm0 + wm0 + mi * 16 + g;
            int col0 = bn0 + wn0 + ni * 8 + 2 * tg;
            #pragma unroll
            for (int rr = 0; rr < 2; rr++) {
                int row = row0 + rr * 8;
                #pragma unroll
                for (int cc = 0; cc < 2; cc++) {
                    int col = col0 + cc;
                    if (!GUARD || col < N) {
                        float v = acc[mi][ni][rr * 2 + cc] + bias[col];
                        if (MODE == 1) v = f2tf(fmaxf(v, 0.f));
                        if (MODE == 2) v += R[(size_t)row * N + col];
                        C[(size_t)row * N + col] = v;
                    }
                }
            }
        }
    }
}

// bn-fastest grid (A-tile reuse across the wave)
template <int MODE, int BN_, int GUARD>
__global__ __launch_bounds__(256, 2)
void tgemm(const float* __restrict__ A, const float* __restrict__ W,
           const float* __restrict__ bias, const float* __restrict__ R,
           float* __restrict__ C, int K, int N, int Npad) {
    tgemm_body<MODE, BN_, GUARD>(A, W, bias, R, C, K, N, Npad,
                                 blockIdx.y * 128, blockIdx.x * BN_);
}

// bm-fastest grid (B-tile reuse across the wave; for N >> M GEMMs)
template <int MODE, int BN_, int GUARD>
__global__ __launch_bounds__(256, 2)
void tgemm_s(const float* __restrict__ A, const float* __restrict__ W,
             const float* __restrict__ bias, const float* __restrict__ R,
             float* __restrict__ C, int K, int N, int Npad) {
    tgemm_body<MODE, BN_, GUARD>(A, W, bias, R, C, K, N, Npad,
                                 blockIdx.x * 128, blockIdx.y * BN_);
}

__global__ __launch_bounds__(256, 2)
void tgemm_qkv(const float* __restrict__ A,
               const float* __restrict__ wq, const float* __restrict__ wk,
               const float* __restrict__ wv,
               const float* __restrict__ bq, const float* __restrict__ bk,
               const float* __restrict__ bv,
               float* __restrict__ q, float* __restrict__ k, float* __restrict__ v) {
    int z = blockIdx.z;
    const float* W    = (z == 0) ? wq : (z == 1) ? wk : wv;
    const float* bias = (z == 0) ? bq : (z == 1) ? bk : bv;
    float*       C    = (z == 0) ? q  : (z == 1) ? k  : v;
    tgemm_body<0, 128, 0>(A, W, bias, nullptr, C, D_, D_, D_,
                          blockIdx.y * 128, blockIdx.x * 128);
}

// ---------------- flash attention --------------------------------------------
#define QT 64
#define KT 32

__global__ __launch_bounds__(256)
void flash_attn(const float* __restrict__ q,
                const float* __restrict__ k,
                const float* __restrict__ v,
                float* __restrict__ out) {
    const int q0  = blockIdx.x * QT;
    const int h   = blockIdx.y;
    const int b   = blockIdx.z;
    const int tid = threadIdx.x;
    const int qr  = tid >> 2;
    const int qt  = tid & 3;

    __shared__ float Qs[QT][68];
    __shared__ float Ks[KT][68];
    __shared__ float Vs[KT][68];
    __shared__ float Ps[QT][33];

    const size_t base = ((size_t)b * T_) * D_ + (size_t)h * HD_;
    const int qg = q0 + qr;

    #pragma unroll
    for (int i = tid; i < QT * 16; i += 256) {
        int r = i >> 4, c4 = (i & 15) << 2;
        *(float4*)&Qs[r][c4] = *(const float4*)&q[base + (size_t)(q0 + r) * D_ + c4];
    }

    float o[16];
    #pragma unroll
    for (int i = 0; i < 16; i++) o[i] = 0.f;
    float m = -1e30f, l = 0.f;

    const int nTiles = (q0 + QT) / KT;
    __syncthreads();

    for (int t0 = 0; t0 < nTiles; t0++) {
        const int s0 = t0 * KT;
        #pragma unroll
        for (int i = tid; i < KT * 16; i += 256) {
            int r = i >> 4, c4 = (i & 15) << 2;
            *(float4*)&Ks[r][c4] = *(const float4*)&k[base + (size_t)(s0 + r) * D_ + c4];
            *(float4*)&Vs[r][c4] = *(const float4*)&v[base + (size_t)(s0 + r) * D_ + c4];
        }
        __syncthreads();

        float s[8];
        #pragma unroll
        for (int j = 0; j < 8; j++) s[j] = 0.f;
        #pragma unroll
        for (int d4 = 0; d4 < 16; d4++) {
            float4 qv = *(const float4*)&Qs[qr][d4 << 2];
            #pragma unroll
            for (int j = 0; j < 8; j++) {
                float4 kv4 = *(const float4*)&Ks[qt * 8 + j][d4 << 2];
                s[j] += qv.x * kv4.x + qv.y * kv4.y + qv.z * kv4.z + qv.w * kv4.w;
            }
        }
        #pragma unroll
        for (int j = 0; j < 8; j++) {
            int kvg = s0 + qt * 8 + j;
            s[j] = (kvg <= qg) ? s[j] * 0.125f : -1e30f;
        }
        float tm = s[0];
        #pragma unroll
        for (int j = 1; j < 8; j++) tm = fmaxf(tm, s[j]);
        tm = fmaxf(tm, __shfl_xor_sync(0xffffffffu, tm, 1));
        tm = fmaxf(tm, __shfl_xor_sync(0xffffffffu, tm, 2));
        float m_new = fmaxf(m, tm);
        float scale = __expf(m - m_new);
        float ps = 0.f;
        #pragma unroll
        for (int j = 0; j < 8; j++) { s[j] = __expf(s[j] - m_new); ps += s[j]; }
        ps += __shfl_xor_sync(0xffffffffu, ps, 1);
        ps += __shfl_xor_sync(0xffffffffu, ps, 2);
        l = l * scale + ps;
        m = m_new;
        #pragma unroll
        for (int i = 0; i < 16; i++) o[i] *= scale;
        #pragma unroll
        for (int j = 0; j < 8; j++) Ps[qr][qt * 8 + j] = s[j];
        __syncthreads();

        #pragma unroll 4
        for (int kv = 0; kv < KT; kv++) {
            float p = Ps[qr][kv];
            #pragma unroll
            for (int d4 = 0; d4 < 4; d4++) {
                float4 vv = *(const float4*)&Vs[kv][qt * 16 + (d4 << 2)];
                o[d4 * 4 + 0] += p * vv.x;
                o[d4 * 4 + 1] += p * vv.y;
                o[d4 * 4 + 2] += p * vv.z;
                o[d4 * 4 + 3] += p * vv.w;
            }
        }
        __syncthreads();
    }

    float inv = 1.f / l;
    #pragma unroll
    for (int d4 = 0; d4 < 4; d4++) {
        float4 ov = make_float4(f2tf(o[d4 * 4 + 0] * inv), f2tf(o[d4 * 4 + 1] * inv),
                                f2tf(o[d4 * 4 + 2] * inv), f2tf(o[d4 * 4 + 3] * inv));
        *(float4*)&out[base + (size_t)qg * D_ + qt * 16 + (d4 << 2)] = ov;
    }
}

// ---------------- launch -----------------------------------------------------
extern "C" void kernel_launch(void* const* d_in, const int* in_sizes, int n_in,
                              void* d_out, int out_size) {
    const int*   x       = (const int*)  d_in[0];
    const float* tok_emb = (const float*)d_in[1];
    const float* pos_emb = (const float*)d_in[2];
    const float* wq      = (const float*)d_in[3];
    const float* bq      = (const float*)d_in[4];
    const float* wk      = (const float*)d_in[5];
    const float* bk      = (const float*)d_in[6];
    const float* wv      = (const float*)d_in[7];
    const float* bv      = (const float*)d_in[8];
    const float* wo      = (const float*)d_in[9];
    const float* bo      = (const float*)d_in[10];
    const float* ln1_w   = (const float*)d_in[11];
    const float* ln1_b   = (const float*)d_in[12];
    const float* ln2_w   = (const float*)d_in[13];
    const float* ln2_b   = (const float*)d_in[14];
    const float* ffn_w1  = (const float*)d_in[15];
    const float* ffn_b1  = (const float*)d_in[16];
    const float* ffn_w2  = (const float*)d_in[17];
    const float* ffn_b2  = (const float*)d_in[18];
    const float* lnf_w   = (const float*)d_in[19];
    const float* lnf_b   = (const float*)d_in[20];
    const float* proj_w  = (const float*)d_in[21];
    const float* proj_b  = (const float*)d_in[22];
    float* logits = (float*)d_out;

    float *h, *ln, *q, *k, *v, *attn, *mid;
    float *cwq, *cwk, *cwv, *cwo, *cw1, *cw2, *cpj;
    cudaGetSymbolAddress((void**)&h,    g_h);
    cudaGetSymbolAddress((void**)&ln,   g_ln);
    cudaGetSymbolAddress((void**)&q,    g_q);
    cudaGetSymbolAddress((void**)&k,    g_k);
    cudaGetSymbolAddress((void**)&v,    g_v);
    cudaGetSymbolAddress((void**)&attn, g_attn);
    cudaGetSymbolAddress((void**)&mid,  g_mid);
    cudaGetSymbolAddress((void**)&cwq,  g_cwq);
    cudaGetSymbolAddress((void**)&cwk,  g_cwk);
    cudaGetSymbolAddress((void**)&cwv,  g_cwv);
    cudaGetSymbolAddress((void**)&cwo,  g_cwo);
    cudaGetSymbolAddress((void**)&cw1,  g_cw1);
    cudaGetSymbolAddress((void**)&cw2,  g_cw2);
    cudaGetSymbolAddress((void**)&cpj,  g_cpj);

    const int SMEM128 = 3 * (128 * 36 + 32 * 136) * 4;   // 107520 B
    const int SMEM64  = 3 * (128 * 36 + 32 * 72)  * 4;   // 82944 B
    cudaFuncSetAttribute(tgemm<2,64,0>,   cudaFuncAttributeMaxDynamicSharedMemorySize, SMEM64);
    cudaFuncSetAttribute(tgemm_s<1,128,0>,cudaFuncAttributeMaxDynamicSharedMemorySize, SMEM128);
    cudaFuncSetAttribute(tgemm_s<0,128,1>,cudaFuncAttributeMaxDynamicSharedMemorySize, SMEM128);
    cudaFuncSetAttribute(tgemm_qkv,       cudaFuncAttributeMaxDynamicSharedMemorySize, SMEM128);

    dim3 gDD64(D_ / 64, M_ / 128);           // (16,16)  bn-fastest
    dim3 gQKV(D_ / 128, M_ / 128, 3);        // (8,16,3)
    dim3 gFF1(M_ / 128, FF_ / 128);          // (16,32)  bm-fastest
    dim3 gPRJ(M_ / 128, VP_ / 128);          // (16,393) bm-fastest
    dim3 gAT(T_ / QT, H_, B_);

    // Launch order: our #4 is tgemm_qkv (harness prepends 2 launches; ncu -s 5
    // profiles our 4th).
    embed_kernel<<<M_, 256>>>(x, tok_emb, pos_emb, h);                        // 1
    conv_all<<<dim3(1024, 7), 256>>>(                                         // 2
        (const float4*)wq, (const float4*)wk, (const float4*)wv,
        (const float4*)wo, (const float4*)ffn_w1, (const float4*)ffn_w2,
        proj_w,
        (float4*)cwq, (float4*)cwk, (float4*)cwv,
        (float4*)cwo, (float4*)cw1, (float4*)cw2, cpj);

    for (int l = 0; l < L_; l++) {
        float* cwq_l = cwq + (size_t)l * D_ * D_;
        float* cwk_l = cwk + (size_t)l * D_ * D_;
        float* cwv_l = cwv + (size_t)l * D_ * D_;
        float* cwo_l = cwo + (size_t)l * D_ * D_;
        float* cw1_l = cw1 + (size_t)l * D_ * FF_;
        float* cw2_l = cw2 + (size_t)l * FF_ * D_;

        ln_kernel<<<M_, 256>>>(h, ln1_w + l * D_, ln1_b + l * D_, ln);        // 3 (l=0)

        tgemm_qkv<<<gQKV, 256, SMEM128>>>(ln, cwq_l, cwk_l, cwv_l,
                                          bq + l * D_, bk + l * D_, bv + l * D_,
                                          q, k, v);                           // 4 (l=0) <- profiled

        flash_attn<<<gAT, 256>>>(q, k, v, attn);

        tgemm<2,64,0><<<gDD64, 256, SMEM64>>>(attn, cwo_l, bo + l * D_, h, h,
                                              D_, D_, D_);

        ln_kernel<<<M_, 256>>>(h, ln2_w + l * D_, ln2_b + l * D_, ln);

        tgemm_s<1,128,0><<<gFF1, 256, SMEM128>>>(ln, cw1_l, ffn_b1 + l * FF_,
                                                 nullptr, mid, D_, FF_, FF_);
        tgemm<2,64,0><<<gDD64, 256, SMEM64>>>(mid, cw2_l, ffn_b2 + l * D_, h, h,
                                              FF_, D_, D_);
    }

    ln_kernel<<<M_, 256>>>(h, lnf_w, lnf_b, ln);
    tgemm_s<0,128,1><<<gPRJ, 256, SMEM128>>>(ln, cpj, proj_b, nullptr, logits,
                                             D_, V_, VP_);
}

// round 11
// speedup vs baseline: 1.0149x; 1.0149x over previous
#include <cuda_runtime.h>
#include <math.h>

#define B_  2
#define T_  1024
#define D_  1024
#define H_  16
#define HD_ 64
#define FF_ 4096
#define L_  6
#define V_  50257
#define M_  (B_*T_)        // 2048 rows
#define VP_ 50304          // V padded to 128

// ---------------- scratch (static device globals; no allocation) -------------
__device__ float g_h   [M_*D_];
__device__ float g_ln  [M_*D_];
__device__ float g_q   [M_*D_];
__device__ float g_k   [M_*D_];
__device__ float g_v   [M_*D_];
__device__ float g_attn[M_*D_];
__device__ float g_mid [M_*FF_];
__device__ float g_part[4*M_*D_];        // split-K partials (32 MB)
// tf32-preconverted weights (row-major [K][N])
__device__ float g_cwq [L_*D_*D_];
__device__ float g_cwk [L_*D_*D_];
__device__ float g_cwv [L_*D_*D_];
__device__ float g_cwo [L_*D_*D_];
__device__ float g_cw1 [L_*D_*FF_];
__device__ float g_cw2 [L_*FF_*D_];
__device__ float g_cpj [(size_t)D_*VP_];

__device__ __forceinline__ float f2tf(float x) {
    unsigned u;
    asm("cvt.rna.tf32.f32 %0, %1;" : "=r"(u) : "f"(x));
    return __uint_as_float(u);
}

// ---------------- single fused weight conversion -------------------------------
__global__ void conv_all(const float4* __restrict__ wq, const float4* __restrict__ wk,
                         const float4* __restrict__ wv, const float4* __restrict__ wo,
                         const float4* __restrict__ w1, const float4* __restrict__ w2,
                         const float*  __restrict__ pj,
                         float4* __restrict__ cwq, float4* __restrict__ cwk,
                         float4* __restrict__ cwv, float4* __restrict__ cwo,
                         float4* __restrict__ cw1, float4* __restrict__ cw2,
                         float*  __restrict__ cpj) {
    const int seg = blockIdx.y;
    if (seg < 6) {
        const float4* s; float4* d; int n4;
        switch (seg) {
            case 0: s = wq; d = cwq; n4 = L_*D_*D_/4;  break;
            case 1: s = wk; d = cwk; n4 = L_*D_*D_/4;  break;
            case 2: s = wv; d = cwv; n4 = L_*D_*D_/4;  break;
            case 3: s = wo; d = cwo; n4 = L_*D_*D_/4;  break;
            case 4: s = w1; d = cw1; n4 = L_*D_*FF_/4; break;
            default:s = w2; d = cw2; n4 = L_*D_*FF_/4; break;
        }
        for (int i = blockIdx.x * blockDim.x + threadIdx.x; i < n4;
             i += gridDim.x * blockDim.x) {
            float4 v = s[i];
            d[i] = make_float4(f2tf(v.x), f2tf(v.y), f2tf(v.z), f2tf(v.w));
        }
    } else {
        const long long total = (long long)D_ * VP_;
        for (long long i = (long long)blockIdx.x * blockDim.x + threadIdx.x; i < total;
             i += (long long)gridDim.x * blockDim.x) {
            int row = (int)(i / VP_), col = (int)(i - (long long)row * VP_);
            cpj[i] = (col < V_) ? f2tf(pj[(size_t)row * V_ + col]) : 0.f;
        }
    }
}

// ---------------- embedding --------------------------------------------------
__global__ void embed_kernel(const int* __restrict__ x,
                             const float* __restrict__ tok,
                             const float* __restrict__ pos,
                             float* __restrict__ h) {
    int row = blockIdx.x;
    int t   = row % T_;
    int id  = x[row];
    const float* te = tok + (size_t)id * D_;
    const float* pe = pos + (size_t)t  * D_;
    float* o = h + (size_t)row * D_;
    for (int d = threadIdx.x; d < D_; d += blockDim.x)
        o[d] = te[d] + pe[d];
}

// ---------------- layernorm (shuffle reduce, tf32-rounded output) -------------
__global__ void ln_kernel(const float* __restrict__ in,
                          const float* __restrict__ w,
                          const float* __restrict__ b,
                          float* __restrict__ out) {
    const int row  = blockIdx.x;
    const int tid  = threadIdx.x;
    const int lane = tid & 31;
    const int warp = tid >> 5;
    const float* xr = in + (size_t)row * D_;

    float s = 0.f, sq = 0.f;
    for (int d = tid; d < D_; d += 256) {
        float v = xr[d];
        s += v; sq += v * v;
    }
    #pragma unroll
    for (int off = 16; off > 0; off >>= 1) {
        s  += __shfl_xor_sync(0xffffffffu, s,  off);
        sq += __shfl_xor_sync(0xffffffffu, sq, off);
    }
    __shared__ float ws[8], wq2[8];
    if (lane == 0) { ws[warp] = s; wq2[warp] = sq; }
    __syncthreads();
    if (warp == 0) {
        float a = (lane < 8) ? ws[lane]  : 0.f;
        float c = (lane < 8) ? wq2[lane] : 0.f;
        #pragma unroll
        for (int off = 4; off > 0; off >>= 1) {
            a += __shfl_xor_sync(0xffffffffu, a, off);
            c += __shfl_xor_sync(0xffffffffu, c, off);
        }
        if (lane == 0) { ws[0] = a; wq2[0] = c; }
    }
    __syncthreads();
    float mu  = ws[0] * (1.f / D_);
    float var = wq2[0] * (1.f / D_) - mu * mu;
    float inv = rsqrtf(var + 1e-5f);
    float* o = out + (size_t)row * D_;
    for (int d = tid; d < D_; d += 256)
        o[d] = f2tf((xr[d] - mu) * inv * w[d] + b[d]);
}

// ---------------- split-K reduce: h += bias + sum(parts) ----------------------
__global__ void reduce_add(float* __restrict__ h, const float* __restrict__ bias,
                           const float* __restrict__ part, int nsplit) {
    const int row = blockIdx.x;
    const int c4  = threadIdx.x * 4;
    float4 acc = *(float4*)&h[(size_t)row * D_ + c4];
    float4 bv  = *(const float4*)&bias[c4];
    acc.x += bv.x; acc.y += bv.y; acc.z += bv.z; acc.w += bv.w;
    for (int s = 0; s < nsplit; s++) {
        float4 p = *(const float4*)&part[(size_t)s * M_ * D_ + (size_t)row * D_ + c4];
        acc.x += p.x; acc.y += p.y; acc.z += p.z; acc.w += p.w;
    }
    *(float4*)&h[(size_t)row * D_ + c4] = acc;
}

// ---------------- common GEMM helpers ------------------------------------------
#define CPA16(dst_u32, src_ptr) \
    asm volatile("cp.async.cg.shared.global [%0], [%1], 16;" :: "r"(dst_u32), "l"(src_ptr))

__device__ __forceinline__ unsigned smem_u32(const void* p) {
    return (unsigned)__cvta_generic_to_shared(p);
}

__device__ __forceinline__ void mma8(float c[4], const unsigned a[4], const unsigned b[2]) {
    asm volatile(
        "mma.sync.aligned.m16n8k8.row.col.f32.tf32.tf32.f32 "
        "{%0,%1,%2,%3}, {%4,%5,%6,%7}, {%8,%9}, {%0,%1,%2,%3};\n"
        : "+f"(c[0]), "+f"(c[1]), "+f"(c[2]), "+f"(c[3])
        : "r"(a[0]), "r"(a[1]), "r"(a[2]), "r"(a[3]), "r"(b[0]), "r"(b[1]));
}

// ---------------- standard GEMM body: 128 x BN_, 3-stage cp.async -------------
// MODE 0: +bias  MODE 1: f2tf(relu(+bias))  MODE 2: +bias+residual  MODE 3: raw
// GUARD 1: col<N guard (vocab tail).  lda = row stride of A; KL = K to process.
template <int BN_>
__device__ __forceinline__ void issue_stage(
    float* As, float* Bs, const float* A, const float* W,
    int lda, int Npad, int bm0, int bn0, int k0, int tid)
{
    constexpr int SB = BN_ + 8;
    #pragma unroll
    for (int j = 0; j < 4; j++) {
        int f = tid + j * 256;
        int row = f >> 3, c4 = (f & 7) << 2;
        CPA16(smem_u32(As + row * 36 + c4), A + (size_t)(bm0 + row) * lda + k0 + c4);
    }
    #pragma unroll
    for (int j = 0; j < BN_ / 32; j++) {
        int f = tid + j * 256;
        int row = (BN_ == 128) ? (f >> 5) : (f >> 4);
        int c4  = (BN_ == 128) ? ((f & 31) << 2) : ((f & 15) << 2);
        CPA16(smem_u32(Bs + row * SB + c4), W + (size_t)(k0 + row) * Npad + bn0 + c4);
    }
    asm volatile("cp.async.commit_group;");
}

template <int MODE, int BN_, int GUARD>
__device__ __forceinline__ void tgemm_body(
    const float* __restrict__ A, const float* __restrict__ W,
    const float* __restrict__ bias, const float* __restrict__ R,
    float* __restrict__ C, int lda, int KL, int N, int Npad, int bm0, int bn0)
{
    constexpr int SB  = BN_ + 8;
    constexpr int ASZ = 128 * 36;
    constexpr int BSZ = 32 * SB;
    constexpr int NI  = BN_ / 32;

    extern __shared__ float sm[];
    float* As = sm;
    float* Bs = sm + 3 * ASZ;

    const int tid  = threadIdx.x;
    const int lane = tid & 31;
    const int warp = tid >> 5;
    const int g    = lane >> 2;
    const int tg   = lane & 3;
    const int wm0  = (warp >> 2) * 64;
    const int wn0  = (warp & 3) * (BN_ / 4);

    float acc[4][NI][4];
    #pragma unroll
    for (int mi = 0; mi < 4; mi++)
        #pragma unroll
        for (int ni = 0; ni < NI; ni++)
            #pragma unroll
            for (int r = 0; r < 4; r++) acc[mi][ni][r] = 0.f;

    const int nIter = KL / 32;
    issue_stage<BN_>(As, Bs, A, W, lda, Npad, bm0, bn0, 0, tid);
    issue_stage<BN_>(As + ASZ, Bs + BSZ, A, W, lda, Npad, bm0, bn0, 32, tid);

    int st = 0, stw = 2;
    for (int t = 0; t < nIter; t++) {
        if (t + 1 < nIter) asm volatile("cp.async.wait_group 1;");
        else               asm volatile("cp.async.wait_group 0;");
        __syncthreads();

        const float* Ast = As + st * ASZ;
        const float* Bst = Bs + st * BSZ;
        #pragma unroll
        for (int kk = 0; kk < 32; kk += 8) {
            unsigned a[4][4], b[NI][2];
            #pragma unroll
            for (int mi = 0; mi < 4; mi++) {
                int r0 = wm0 + mi * 16 + g;
                a[mi][0] = __float_as_uint(Ast[(r0    ) * 36 + kk + tg]);
                a[mi][1] = __float_as_uint(Ast[(r0 + 8) * 36 + kk + tg]);
                a[mi][2] = __float_as_uint(Ast[(r0    ) * 36 + kk + tg + 4]);
                a[mi][3] = __float_as_uint(Ast[(r0 + 8) * 36 + kk + tg + 4]);
            }
            #pragma unroll
            for (int ni = 0; ni < NI; ni++) {
                int c = wn0 + ni * 8 + g;
                b[ni][0] = __float_as_uint(Bst[(kk + tg    ) * SB + c]);
                b[ni][1] = __float_as_uint(Bst[(kk + tg + 4) * SB + c]);
            }
            #pragma unroll
            for (int mi = 0; mi < 4; mi++)
                #pragma unroll
                for (int ni = 0; ni < NI; ni++)
                    mma8(acc[mi][ni], a[mi], b[ni]);
        }

        if (t + 2 < nIter) {
            issue_stage<BN_>(As + stw * ASZ, Bs + stw * BSZ, A, W, lda, Npad, bm0, bn0,
                             (t + 2) * 32, tid);
            stw = (stw == 2) ? 0 : stw + 1;
        }
        st = (st == 2) ? 0 : st + 1;
    }

    #pragma unroll
    for (int mi = 0; mi < 4; mi++) {
        #pragma unroll
        for (int ni = 0; ni < NI; ni++) {
            int row0 = bm0 + wm0 + mi * 16 + g;
            int col0 = bn0 + wn0 + ni * 8 + 2 * tg;
            #pragma unroll
            for (int rr = 0; rr < 2; rr++) {
                int row = row0 + rr * 8;
                #pragma unroll
                for (int cc = 0; cc < 2; cc++) {
                    int col = col0 + cc;
                    if (!GUARD || col < N) {
                        float v = acc[mi][ni][rr * 2 + cc];
                        if (MODE != 3) v += bias[col];
                        if (MODE == 1) v = f2tf(fmaxf(v, 0.f));
                        if (MODE == 2) v += R[(size_t)row * N + col];
                        C[(size_t)row * N + col] = v;
                    }
                }
            }
        }
    }
}

// bm-fastest grid (B-tile reuse across the wave; for N >> M GEMMs)
template <int MODE, int BN_, int GUARD>
__global__ __launch_bounds__(256, 2)
void tgemm_s(const float* __restrict__ A, const float* __restrict__ W,
             const float* __restrict__ bias, const float* __restrict__ R,
             float* __restrict__ C, int K, int N, int Npad) {
    tgemm_body<MODE, BN_, GUARD>(A, W, bias, R, C, K, K, N, Npad,
                                 blockIdx.x * 128, blockIdx.y * BN_);
}

__global__ __launch_bounds__(256, 2)
void tgemm_qkv(const float* __restrict__ A,
               const float* __restrict__ wq, const float* __restrict__ wk,
               const float* __restrict__ wv,
               const float* __restrict__ bq, const float* __restrict__ bk,
               const float* __restrict__ bv,
               float* __restrict__ q, float* __restrict__ k, float* __restrict__ v) {
    int z = blockIdx.z;
    const float* W    = (z == 0) ? wq : (z == 1) ? wk : wv;
    const float* bias = (z == 0) ? bq : (z == 1) ? bk : bv;
    float*       C    = (z == 0) ? q  : (z == 1) ? k  : v;
    tgemm_body<0, 128, 0>(A, W, bias, nullptr, C, D_, D_, D_, D_,
                          blockIdx.y * 128, blockIdx.x * 128);
}

// split-K GEMM: blockIdx.z = split; raw partials to part[z][M][N]
__global__ __launch_bounds__(256, 2)
void tgemm_sk(const float* __restrict__ A, const float* __restrict__ W,
              float* __restrict__ part, int K, int KL, int N) {
    const int s = blockIdx.z;
    tgemm_body<3, 64, 0>(A + (size_t)s * KL,
                         W + (size_t)s * KL * N,
                         nullptr, nullptr,
                         part + (size_t)s * M_ * N,
                         K, KL, N, N,
                         blockIdx.y * 128, blockIdx.x * 64);
}

// ---------------- flash attention (cp.async double-buffered K/V) ---------------
#define QT 64
#define KT 32
#define FA_QS   0                       // Qs: 64 x 68
#define FA_KS   (QT*68)                 // Ks: 2 x 32 x 68
#define FA_VS   (FA_KS + 2*KT*68)       // Vs: 2 x 32 x 68
#define FA_PS   (FA_VS + 2*KT*68)       // Ps: 64 x 33
#define SMEM_ATT ((FA_PS + QT*33)*4)    // 60672 B

__global__ __launch_bounds__(256)
void flash_attn(const float* __restrict__ q,
                const float* __restrict__ k,
                const float* __restrict__ v,
                float* __restrict__ out) {
    extern __shared__ float sm[];
    float* Qs = sm + FA_QS;
    float* Ks = sm + FA_KS;
    float* Vs = sm + FA_VS;
    float* Ps = sm + FA_PS;

    const int q0  = blockIdx.x * QT;
    const int h   = blockIdx.y;
    const int b   = blockIdx.z;
    const int tid = threadIdx.x;
    const int qr  = tid >> 2;
    const int qt  = tid & 3;

    const size_t base = ((size_t)b * T_) * D_ + (size_t)h * HD_;
    const int qg = q0 + qr;

    #pragma unroll
    for (int i = tid; i < QT * 16; i += 256) {
        int r = i >> 4, c4 = (i & 15) << 2;
        *(float4*)&Qs[r * 68 + c4] = *(const float4*)&q[base + (size_t)(q0 + r) * D_ + c4];
    }

    float o[16];
    #pragma unroll
    for (int i = 0; i < 16; i++) o[i] = 0.f;
    float m = -1e30f, l = 0.f;

    const int nTiles = (q0 + QT) / KT;

    // prologue: stream tile 0 into buffer 0
    {
        #pragma unroll
        for (int j = 0; j < 2; j++) {
            int f = tid + j * 256;
            int r = f >> 4, c4 = (f & 15) << 2;
            CPA16(smem_u32(Ks + r * 68 + c4), k + base + (size_t)r * D_ + c4);
            CPA16(smem_u32(Vs + r * 68 + c4), v + base + (size_t)r * D_ + c4);
        }
        asm volatile("cp.async.commit_group;");
    }

    for (int t0 = 0; t0 < nTiles; t0++) {
        const int s0 = t0 * KT;
        const int buf = t0 & 1;
        if (t0 + 1 < nTiles) {
            const int nb = (t0 + 1) & 1;
            const int ns0 = s0 + KT;
            #pragma unroll
            for (int j = 0; j < 2; j++) {
                int f = tid + j * 256;
                int r = f >> 4, c4 = (f & 15) << 2;
                CPA16(smem_u32(Ks + (nb * KT + r) * 68 + c4),
                      k + base + (size_t)(ns0 + r) * D_ + c4);
                CPA16(smem_u32(Vs + (nb * KT + r) * 68 + c4),
                      v + base + (size_t)(ns0 + r) * D_ + c4);
            }
            asm volatile("cp.async.commit_group;");
            asm volatile("cp.async.wait_group 1;");
        } else {
            asm volatile("cp.async.wait_group 0;");
        }
        __syncthreads();

        const float* Kb = Ks + buf * KT * 68;
        const float* Vb = Vs + buf * KT * 68;

        float s[8];
        #pragma unroll
        for (int j = 0; j < 8; j++) s[j] = 0.f;
        #pragma unroll
        for (int d4 = 0; d4 < 16; d4++) {
            float4 qv = *(const float4*)&Qs[qr * 68 + (d4 << 2)];
            #pragma unroll
            for (int j = 0; j < 8; j++) {
                float4 kv4 = *(const float4*)&Kb[(qt * 8 + j) * 68 + (d4 << 2)];
                s[j] += qv.x * kv4.x + qv.y * kv4.y + qv.z * kv4.z + qv.w * kv4.w;
            }
        }
        #pragma unroll
        for (int j = 0; j < 8; j++) {
            int kvg = s0 + qt * 8 + j;
            s[j] = (kvg <= qg) ? s[j] * 0.125f : -1e30f;
        }
        float tm = s[0];
        #pragma unroll
        for (int j = 1; j < 8; j++) tm = fmaxf(tm, s[j]);
        tm = fmaxf(tm, __shfl_xor_sync(0xffffffffu, tm, 1));
        tm = fmaxf(tm, __shfl_xor_sync(0xffffffffu, tm, 2));
        float m_new = fmaxf(m, tm);
        float scale = __expf(m - m_new);
        float ps = 0.f;
        #pragma unroll
        for (int j = 0; j < 8; j++) { s[j] = __expf(s[j] - m_new); ps += s[j]; }
        ps += __shfl_xor_sync(0xffffffffu, ps, 1);
        ps += __shfl_xor_sync(0xffffffffu, ps, 2);
        l = l * scale + ps;
        m = m_new;
        #pragma unroll
        for (int i = 0; i < 16; i++) o[i] *= scale;
        #pragma unroll
        for (int j = 0; j < 8; j++) Ps[qr * 33 + qt * 8 + j] = s[j];
        __syncthreads();

        #pragma unroll 4
        for (int kv = 0; kv < KT; kv++) {
            float p = Ps[qr * 33 + kv];
            #pragma unroll
            for (int d4 = 0; d4 < 4; d4++) {
                float4 vv = *(const float4*)&Vb[kv * 68 + qt * 16 + (d4 << 2)];
                o[d4 * 4 + 0] += p * vv.x;
                o[d4 * 4 + 1] += p * vv.y;
                o[d4 * 4 + 2] += p * vv.z;
                o[d4 * 4 + 3] += p * vv.w;
            }
        }
        __syncthreads();
    }

    float inv = 1.f / l;
    #pragma unroll
    for (int d4 = 0; d4 < 4; d4++) {
        float4 ov = make_float4(f2tf(o[d4 * 4 + 0] * inv), f2tf(o[d4 * 4 + 1] * inv),
                                f2tf(o[d4 * 4 + 2] * inv), f2tf(o[d4 * 4 + 3] * inv));
        *(float4*)&out[base + (size_t)qg * D_ + qt * 16 + (d4 << 2)] = ov;
    }
}

// ---------------- launch -----------------------------------------------------
extern "C" void kernel_launch(void* const* d_in, const int* in_sizes, int n_in,
                              void* d_out, int out_size) {
    const int*   x       = (const int*)  d_in[0];
    const float* tok_emb = (const float*)d_in[1];
    const float* pos_emb = (const float*)d_in[2];
    const float* wq      = (const float*)d_in[3];
    const float* bq      = (const float*)d_in[4];
    const float* wk      = (const float*)d_in[5];
    const float* bk      = (const float*)d_in[6];
    const float* wv      = (const float*)d_in[7];
    const float* bv      = (const float*)d_in[8];
    const float* wo      = (const float*)d_in[9];
    const float* bo      = (const float*)d_in[10];
    const float* ln1_w   = (const float*)d_in[11];
    const float* ln1_b   = (const float*)d_in[12];
    const float* ln2_w   = (const float*)d_in[13];
    const float* ln2_b   = (const float*)d_in[14];
    const float* ffn_w1  = (const float*)d_in[15];
    const float* ffn_b1  = (const float*)d_in[16];
    const float* ffn_w2  = (const float*)d_in[17];
    const float* ffn_b2  = (const float*)d_in[18];
    const float* lnf_w   = (const float*)d_in[19];
    const float* lnf_b   = (const float*)d_in[20];
    const float* proj_w  = (const float*)d_in[21];
    const float* proj_b  = (const float*)d_in[22];
    float* logits = (float*)d_out;

    float *h, *ln, *q, *k, *v, *attn, *mid, *part;
    float *cwq, *cwk, *cwv, *cwo, *cw1, *cw2, *cpj;
    cudaGetSymbolAddress((void**)&h,    g_h);
    cudaGetSymbolAddress((void**)&ln,   g_ln);
    cudaGetSymbolAddress((void**)&q,    g_q);
    cudaGetSymbolAddress((void**)&k,    g_k);
    cudaGetSymbolAddress((void**)&v,    g_v);
    cudaGetSymbolAddress((void**)&attn, g_attn);
    cudaGetSymbolAddress((void**)&mid,  g_mid);
    cudaGetSymbolAddress((void**)&part, g_part);
    cudaGetSymbolAddress((void**)&cwq,  g_cwq);
    cudaGetSymbolAddress((void**)&cwk,  g_cwk);
    cudaGetSymbolAddress((void**)&cwv,  g_cwv);
    cudaGetSymbolAddress((void**)&cwo,  g_cwo);
    cudaGetSymbolAddress((void**)&cw1,  g_cw1);
    cudaGetSymbolAddress((void**)&cw2,  g_cw2);
    cudaGetSymbolAddress((void**)&cpj,  g_cpj);

    const int SMEM128 = 3 * (128 * 36 + 32 * 136) * 4;   // 107520 B
    const int SMEM64  = 3 * (128 * 36 + 32 * 72)  * 4;   // 82944 B
    cudaFuncSetAttribute(tgemm_sk,        cudaFuncAttributeMaxDynamicSharedMemorySize, SMEM64);
    cudaFuncSetAttribute(tgemm_s<1,128,0>,cudaFuncAttributeMaxDynamicSharedMemorySize, SMEM128);
    cudaFuncSetAttribute(tgemm_s<0,128,1>,cudaFuncAttributeMaxDynamicSharedMemorySize, SMEM128);
    cudaFuncSetAttribute(tgemm_qkv,       cudaFuncAttributeMaxDynamicSharedMemorySize, SMEM128);
    cudaFuncSetAttribute(flash_attn,      cudaFuncAttributeMaxDynamicSharedMemorySize, SMEM_ATT);

    dim3 gQKV(D_ / 128, M_ / 128, 3);        // (8,16,3)
    dim3 gWO(D_ / 64, M_ / 128, 2);          // (16,16,2) split-K=2
    dim3 gFF1(M_ / 128, FF_ / 128);          // (16,32)  bm-fastest
    dim3 gFF2(D_ / 64, M_ / 128, 4);         // (16,16,4) split-K=4
    dim3 gPRJ(M_ / 128, VP_ / 128);          // (16,393) bm-fastest
    dim3 gAT(T_ / QT, H_, B_);

    // Launch order: our #4 is tgemm_qkv (ncu -s 5 lands on our 4th launch).
    embed_kernel<<<M_, 256>>>(x, tok_emb, pos_emb, h);                        // 1
    conv_all<<<dim3(1024, 7), 256>>>(                                         // 2
        (const float4*)wq, (const float4*)wk, (const float4*)wv,
        (const float4*)wo, (const float4*)ffn_w1, (const float4*)ffn_w2,
        proj_w,
        (float4*)cwq, (float4*)cwk, (float4*)cwv,
        (float4*)cwo, (float4*)cw1, (float4*)cw2, cpj);

    for (int l = 0; l < L_; l++) {
        float* cwq_l = cwq + (size_t)l * D_ * D_;
        float* cwk_l = cwk + (size_t)l * D_ * D_;
        float* cwv_l = cwv + (size_t)l * D_ * D_;
        float* cwo_l = cwo + (size_t)l * D_ * D_;
        float* cw1_l = cw1 + (size_t)l * D_ * FF_;
        float* cw2_l = cw2 + (size_t)l * FF_ * D_;

        ln_kernel<<<M_, 256>>>(h, ln1_w + l * D_, ln1_b + l * D_, ln);        // 3 (l=0)

        tgemm_qkv<<<gQKV, 256, SMEM128>>>(ln, cwq_l, cwk_l, cwv_l,
                                          bq + l * D_, bk + l * D_, bv + l * D_,
                                          q, k, v);                           // 4 (l=0)

        flash_attn<<<gAT, 256, SMEM_ATT>>>(q, k, v, attn);

        tgemm_sk<<<gWO, 256, SMEM64>>>(attn, cwo_l, part, D_, D_ / 2, D_);
        reduce_add<<<M_, 256>>>(h, bo + l * D_, part, 2);

        ln_kernel<<<M_, 256>>>(h, ln2_w + l * D_, ln2_b + l * D_, ln);

        tgemm_s<1,128,0><<<gFF1, 256, SMEM128>>>(ln, cw1_l, ffn_b1 + l * FF_,
                                                 nullptr, mid, D_, FF_, FF_);

        tgemm_sk<<<gFF2, 256, SMEM64>>>(mid, cw2_l, part, FF_, FF_ / 4, D_);
        reduce_add<<<M_, 256>>>(h, ffn_b2 + l * D_, part, 4);
    }

    ln_kernel<<<M_, 256>>>(h, lnf_w, lnf_b, ln);
    tgemm_s<0,128,1><<<gPRJ, 256, SMEM128>>>(ln, cpj, proj_b, nullptr, logits,
                                             D_, V_, VP_);
}

// round 12
// speedup vs baseline: 1.2298x; 1.2118x over previous
#include <cuda_runtime.h>
#include <math.h>

#define B_  2
#define T_  1024
#define D_  1024
#define H_  16
#define HD_ 64
#define FF_ 4096
#define L_  6
#define V_  50257
#define M_  (B_*T_)        // 2048 rows
#define VP_ 50304          // V padded to 128

// ---------------- scratch (static device globals; no allocation) -------------
__device__ float g_h   [M_*D_];
__device__ float g_ln  [M_*D_];
__device__ float g_q   [M_*D_];
__device__ float g_k   [M_*D_];
__device__ float g_v   [M_*D_];
__device__ float g_attn[M_*D_];
__device__ float g_mid [M_*FF_];
__device__ float g_part[4*M_*D_];        // split-K partials (32 MB)
// tf32-preconverted weights (row-major [K][N])
__device__ float g_cwq [L_*D_*D_];
__device__ float g_cwk [L_*D_*D_];
__device__ float g_cwv [L_*D_*D_];
__device__ float g_cwo [L_*D_*D_];
__device__ float g_cw1 [L_*D_*FF_];
__device__ float g_cw2 [L_*FF_*D_];
__device__ float g_cpj [(size_t)D_*VP_];

__device__ __forceinline__ float f2tf(float x) {
    unsigned u;
    asm("cvt.rna.tf32.f32 %0, %1;" : "=r"(u) : "f"(x));
    return __uint_as_float(u);
}

// ---------------- single fused weight conversion -------------------------------
__global__ void conv_all(const float4* __restrict__ wq, const float4* __restrict__ wk,
                         const float4* __restrict__ wv, const float4* __restrict__ wo,
                         const float4* __restrict__ w1, const float4* __restrict__ w2,
                         const float*  __restrict__ pj,
                         float4* __restrict__ cwq, float4* __restrict__ cwk,
                         float4* __restrict__ cwv, float4* __restrict__ cwo,
                         float4* __restrict__ cw1, float4* __restrict__ cw2,
                         float*  __restrict__ cpj) {
    const int seg = blockIdx.y;
    if (seg < 6) {
        const float4* s; float4* d; int n4;
        switch (seg) {
            case 0: s = wq; d = cwq; n4 = L_*D_*D_/4;  break;
            case 1: s = wk; d = cwk; n4 = L_*D_*D_/4;  break;
            case 2: s = wv; d = cwv; n4 = L_*D_*D_/4;  break;
            case 3: s = wo; d = cwo; n4 = L_*D_*D_/4;  break;
            case 4: s = w1; d = cw1; n4 = L_*D_*FF_/4; break;
            default:s = w2; d = cw2; n4 = L_*D_*FF_/4; break;
        }
        for (int i = blockIdx.x * blockDim.x + threadIdx.x; i < n4;
             i += gridDim.x * blockDim.x) {
            float4 v = s[i];
            d[i] = make_float4(f2tf(v.x), f2tf(v.y), f2tf(v.z), f2tf(v.w));
        }
    } else {
        const long long total = (long long)D_ * VP_;
        for (long long i = (long long)blockIdx.x * blockDim.x + threadIdx.x; i < total;
             i += (long long)gridDim.x * blockDim.x) {
            int row = (int)(i / VP_), col = (int)(i - (long long)row * VP_);
            cpj[i] = (col < V_) ? f2tf(pj[(size_t)row * V_ + col]) : 0.f;
        }
    }
}

// ---------------- fused embedding + layer-0 LN1 --------------------------------
__global__ void embed_ln(const int* __restrict__ x,
                         const float* __restrict__ tok,
                         const float* __restrict__ pos,
                         const float* __restrict__ w,
                         const float* __restrict__ b,
                         float* __restrict__ h, float* __restrict__ lnout) {
    const int row  = blockIdx.x;
    const int tid  = threadIdx.x;
    const int lane = tid & 31;
    const int warp = tid >> 5;
    const int t    = row % T_;
    const int id   = x[row];
    const float* te = tok + (size_t)id * D_;
    const float* pe = pos + (size_t)t  * D_;

    float e[4];
    float s = 0.f, sq = 0.f;
    #pragma unroll
    for (int i = 0; i < 4; i++) {
        int d = tid + i * 256;
        e[i] = te[d] + pe[d];
        s += e[i]; sq += e[i] * e[i];
        h[(size_t)row * D_ + d] = e[i];
    }
    #pragma unroll
    for (int off = 16; off > 0; off >>= 1) {
        s  += __shfl_xor_sync(0xffffffffu, s,  off);
        sq += __shfl_xor_sync(0xffffffffu, sq, off);
    }
    __shared__ float ws[8], wq2[8];
    if (lane == 0) { ws[warp] = s; wq2[warp] = sq; }
    __syncthreads();
    if (warp == 0) {
        float a = (lane < 8) ? ws[lane]  : 0.f;
        float c = (lane < 8) ? wq2[lane] : 0.f;
        #pragma unroll
        for (int off = 4; off > 0; off >>= 1) {
            a += __shfl_xor_sync(0xffffffffu, a, off);
            c += __shfl_xor_sync(0xffffffffu, c, off);
        }
        if (lane == 0) { ws[0] = a; wq2[0] = c; }
    }
    __syncthreads();
    float mu  = ws[0] * (1.f / D_);
    float var = wq2[0] * (1.f / D_) - mu * mu;
    float inv = rsqrtf(var + 1e-5f);
    #pragma unroll
    for (int i = 0; i < 4; i++) {
        int d = tid + i * 256;
        lnout[(size_t)row * D_ + d] = f2tf((e[i] - mu) * inv * w[d] + b[d]);
    }
}

// ---------------- layernorm (shuffle reduce, tf32-rounded output) -------------
__global__ void ln_kernel(const float* __restrict__ in,
                          const float* __restrict__ w,
                          const float* __restrict__ b,
                          float* __restrict__ out) {
    const int row  = blockIdx.x;
    const int tid  = threadIdx.x;
    const int lane = tid & 31;
    const int warp = tid >> 5;
    const float* xr = in + (size_t)row * D_;

    float s = 0.f, sq = 0.f;
    for (int d = tid; d < D_; d += 256) {
        float v = xr[d];
        s += v; sq += v * v;
    }
    #pragma unroll
    for (int off = 16; off > 0; off >>= 1) {
        s  += __shfl_xor_sync(0xffffffffu, s,  off);
        sq += __shfl_xor_sync(0xffffffffu, sq, off);
    }
    __shared__ float ws[8], wq2[8];
    if (lane == 0) { ws[warp] = s; wq2[warp] = sq; }
    __syncthreads();
    if (warp == 0) {
        float a = (lane < 8) ? ws[lane]  : 0.f;
        float c = (lane < 8) ? wq2[lane] : 0.f;
        #pragma unroll
        for (int off = 4; off > 0; off >>= 1) {
            a += __shfl_xor_sync(0xffffffffu, a, off);
            c += __shfl_xor_sync(0xffffffffu, c, off);
        }
        if (lane == 0) { ws[0] = a; wq2[0] = c; }
    }
    __syncthreads();
    float mu  = ws[0] * (1.f / D_);
    float var = wq2[0] * (1.f / D_) - mu * mu;
    float inv = rsqrtf(var + 1e-5f);
    float* o = out + (size_t)row * D_;
    for (int d = tid; d < D_; d += 256)
        o[d] = f2tf((xr[d] - mu) * inv * w[d] + b[d]);
}

// ---------------- split-K reduce: h += bias + sum(parts) ----------------------
__global__ void reduce_add(float* __restrict__ h, const float* __restrict__ bias,
                           const float* __restrict__ part, int nsplit) {
    const int row = blockIdx.x;
    const int c4  = threadIdx.x * 4;
    float4 acc = *(float4*)&h[(size_t)row * D_ + c4];
    float4 bv  = *(const float4*)&bias[c4];
    acc.x += bv.x; acc.y += bv.y; acc.z += bv.z; acc.w += bv.w;
    for (int s = 0; s < nsplit; s++) {
        float4 p = *(const float4*)&part[(size_t)s * M_ * D_ + (size_t)row * D_ + c4];
        acc.x += p.x; acc.y += p.y; acc.z += p.z; acc.w += p.w;
    }
    *(float4*)&h[(size_t)row * D_ + c4] = acc;
}

// ---------------- common GEMM helpers ------------------------------------------
#define CPA16(dst_u32, src_ptr) \
    asm volatile("cp.async.cg.shared.global [%0], [%1], 16;" :: "r"(dst_u32), "l"(src_ptr))

__device__ __forceinline__ unsigned smem_u32(const void* p) {
    return (unsigned)__cvta_generic_to_shared(p);
}

__device__ __forceinline__ void mma8(float c[4], const unsigned a[4], const unsigned b[2]) {
    asm volatile(
        "mma.sync.aligned.m16n8k8.row.col.f32.tf32.tf32.f32 "
        "{%0,%1,%2,%3}, {%4,%5,%6,%7}, {%8,%9}, {%0,%1,%2,%3};\n"
        : "+f"(c[0]), "+f"(c[1]), "+f"(c[2]), "+f"(c[3])
        : "r"(a[0]), "r"(a[1]), "r"(a[2]), "r"(a[3]), "r"(b[0]), "r"(b[1]));
}

// ---------------- standard GEMM body: 128 x BN_, 3-stage cp.async -------------
// MODE 0:+bias  1:f2tf(relu(+bias))  2:+bias+residual  3:raw  5:f2tf(+bias)
// GUARD 1: col<N guard.  lda = row stride of A; KL = K to process.
template <int BN_>
__device__ __forceinline__ void issue_stage(
    float* As, float* Bs, const float* A, const float* W,
    int lda, int Npad, int bm0, int bn0, int k0, int tid)
{
    constexpr int SB = BN_ + 8;
    #pragma unroll
    for (int j = 0; j < 4; j++) {
        int f = tid + j * 256;
        int row = f >> 3, c4 = (f & 7) << 2;
        CPA16(smem_u32(As + row * 36 + c4), A + (size_t)(bm0 + row) * lda + k0 + c4);
    }
    #pragma unroll
    for (int j = 0; j < BN_ / 32; j++) {
        int f = tid + j * 256;
        int row = (BN_ == 128) ? (f >> 5) : (f >> 4);
        int c4  = (BN_ == 128) ? ((f & 31) << 2) : ((f & 15) << 2);
        CPA16(smem_u32(Bs + row * SB + c4), W + (size_t)(k0 + row) * Npad + bn0 + c4);
    }
    asm volatile("cp.async.commit_group;");
}

template <int MODE, int BN_, int GUARD>
__device__ __forceinline__ void tgemm_body(
    const float* __restrict__ A, const float* __restrict__ W,
    const float* __restrict__ bias, const float* __restrict__ R,
    float* __restrict__ C, int lda, int KL, int N, int Npad, int bm0, int bn0)
{
    constexpr int SB  = BN_ + 8;
    constexpr int ASZ = 128 * 36;
    constexpr int BSZ = 32 * SB;
    constexpr int NI  = BN_ / 32;

    extern __shared__ float sm[];
    float* As = sm;
    float* Bs = sm + 3 * ASZ;

    const int tid  = threadIdx.x;
    const int lane = tid & 31;
    const int warp = tid >> 5;
    const int g    = lane >> 2;
    const int tg   = lane & 3;
    const int wm0  = (warp >> 2) * 64;
    const int wn0  = (warp & 3) * (BN_ / 4);

    float acc[4][NI][4];
    #pragma unroll
    for (int mi = 0; mi < 4; mi++)
        #pragma unroll
        for (int ni = 0; ni < NI; ni++)
            #pragma unroll
            for (int r = 0; r < 4; r++) acc[mi][ni][r] = 0.f;

    const int nIter = KL / 32;
    issue_stage<BN_>(As, Bs, A, W, lda, Npad, bm0, bn0, 0, tid);
    issue_stage<BN_>(As + ASZ, Bs + BSZ, A, W, lda, Npad, bm0, bn0, 32, tid);

    int st = 0, stw = 2;
    for (int t = 0; t < nIter; t++) {
        if (t + 1 < nIter) asm volatile("cp.async.wait_group 1;");
        else               asm volatile("cp.async.wait_group 0;");
        __syncthreads();

        const float* Ast = As + st * ASZ;
        const float* Bst = Bs + st * BSZ;
        #pragma unroll
        for (int kk = 0; kk < 32; kk += 8) {
            unsigned a[4][4], b[NI][2];
            #pragma unroll
            for (int mi = 0; mi < 4; mi++) {
                int r0 = wm0 + mi * 16 + g;
                a[mi][0] = __float_as_uint(Ast[(r0    ) * 36 + kk + tg]);
                a[mi][1] = __float_as_uint(Ast[(r0 + 8) * 36 + kk + tg]);
                a[mi][2] = __float_as_uint(Ast[(r0    ) * 36 + kk + tg + 4]);
                a[mi][3] = __float_as_uint(Ast[(r0 + 8) * 36 + kk + tg + 4]);
            }
            #pragma unroll
            for (int ni = 0; ni < NI; ni++) {
                int c = wn0 + ni * 8 + g;
                b[ni][0] = __float_as_uint(Bst[(kk + tg    ) * SB + c]);
                b[ni][1] = __float_as_uint(Bst[(kk + tg + 4) * SB + c]);
            }
            #pragma unroll
            for (int mi = 0; mi < 4; mi++)
                #pragma unroll
                for (int ni = 0; ni < NI; ni++)
                    mma8(acc[mi][ni], a[mi], b[ni]);
        }

        if (t + 2 < nIter) {
            issue_stage<BN_>(As + stw * ASZ, Bs + stw * BSZ, A, W, lda, Npad, bm0, bn0,
                             (t + 2) * 32, tid);
            stw = (stw == 2) ? 0 : stw + 1;
        }
        st = (st == 2) ? 0 : st + 1;
    }

    #pragma unroll
    for (int mi = 0; mi < 4; mi++) {
        #pragma unroll
        for (int ni = 0; ni < NI; ni++) {
            int row0 = bm0 + wm0 + mi * 16 + g;
            int col0 = bn0 + wn0 + ni * 8 + 2 * tg;
            #pragma unroll
            for (int rr = 0; rr < 2; rr++) {
                int row = row0 + rr * 8;
                #pragma unroll
                for (int cc = 0; cc < 2; cc++) {
                    int col = col0 + cc;
                    if (!GUARD || col < N) {
                        float v = acc[mi][ni][rr * 2 + cc];
                        if (MODE != 3) v += bias[col];
                        if (MODE == 1) v = f2tf(fmaxf(v, 0.f));
                        if (MODE == 2) v += R[(size_t)row * N + col];
                        if (MODE == 5) v = f2tf(v);
                        C[(size_t)row * N + col] = v;
                    }
                }
            }
        }
    }
}

// bm-fastest grid (B-tile reuse; for N >> M GEMMs)
template <int MODE, int BN_, int GUARD>
__global__ __launch_bounds__(256, 2)
void tgemm_s(const float* __restrict__ A, const float* __restrict__ W,
             const float* __restrict__ bias, const float* __restrict__ R,
             float* __restrict__ C, int K, int N, int Npad) {
    tgemm_body<MODE, BN_, GUARD>(A, W, bias, R, C, K, K, N, Npad,
                                 blockIdx.x * 128, blockIdx.y * BN_);
}

__global__ __launch_bounds__(256, 2)
void tgemm_qkv(const float* __restrict__ A,
               const float* __restrict__ wq, const float* __restrict__ wk,
               const float* __restrict__ wv,
               const float* __restrict__ bq, const float* __restrict__ bk,
               const float* __restrict__ bv,
               float* __restrict__ q, float* __restrict__ k, float* __restrict__ v) {
    int z = blockIdx.z;
    if (z == 2) {
        // V output tf32-rounded (feeds flash PV tensor-core product)
        tgemm_body<5, 128, 0>(A, wv, bv, nullptr, v, D_, D_, D_, D_,
                              blockIdx.y * 128, blockIdx.x * 128);
    } else {
        const float* W    = (z == 0) ? wq : wk;
        const float* bias = (z == 0) ? bq : bk;
        float*       C    = (z == 0) ? q  : k;
        tgemm_body<0, 128, 0>(A, W, bias, nullptr, C, D_, D_, D_, D_,
                              blockIdx.y * 128, blockIdx.x * 128);
    }
}

// split-K GEMM: blockIdx.z = split; raw partials to part[z][M][N]
__global__ __launch_bounds__(256, 2)
void tgemm_sk(const float* __restrict__ A, const float* __restrict__ W,
              float* __restrict__ part, int K, int KL, int N) {
    const int s = blockIdx.z;
    tgemm_body<3, 64, 0>(A + (size_t)s * KL,
                         W + (size_t)s * KL * N,
                         nullptr, nullptr,
                         part + (size_t)s * M_ * N,
                         K, KL, N, N,
                         blockIdx.y * 128, blockIdx.x * 64);
}

// ---------------- flash attention v3: fp32 scores + tensor-core P@V -----------
#define QT 64
#define KT 32
// smem (floats): Qs[64][68] | Ks[2][32][68] | Vs[2][32][68] | Ps[64][36] | Ssc[64]
#define FQ 0
#define FK (QT*68)
#define FV (FK + 2*KT*68)
#define FP (FV + 2*KT*68)
#define FS (FP + QT*36)
#define SMEM_ATT ((FS + 64) * 4)       // 61952 B -> 3 CTAs/SM

__global__ __launch_bounds__(256)
void flash_attn(const float* __restrict__ q,
                const float* __restrict__ k,
                const float* __restrict__ v,
                float* __restrict__ out) {
    extern __shared__ float sm[];
    float* Qs  = sm + FQ;
    float* Ks  = sm + FK;
    float* Vs  = sm + FV;
    float* Ps  = sm + FP;
    float* Ssc = sm + FS;

    const int q0  = (gridDim.x - 1 - blockIdx.x) * QT;   // longest tiles first
    const int h   = blockIdx.y;
    const int b   = blockIdx.z;
    const int tid = threadIdx.x;
    const int lane = tid & 31;
    const int warp = tid >> 5;
    const int qr  = tid >> 2;          // softmax layout: row
    const int qt  = tid & 3;           // softmax layout: quarter
    const int g   = lane >> 2;         // fragment layout
    const int tg  = lane & 3;
    const int wm  = (warp >> 1) * 16;  // PV warp m-slice (0/16/32/48)
    const int wn  = (warp & 1) * 32;   // PV warp n-half  (0/32)

    const size_t base = ((size_t)b * T_) * D_ + (size_t)h * HD_;
    const int qg = q0 + qr;

    // load Q tile (fp32)
    #pragma unroll
    for (int i = tid; i < QT * 16; i += 256) {
        int r = i >> 4, c4 = (i & 15) << 2;
        *(float4*)&Qs[r * 68 + c4] = *(const float4*)&q[base + (size_t)(q0 + r) * D_ + c4];
    }

    float oa[4][4];                    // O c-frags: [ni][{r,c}]
    #pragma unroll
    for (int ni = 0; ni < 4; ni++)
        #pragma unroll
        for (int r = 0; r < 4; r++) oa[ni][r] = 0.f;
    float m = -1e30f, l = 0.f;

    const int nTiles = (q0 + QT) / KT;

    // prologue: stream tile 0 into buffer 0
    #pragma unroll
    for (int j = 0; j < 2; j++) {
        int f = tid + j * 256;
        int r = f >> 4, c4 = (f & 15) << 2;
        CPA16(smem_u32(Ks + r * 68 + c4), k + base + (size_t)r * D_ + c4);
        CPA16(smem_u32(Vs + r * 68 + c4), v + base + (size_t)r * D_ + c4);
    }
    asm volatile("cp.async.commit_group;");

    for (int t0 = 0; t0 < nTiles; t0++) {
        const int s0  = t0 * KT;
        const int buf = t0 & 1;
        asm volatile("cp.async.wait_group 0;");
        __syncthreads();                               // A: K/V[buf] ready, Ps free

        const float* Kb = Ks + buf * KT * 68;
        const float* Vb = Vs + buf * KT * 68;

        // ---- scores (fp32) ----
        float s[8];
        #pragma unroll
        for (int j = 0; j < 8; j++) s[j] = 0.f;
        #pragma unroll
        for (int d4 = 0; d4 < 16; d4++) {
            float4 qv = *(const float4*)&Qs[qr * 68 + (d4 << 2)];
            #pragma unroll
            for (int j = 0; j < 8; j++) {
                float4 kv4 = *(const float4*)&Kb[(qt * 8 + j) * 68 + (d4 << 2)];
                s[j] += qv.x * kv4.x + qv.y * kv4.y + qv.z * kv4.z + qv.w * kv4.w;
            }
        }
        #pragma unroll
        for (int j = 0; j < 8; j++) {
            int kvg = s0 + qt * 8 + j;
            s[j] = (kvg <= qg) ? s[j] * 0.125f : -1e30f;
        }
        float tm = s[0];
        #pragma unroll
        for (int j = 1; j < 8; j++) tm = fmaxf(tm, s[j]);
        tm = fmaxf(tm, __shfl_xor_sync(0xffffffffu, tm, 1));
        tm = fmaxf(tm, __shfl_xor_sync(0xffffffffu, tm, 2));
        float m_new = fmaxf(m, tm);
        float scale = __expf(m - m_new);
        float ps = 0.f;
        #pragma unroll
        for (int j = 0; j < 8; j++) { s[j] = __expf(s[j] - m_new); ps += s[j]; }
        ps += __shfl_xor_sync(0xffffffffu, ps, 1);
        ps += __shfl_xor_sync(0xffffffffu, ps, 2);
        l = l * scale + ps;
        m = m_new;
        if (qt == 0) Ssc[qr] = scale;
        #pragma unroll
        for (int j = 0; j < 8; j++) Ps[qr * 36 + qt * 8 + j] = f2tf(s[j]);
        __syncthreads();                               // B: Ps/Ssc published

        // prefetch next K/V tile (safe: all warps past barrier A of this tile)
        if (t0 + 1 < nTiles) {
            const int nb  = (t0 + 1) & 1;
            const int ns0 = s0 + KT;
            #pragma unroll
            for (int j = 0; j < 2; j++) {
                int f = tid + j * 256;
                int r = f >> 4, c4 = (f & 15) << 2;
                CPA16(smem_u32(Ks + (nb * KT + r) * 68 + c4),
                      k + base + (size_t)(ns0 + r) * D_ + c4);
                CPA16(smem_u32(Vs + (nb * KT + r) * 68 + c4),
                      v + base + (size_t)(ns0 + r) * D_ + c4);
            }
            asm volatile("cp.async.commit_group;");
        }

        // ---- P @ V on tensor cores (m16n32k32 per warp) ----
        float sc0 = Ssc[wm + g], sc1 = Ssc[wm + g + 8];
        #pragma unroll
        for (int ni = 0; ni < 4; ni++) {
            oa[ni][0] *= sc0; oa[ni][1] *= sc0;
            oa[ni][2] *= sc1; oa[ni][3] *= sc1;
        }
        #pragma unroll
        for (int kk = 0; kk < KT; kk += 8) {
            unsigned a[4], bfr[4][2];
            a[0] = __float_as_uint(Ps[(wm + g    ) * 36 + kk + tg]);
            a[1] = __float_as_uint(Ps[(wm + g + 8) * 36 + kk + tg]);
            a[2] = __float_as_uint(Ps[(wm + g    ) * 36 + kk + tg + 4]);
            a[3] = __float_as_uint(Ps[(wm + g + 8) * 36 + kk + tg + 4]);
            #pragma unroll
            for (int ni = 0; ni < 4; ni++) {
                int c = wn + ni * 8 + g;
                bfr[ni][0] = __float_as_uint(Vb[(kk + tg    ) * 68 + c]);
                bfr[ni][1] = __float_as_uint(Vb[(kk + tg + 4) * 68 + c]);
            }
            #pragma unroll
            for (int ni = 0; ni < 4; ni++)
                mma8(oa[ni], a, bfr[ni]);
        }
    }

    // epilogue: publish 1/l per row, then write O frags
    __syncthreads();
    if (qt == 0) Ssc[qr] = 1.f / l;
    __syncthreads();
    float li0 = Ssc[wm + g], li1 = Ssc[wm + g + 8];
    #pragma unroll
    for (int ni = 0; ni < 4; ni++) {
        int col = wn + ni * 8 + 2 * tg;
        size_t r0 = base + (size_t)(q0 + wm + g    ) * D_ + col;
        size_t r1 = base + (size_t)(q0 + wm + g + 8) * D_ + col;
        out[r0    ] = f2tf(oa[ni][0] * li0);
        out[r0 + 1] = f2tf(oa[ni][1] * li0);
        out[r1    ] = f2tf(oa[ni][2] * li1);
        out[r1 + 1] = f2tf(oa[ni][3] * li1);
    }
}

// ---------------- launch -----------------------------------------------------
extern "C" void kernel_launch(void* const* d_in, const int* in_sizes, int n_in,
                              void* d_out, int out_size) {
    const int*   x       = (const int*)  d_in[0];
    const float* tok_emb = (const float*)d_in[1];
    const float* pos_emb = (const float*)d_in[2];
    const float* wq      = (const float*)d_in[3];
    const float* bq      = (const float*)d_in[4];
    const float* wk      = (const float*)d_in[5];
    const float* bk      = (const float*)d_in[6];
    const float* wv      = (const float*)d_in[7];
    const float* bv      = (const float*)d_in[8];
    const float* wo      = (const float*)d_in[9];
    const float* bo      = (const float*)d_in[10];
    const float* ln1_w   = (const float*)d_in[11];
    const float* ln1_b   = (const float*)d_in[12];
    const float* ln2_w   = (const float*)d_in[13];
    const float* ln2_b   = (const float*)d_in[14];
    const float* ffn_w1  = (const float*)d_in[15];
    const float* ffn_b1  = (const float*)d_in[16];
    const float* ffn_w2  = (const float*)d_in[17];
    const float* ffn_b2  = (const float*)d_in[18];
    const float* lnf_w   = (const float*)d_in[19];
    const float* lnf_b   = (const float*)d_in[20];
    const float* proj_w  = (const float*)d_in[21];
    const float* proj_b  = (const float*)d_in[22];
    float* logits = (float*)d_out;

    float *h, *ln, *q, *k, *v, *attn, *mid, *part;
    float *cwq, *cwk, *cwv, *cwo, *cw1, *cw2, *cpj;
    cudaGetSymbolAddress((void**)&h,    g_h);
    cudaGetSymbolAddress((void**)&ln,   g_ln);
    cudaGetSymbolAddress((void**)&q,    g_q);
    cudaGetSymbolAddress((void**)&k,    g_k);
    cudaGetSymbolAddress((void**)&v,    g_v);
    cudaGetSymbolAddress((void**)&attn, g_attn);
    cudaGetSymbolAddress((void**)&mid,  g_mid);
    cudaGetSymbolAddress((void**)&part, g_part);
    cudaGetSymbolAddress((void**)&cwq,  g_cwq);
    cudaGetSymbolAddress((void**)&cwk,  g_cwk);
    cudaGetSymbolAddress((void**)&cwv,  g_cwv);
    cudaGetSymbolAddress((void**)&cwo,  g_cwo);
    cudaGetSymbolAddress((void**)&cw1,  g_cw1);
    cudaGetSymbolAddress((void**)&cw2,  g_cw2);
    cudaGetSymbolAddress((void**)&cpj,  g_cpj);

    const int SMEM128 = 3 * (128 * 36 + 32 * 136) * 4;   // 107520 B
    const int SMEM64  = 3 * (128 * 36 + 32 * 72)  * 4;   // 82944 B
    cudaFuncSetAttribute(tgemm_sk,        cudaFuncAttributeMaxDynamicSharedMemorySize, SMEM64);
    cudaFuncSetAttribute(tgemm_s<1,128,0>,cudaFuncAttributeMaxDynamicSharedMemorySize, SMEM128);
    cudaFuncSetAttribute(tgemm_s<0,128,1>,cudaFuncAttributeMaxDynamicSharedMemorySize, SMEM128);
    cudaFuncSetAttribute(tgemm_qkv,       cudaFuncAttributeMaxDynamicSharedMemorySize, SMEM128);
    cudaFuncSetAttribute(flash_attn,      cudaFuncAttributeMaxDynamicSharedMemorySize, SMEM_ATT);

    dim3 gQKV(D_ / 128, M_ / 128, 3);        // (8,16,3)
    dim3 gWO(D_ / 64, M_ / 128, 2);          // (16,16,2) split-K=2
    dim3 gFF1(M_ / 128, FF_ / 128);          // (16,32)  bm-fastest
    dim3 gFF2(D_ / 64, M_ / 128, 4);         // (16,16,4) split-K=4
    dim3 gPRJ(M_ / 128, VP_ / 128);          // (16,393) bm-fastest
    dim3 gAT(T_ / QT, H_, B_);

    // Launch order: our #4 is flash_attn (ncu -s 5 lands on our 4th launch).
    conv_all<<<dim3(1024, 7), 256>>>(                                         // 1
        (const float4*)wq, (const float4*)wk, (const float4*)wv,
        (const float4*)wo, (const float4*)ffn_w1, (const float4*)ffn_w2,
        proj_w,
        (float4*)cwq, (float4*)cwk, (float4*)cwv,
        (float4*)cwo, (float4*)cw1, (float4*)cw2, cpj);
    embed_ln<<<M_, 256>>>(x, tok_emb, pos_emb, ln1_w, ln1_b, h, ln);          // 2

    for (int l = 0; l < L_; l++) {
        float* cwq_l = cwq + (size_t)l * D_ * D_;
        float* cwk_l = cwk + (size_t)l * D_ * D_;
        float* cwv_l = cwv + (size_t)l * D_ * D_;
        float* cwo_l = cwo + (size_t)l * D_ * D_;
        float* cw1_l = cw1 + (size_t)l * D_ * FF_;
        float* cw2_l = cw2 + (size_t)l * FF_ * D_;

        if (l > 0)
            ln_kernel<<<M_, 256>>>(h, ln1_w + l * D_, ln1_b + l * D_, ln);

        tgemm_qkv<<<gQKV, 256, SMEM128>>>(ln, cwq_l, cwk_l, cwv_l,
                                          bq + l * D_, bk + l * D_, bv + l * D_,
                                          q, k, v);                           // 3 (l=0)

        flash_attn<<<gAT, 256, SMEM_ATT>>>(q, k, v, attn);                    // 4 (l=0) <- profiled

        tgemm_sk<<<gWO, 256, SMEM64>>>(attn, cwo_l, part, D_, D_ / 2, D_);
        reduce_add<<<M_, 256>>>(h, bo + l * D_, part, 2);

        ln_kernel<<<M_, 256>>>(h, ln2_w + l * D_, ln2_b + l * D_, ln);

        tgemm_s<1,128,0><<<gFF1, 256, SMEM128>>>(ln, cw1_l, ffn_b1 + l * FF_,
                                                 nullptr, mid, D_, FF_, FF_);

        tgemm_sk<<<gFF2, 256, SMEM64>>>(mid, cw2_l, part, FF_, FF_ / 4, D_);
        reduce_add<<<M_, 256>>>(h, ffn_b2 + l * D_, part, 4);
    }

    ln_kernel<<<M_, 256>>>(h, lnf_w, lnf_b, ln);
    tgemm_s<0,128,1><<<gPRJ, 256, SMEM128>>>(ln, cpj, proj_b, nullptr, logits,
                                             D_, V_, VP_);
}

// round 13
// speedup vs baseline: 2.3804x; 1.9356x over previous
#include <cuda_runtime.h>
#include <math.h>

#define B_  2
#define T_  1024
#define D_  1024
#define H_  16
#define HD_ 64
#define FF_ 4096
#define L_  6
#define V_  50257
#define M_  (B_*T_)        // 2048 rows
#define VP_ 50304          // V padded to 128

// ---------------- scratch (static device globals; no allocation) -------------
__device__ float g_h   [M_*D_];
__device__ float g_ln  [M_*D_];
__device__ float g_q   [M_*D_];
__device__ float g_kt  [M_*D_];          // K stored TRANSPOSED: [(b*D + hd)*T + t]
__device__ float g_v   [M_*D_];
__device__ float g_attn[M_*D_];
__device__ float g_mid [M_*FF_];
__device__ float g_part[4*M_*D_];        // split-K partials (32 MB)
// tf32-preconverted weights (row-major [K][N])
__device__ float g_cwq [L_*D_*D_];
__device__ float g_cwk [L_*D_*D_];
__device__ float g_cwv [L_*D_*D_];
__device__ float g_cwo [L_*D_*D_];
__device__ float g_cw1 [L_*D_*FF_];
__device__ float g_cw2 [L_*FF_*D_];
__device__ float g_cpj [(size_t)D_*VP_];

__device__ __forceinline__ float f2tf(float x) {
    unsigned u;
    asm("cvt.rna.tf32.f32 %0, %1;" : "=r"(u) : "f"(x));
    return __uint_as_float(u);
}

// ---------------- single fused weight conversion -------------------------------
__global__ void conv_all(const float4* __restrict__ wq, const float4* __restrict__ wk,
                         const float4* __restrict__ wv, const float4* __restrict__ wo,
                         const float4* __restrict__ w1, const float4* __restrict__ w2,
                         const float*  __restrict__ pj,
                         float4* __restrict__ cwq, float4* __restrict__ cwk,
                         float4* __restrict__ cwv, float4* __restrict__ cwo,
                         float4* __restrict__ cw1, float4* __restrict__ cw2,
                         float*  __restrict__ cpj) {
    const int seg = blockIdx.y;
    if (seg < 6) {
        const float4* s; float4* d; int n4;
        switch (seg) {
            case 0: s = wq; d = cwq; n4 = L_*D_*D_/4;  break;
            case 1: s = wk; d = cwk; n4 = L_*D_*D_/4;  break;
            case 2: s = wv; d = cwv; n4 = L_*D_*D_/4;  break;
            case 3: s = wo; d = cwo; n4 = L_*D_*D_/4;  break;
            case 4: s = w1; d = cw1; n4 = L_*D_*FF_/4; break;
            default:s = w2; d = cw2; n4 = L_*D_*FF_/4; break;
        }
        for (int i = blockIdx.x * blockDim.x + threadIdx.x; i < n4;
             i += gridDim.x * blockDim.x) {
            float4 v = s[i];
            d[i] = make_float4(f2tf(v.x), f2tf(v.y), f2tf(v.z), f2tf(v.w));
        }
    } else {
        const long long total = (long long)D_ * VP_;
        for (long long i = (long long)blockIdx.x * blockDim.x + threadIdx.x; i < total;
             i += (long long)gridDim.x * blockDim.x) {
            int row = (int)(i / VP_), col = (int)(i - (long long)row * VP_);
            cpj[i] = (col < V_) ? f2tf(pj[(size_t)row * V_ + col]) : 0.f;
        }
    }
}

// ---------------- fused embedding + layer-0 LN1 --------------------------------
__global__ void embed_ln(const int* __restrict__ x,
                         const float* __restrict__ tok,
                         const float* __restrict__ pos,
                         const float* __restrict__ w,
                         const float* __restrict__ b,
                         float* __restrict__ h, float* __restrict__ lnout) {
    const int row  = blockIdx.x;
    const int tid  = threadIdx.x;
    const int lane = tid & 31;
    const int warp = tid >> 5;
    const int t    = row % T_;
    const int id   = x[row];
    const float* te = tok + (size_t)id * D_;
    const float* pe = pos + (size_t)t  * D_;

    float e[4];
    float s = 0.f, sq = 0.f;
    #pragma unroll
    for (int i = 0; i < 4; i++) {
        int d = tid + i * 256;
        e[i] = te[d] + pe[d];
        s += e[i]; sq += e[i] * e[i];
        h[(size_t)row * D_ + d] = e[i];
    }
    #pragma unroll
    for (int off = 16; off > 0; off >>= 1) {
        s  += __shfl_xor_sync(0xffffffffu, s,  off);
        sq += __shfl_xor_sync(0xffffffffu, sq, off);
    }
    __shared__ float ws[8], wq2[8];
    if (lane == 0) { ws[warp] = s; wq2[warp] = sq; }
    __syncthreads();
    if (warp == 0) {
        float a = (lane < 8) ? ws[lane]  : 0.f;
        float c = (lane < 8) ? wq2[lane] : 0.f;
        #pragma unroll
        for (int off = 4; off > 0; off >>= 1) {
            a += __shfl_xor_sync(0xffffffffu, a, off);
            c += __shfl_xor_sync(0xffffffffu, c, off);
        }
        if (lane == 0) { ws[0] = a; wq2[0] = c; }
    }
    __syncthreads();
    float mu  = ws[0] * (1.f / D_);
    float var = wq2[0] * (1.f / D_) - mu * mu;
    float inv = rsqrtf(var + 1e-5f);
    #pragma unroll
    for (int i = 0; i < 4; i++) {
        int d = tid + i * 256;
        lnout[(size_t)row * D_ + d] = f2tf((e[i] - mu) * inv * w[d] + b[d]);
    }
}

// ---------------- layernorm (shuffle reduce, tf32-rounded output) -------------
__global__ void ln_kernel(const float* __restrict__ in,
                          const float* __restrict__ w,
                          const float* __restrict__ b,
                          float* __restrict__ out) {
    const int row  = blockIdx.x;
    const int tid  = threadIdx.x;
    const int lane = tid & 31;
    const int warp = tid >> 5;
    const float* xr = in + (size_t)row * D_;

    float s = 0.f, sq = 0.f;
    for (int d = tid; d < D_; d += 256) {
        float v = xr[d];
        s += v; sq += v * v;
    }
    #pragma unroll
    for (int off = 16; off > 0; off >>= 1) {
        s  += __shfl_xor_sync(0xffffffffu, s,  off);
        sq += __shfl_xor_sync(0xffffffffu, sq, off);
    }
    __shared__ float ws[8], wq2[8];
    if (lane == 0) { ws[warp] = s; wq2[warp] = sq; }
    __syncthreads();
    if (warp == 0) {
        float a = (lane < 8) ? ws[lane]  : 0.f;
        float c = (lane < 8) ? wq2[lane] : 0.f;
        #pragma unroll
        for (int off = 4; off > 0; off >>= 1) {
            a += __shfl_xor_sync(0xffffffffu, a, off);
            c += __shfl_xor_sync(0xffffffffu, c, off);
        }
        if (lane == 0) { ws[0] = a; wq2[0] = c; }
    }
    __syncthreads();
    float mu  = ws[0] * (1.f / D_);
    float var = wq2[0] * (1.f / D_) - mu * mu;
    float inv = rsqrtf(var + 1e-5f);
    float* o = out + (size_t)row * D_;
    for (int d = tid; d < D_; d += 256)
        o[d] = f2tf((xr[d] - mu) * inv * w[d] + b[d]);
}

// ---------------- split-K reduce: h += bias + sum(parts) ----------------------
__global__ void reduce_add(float* __restrict__ h, const float* __restrict__ bias,
                           const float* __restrict__ part, int nsplit) {
    const int row = blockIdx.x;
    const int c4  = threadIdx.x * 4;
    float4 acc = *(float4*)&h[(size_t)row * D_ + c4];
    float4 bv  = *(const float4*)&bias[c4];
    acc.x += bv.x; acc.y += bv.y; acc.z += bv.z; acc.w += bv.w;
    for (int s = 0; s < nsplit; s++) {
        float4 p = *(const float4*)&part[(size_t)s * M_ * D_ + (size_t)row * D_ + c4];
        acc.x += p.x; acc.y += p.y; acc.z += p.z; acc.w += p.w;
    }
    *(float4*)&h[(size_t)row * D_ + c4] = acc;
}

// ---------------- common GEMM helpers ------------------------------------------
#define CPA16(dst_u32, src_ptr) \
    asm volatile("cp.async.cg.shared.global [%0], [%1], 16;" :: "r"(dst_u32), "l"(src_ptr))

__device__ __forceinline__ unsigned smem_u32(const void* p) {
    return (unsigned)__cvta_generic_to_shared(p);
}

__device__ __forceinline__ void mma8(float c[4], const unsigned a[4], const unsigned b[2]) {
    asm volatile(
        "mma.sync.aligned.m16n8k8.row.col.f32.tf32.tf32.f32 "
        "{%0,%1,%2,%3}, {%4,%5,%6,%7}, {%8,%9}, {%0,%1,%2,%3};\n"
        : "+f"(c[0]), "+f"(c[1]), "+f"(c[2]), "+f"(c[3])
        : "r"(a[0]), "r"(a[1]), "r"(a[2]), "r"(a[3]), "r"(b[0]), "r"(b[1]));
}

// ---------------- standard GEMM body: 128 x BN_, 3-stage cp.async -------------
// MODE 0:+bias 1:f2tf(relu(+bias)) 2:+bias+residual 3:raw 5:f2tf(+bias)
// MODE 6: f2tf(+bias), store TRANSPOSED to kt[(b*D+col)*T + t]
// GUARD 1: col<N guard.  lda = row stride of A; KL = K to process.
template <int BN_>
__device__ __forceinline__ void issue_stage(
    float* As, float* Bs, const float* A, const float* W,
    int lda, int Npad, int bm0, int bn0, int k0, int tid)
{
    constexpr int SB = BN_ + 8;
    #pragma unroll
    for (int j = 0; j < 4; j++) {
        int f = tid + j * 256;
        int row = f >> 3, c4 = (f & 7) << 2;
        CPA16(smem_u32(As + row * 36 + c4), A + (size_t)(bm0 + row) * lda + k0 + c4);
    }
    #pragma unroll
    for (int j = 0; j < BN_ / 32; j++) {
        int f = tid + j * 256;
        int row = (BN_ == 128) ? (f >> 5) : (f >> 4);
        int c4  = (BN_ == 128) ? ((f & 31) << 2) : ((f & 15) << 2);
        CPA16(smem_u32(Bs + row * SB + c4), W + (size_t)(k0 + row) * Npad + bn0 + c4);
    }
    asm volatile("cp.async.commit_group;");
}

template <int MODE, int BN_, int GUARD>
__device__ __forceinline__ void tgemm_body(
    const float* __restrict__ A, const float* __restrict__ W,
    const float* __restrict__ bias, const float* __restrict__ R,
    float* __restrict__ C, int lda, int KL, int N, int Npad, int bm0, int bn0)
{
    constexpr int SB  = BN_ + 8;
    constexpr int ASZ = 128 * 36;
    constexpr int BSZ = 32 * SB;
    constexpr int NI  = BN_ / 32;

    extern __shared__ float sm[];
    float* As = sm;
    float* Bs = sm + 3 * ASZ;

    const int tid  = threadIdx.x;
    const int lane = tid & 31;
    const int warp = tid >> 5;
    const int g    = lane >> 2;
    const int tg   = lane & 3;
    const int wm0  = (warp >> 2) * 64;
    const int wn0  = (warp & 3) * (BN_ / 4);

    float acc[4][NI][4];
    #pragma unroll
    for (int mi = 0; mi < 4; mi++)
        #pragma unroll
        for (int ni = 0; ni < NI; ni++)
            #pragma unroll
            for (int r = 0; r < 4; r++) acc[mi][ni][r] = 0.f;

    const int nIter = KL / 32;
    issue_stage<BN_>(As, Bs, A, W, lda, Npad, bm0, bn0, 0, tid);
    issue_stage<BN_>(As + ASZ, Bs + BSZ, A, W, lda, Npad, bm0, bn0, 32, tid);

    int st = 0, stw = 2;
    for (int t = 0; t < nIter; t++) {
        if (t + 1 < nIter) asm volatile("cp.async.wait_group 1;");
        else               asm volatile("cp.async.wait_group 0;");
        __syncthreads();

        const float* Ast = As + st * ASZ;
        const float* Bst = Bs + st * BSZ;
        #pragma unroll
        for (int kk = 0; kk < 32; kk += 8) {
            unsigned a[4][4], b[NI][2];
            #pragma unroll
            for (int mi = 0; mi < 4; mi++) {
                int r0 = wm0 + mi * 16 + g;
                a[mi][0] = __float_as_uint(Ast[(r0    ) * 36 + kk + tg]);
                a[mi][1] = __float_as_uint(Ast[(r0 + 8) * 36 + kk + tg]);
                a[mi][2] = __float_as_uint(Ast[(r0    ) * 36 + kk + tg + 4]);
                a[mi][3] = __float_as_uint(Ast[(r0 + 8) * 36 + kk + tg + 4]);
            }
            #pragma unroll
            for (int ni = 0; ni < NI; ni++) {
                int c = wn0 + ni * 8 + g;
                b[ni][0] = __float_as_uint(Bst[(kk + tg    ) * SB + c]);
                b[ni][1] = __float_as_uint(Bst[(kk + tg + 4) * SB + c]);
            }
            #pragma unroll
            for (int mi = 0; mi < 4; mi++)
                #pragma unroll
                for (int ni = 0; ni < NI; ni++)
                    mma8(acc[mi][ni], a[mi], b[ni]);
        }

        if (t + 2 < nIter) {
            issue_stage<BN_>(As + stw * ASZ, Bs + stw * BSZ, A, W, lda, Npad, bm0, bn0,
                             (t + 2) * 32, tid);
            stw = (stw == 2) ? 0 : stw + 1;
        }
        st = (st == 2) ? 0 : st + 1;
    }

    #pragma unroll
    for (int mi = 0; mi < 4; mi++) {
        #pragma unroll
        for (int ni = 0; ni < NI; ni++) {
            int row0 = bm0 + wm0 + mi * 16 + g;
            int col0 = bn0 + wn0 + ni * 8 + 2 * tg;
            #pragma unroll
            for (int rr = 0; rr < 2; rr++) {
                int row = row0 + rr * 8;
                #pragma unroll
                for (int cc = 0; cc < 2; cc++) {
                    int col = col0 + cc;
                    if (!GUARD || col < N) {
                        float v = acc[mi][ni][rr * 2 + cc];
                        if (MODE != 3) v += bias[col];
                        if (MODE == 1) v = f2tf(fmaxf(v, 0.f));
                        if (MODE == 2) v += R[(size_t)row * N + col];
                        if (MODE == 5) v = f2tf(v);
                        if (MODE == 6) {
                            C[((size_t)(row >> 10) * D_ + col) * T_ + (row & (T_ - 1))]
                                = f2tf(v);
                        } else {
                            C[(size_t)row * N + col] = v;
                        }
                    }
                }
            }
        }
    }
}

// bm-fastest grid (B-tile reuse; for N >> M GEMMs)
template <int MODE, int BN_, int GUARD>
__global__ __launch_bounds__(256, 2)
void tgemm_s(const float* __restrict__ A, const float* __restrict__ W,
             const float* __restrict__ bias, const float* __restrict__ R,
             float* __restrict__ C, int K, int N, int Npad) {
    tgemm_body<MODE, BN_, GUARD>(A, W, bias, R, C, K, K, N, Npad,
                                 blockIdx.x * 128, blockIdx.y * BN_);
}

__global__ __launch_bounds__(256, 2)
void tgemm_qkv(const float* __restrict__ A,
               const float* __restrict__ wq, const float* __restrict__ wk,
               const float* __restrict__ wv,
               const float* __restrict__ bq, const float* __restrict__ bk,
               const float* __restrict__ bv,
               float* __restrict__ q, float* __restrict__ kt, float* __restrict__ v) {
    int z = blockIdx.z;
    if (z == 0) {
        tgemm_body<5, 128, 0>(A, wq, bq, nullptr, q, D_, D_, D_, D_,
                              blockIdx.y * 128, blockIdx.x * 128);
    } else if (z == 1) {
        // K written transposed + tf32 (feeds flash score mma B operand)
        tgemm_body<6, 128, 0>(A, wk, bk, nullptr, kt, D_, D_, D_, D_,
                              blockIdx.y * 128, blockIdx.x * 128);
    } else {
        tgemm_body<5, 128, 0>(A, wv, bv, nullptr, v, D_, D_, D_, D_,
                              blockIdx.y * 128, blockIdx.x * 128);
    }
}

// split-K GEMM: blockIdx.z = split; raw partials to part[z][M][N]
__global__ __launch_bounds__(256, 2)
void tgemm_sk(const float* __restrict__ A, const float* __restrict__ W,
              float* __restrict__ part, int K, int KL, int N) {
    const int s = blockIdx.z;
    tgemm_body<3, 64, 0>(A + (size_t)s * KL,
                         W + (size_t)s * KL * N,
                         nullptr, nullptr,
                         part + (size_t)s * M_ * N,
                         K, KL, N, N,
                         blockIdx.y * 128, blockIdx.x * 64);
}

// ---------------- flash attention v4: full tensor-core (QK^T + PV) ------------
// QT=128 rows/block, 8 warps each own a private m16 slice -> register softmax.
// K consumed from the transposed global layout kt[(b*D + hd)*T + t].
#define QT 128
#define KT 32
// smem floats: Qs[128][68] | Kt[2][64][36] | Vs[2][32][68] | Ps[128][36]
#define FQ  0
#define FKT (QT*68)
#define FVV (FKT + 2*64*36)
#define FPP (FVV + 2*KT*68)
#define SMEM_ATT ((FPP + QT*36) * 4)    // 89088 B

__global__ __launch_bounds__(256)
void flash_attn(const float* __restrict__ q,
                const float* __restrict__ kt,
                const float* __restrict__ v,
                float* __restrict__ out) {
    extern __shared__ float sm[];
    float* Qs = sm + FQ;
    float* Kt = sm + FKT;
    float* Vs = sm + FVV;
    float* Ps = sm + FPP;

    const int q0   = (gridDim.x - 1 - blockIdx.x) * QT;  // longest first
    const int h    = blockIdx.y;
    const int b    = blockIdx.z;
    const int tid  = threadIdx.x;
    const int lane = tid & 31;
    const int warp = tid >> 5;
    const int g    = lane >> 2;
    const int tg   = lane & 3;
    const int wm   = warp * 16;

    const size_t base   = ((size_t)b * T_) * D_ + (size_t)h * HD_;
    const size_t base_k = ((size_t)b * D_ + (size_t)h * HD_) * T_;

    // load Q tile (tf32 values in fp32 container)
    #pragma unroll
    for (int i = tid; i < QT * 16; i += 256) {
        int r = i >> 4, c4 = (i & 15) << 2;
        *(float4*)&Qs[r * 68 + c4] = *(const float4*)&q[base + (size_t)(q0 + r) * D_ + c4];
    }

    float oa[8][4];
    #pragma unroll
    for (int ni = 0; ni < 8; ni++)
        #pragma unroll
        for (int r = 0; r < 4; r++) oa[ni][r] = 0.f;
    float m0 = -1e30f, m1 = -1e30f, l0 = 0.f, l1 = 0.f;

    const int nTiles = (q0 + QT) / KT;

    // prologue: tile 0 -> stage 0
    #pragma unroll
    for (int j = 0; j < 2; j++) {
        int f = tid + j * 256;
        int rd = f >> 3, chd = (f & 7) << 2;
        CPA16(smem_u32(Kt + rd * 36 + chd), kt + base_k + (size_t)rd * T_ + chd);
        int rv = f >> 4, chv = (f & 15) << 2;
        CPA16(smem_u32(Vs + rv * 68 + chv), v + base + (size_t)rv * D_ + chv);
    }
    asm volatile("cp.async.commit_group;");

    for (int t0 = 0; t0 < nTiles; t0++) {
        const int s0  = t0 * KT;
        const int buf = t0 & 1;
        asm volatile("cp.async.wait_group 0;");
        __syncthreads();                              // data[buf] ready; buf^1 free

        if (t0 + 1 < nTiles) {
            const int nb  = buf ^ 1;
            const int ns0 = s0 + KT;
            #pragma unroll
            for (int j = 0; j < 2; j++) {
                int f = tid + j * 256;
                int rd = f >> 3, chd = (f & 7) << 2;
                CPA16(smem_u32(Kt + nb * 64 * 36 + rd * 36 + chd),
                      kt + base_k + (size_t)rd * T_ + ns0 + chd);
                int rv = f >> 4, chv = (f & 15) << 2;
                CPA16(smem_u32(Vs + nb * KT * 68 + rv * 68 + chv),
                      v + base + (size_t)(ns0 + rv) * D_ + chv);
            }
            asm volatile("cp.async.commit_group;");
        }

        const float* Ktb = Kt + buf * 64 * 36;
        const float* Vb  = Vs + buf * KT * 68;

        // ---- scores: m16 n32 k64 on tensor cores ----
        float sf[4][4];
        #pragma unroll
        for (int ni = 0; ni < 4; ni++)
            #pragma unroll
            for (int r = 0; r < 4; r++) sf[ni][r] = 0.f;
        #pragma unroll
        for (int kk = 0; kk < 64; kk += 8) {
            unsigned a[4], bfr[4][2];
            a[0] = __float_as_uint(Qs[(wm + g    ) * 68 + kk + tg]);
            a[1] = __float_as_uint(Qs[(wm + g + 8) * 68 + kk + tg]);
            a[2] = __float_as_uint(Qs[(wm + g    ) * 68 + kk + tg + 4]);
            a[3] = __float_as_uint(Qs[(wm + g + 8) * 68 + kk + tg + 4]);
            #pragma unroll
            for (int ni = 0; ni < 4; ni++) {
                int c = ni * 8 + g;
                bfr[ni][0] = __float_as_uint(Ktb[(kk + tg    ) * 36 + c]);
                bfr[ni][1] = __float_as_uint(Ktb[(kk + tg + 4) * 36 + c]);
            }
            #pragma unroll
            for (int ni = 0; ni < 4; ni++)
                mma8(sf[ni], a, bfr[ni]);
        }

        // ---- mask + scale + register softmax (rows r0=wm+g, r1=r0+8) ----
        const int r0 = q0 + wm + g;
        const int r1 = r0 + 8;
        #pragma unroll
        for (int ni = 0; ni < 4; ni++) {
            int col = s0 + ni * 8 + 2 * tg;
            sf[ni][0] = (col     <= r0) ? sf[ni][0] * 0.125f : -1e30f;
            sf[ni][1] = (col + 1 <= r0) ? sf[ni][1] * 0.125f : -1e30f;
            sf[ni][2] = (col     <= r1) ? sf[ni][2] * 0.125f : -1e30f;
            sf[ni][3] = (col + 1 <= r1) ? sf[ni][3] * 0.125f : -1e30f;
        }
        float tm0 = -1e30f, tm1 = -1e30f;
        #pragma unroll
        for (int ni = 0; ni < 4; ni++) {
            tm0 = fmaxf(tm0, fmaxf(sf[ni][0], sf[ni][1]));
            tm1 = fmaxf(tm1, fmaxf(sf[ni][2], sf[ni][3]));
        }
        tm0 = fmaxf(tm0, __shfl_xor_sync(0xffffffffu, tm0, 1));
        tm0 = fmaxf(tm0, __shfl_xor_sync(0xffffffffu, tm0, 2));
        tm1 = fmaxf(tm1, __shfl_xor_sync(0xffffffffu, tm1, 1));
        tm1 = fmaxf(tm1, __shfl_xor_sync(0xffffffffu, tm1, 2));
        float m0n = fmaxf(m0, tm0), m1n = fmaxf(m1, tm1);
        float sc0 = __expf(m0 - m0n), sc1 = __expf(m1 - m1n);
        float ps0 = 0.f, ps1 = 0.f;
        #pragma unroll
        for (int ni = 0; ni < 4; ni++) {
            sf[ni][0] = __expf(sf[ni][0] - m0n); ps0 += sf[ni][0];
            sf[ni][1] = __expf(sf[ni][1] - m0n); ps0 += sf[ni][1];
            sf[ni][2] = __expf(sf[ni][2] - m1n); ps1 += sf[ni][2];
            sf[ni][3] = __expf(sf[ni][3] - m1n); ps1 += sf[ni][3];
        }
        ps0 += __shfl_xor_sync(0xffffffffu, ps0, 1);
        ps0 += __shfl_xor_sync(0xffffffffu, ps0, 2);
        ps1 += __shfl_xor_sync(0xffffffffu, ps1, 1);
        ps1 += __shfl_xor_sync(0xffffffffu, ps1, 2);
        l0 = l0 * sc0 + ps0;  l1 = l1 * sc1 + ps1;
        m0 = m0n;  m1 = m1n;
        #pragma unroll
        for (int ni = 0; ni < 8; ni++) {
            oa[ni][0] *= sc0; oa[ni][1] *= sc0;
            oa[ni][2] *= sc1; oa[ni][3] *= sc1;
        }

        // ---- publish P (warp-local rows, tf32) ----
        #pragma unroll
        for (int ni = 0; ni < 4; ni++) {
            int cb = ni * 8 + 2 * tg;
            Ps[(wm + g    ) * 36 + cb    ] = f2tf(sf[ni][0]);
            Ps[(wm + g    ) * 36 + cb + 1] = f2tf(sf[ni][1]);
            Ps[(wm + g + 8) * 36 + cb    ] = f2tf(sf[ni][2]);
            Ps[(wm + g + 8) * 36 + cb + 1] = f2tf(sf[ni][3]);
        }
        __syncwarp();

        // ---- P @ V: m16 n64 k32 on tensor cores ----
        #pragma unroll
        for (int kk = 0; kk < KT; kk += 8) {
            unsigned a2[4], b2[2];
            a2[0] = __float_as_uint(Ps[(wm + g    ) * 36 + kk + tg]);
            a2[1] = __float_as_uint(Ps[(wm + g + 8) * 36 + kk + tg]);
            a2[2] = __float_as_uint(Ps[(wm + g    ) * 36 + kk + tg + 4]);
            a2[3] = __float_as_uint(Ps[(wm + g + 8) * 36 + kk + tg + 4]);
            #pragma unroll
            for (int ni = 0; ni < 8; ni++) {
                int c = ni * 8 + g;
                b2[0] = __float_as_uint(Vb[(kk + tg    ) * 68 + c]);
                b2[1] = __float_as_uint(Vb[(kk + tg + 4) * 68 + c]);
                mma8(oa[ni], a2, b2);
            }
        }
    }

    // ---- epilogue: divide by l, tf32-round, float2 stores ----
    float li0 = 1.f / l0, li1 = 1.f / l1;
    #pragma unroll
    for (int ni = 0; ni < 8; ni++) {
        int col = ni * 8 + 2 * tg;
        float2 o0 = make_float2(f2tf(oa[ni][0] * li0), f2tf(oa[ni][1] * li0));
        float2 o1 = make_float2(f2tf(oa[ni][2] * li1), f2tf(oa[ni][3] * li1));
        *(float2*)&out[base + (size_t)(q0 + wm + g    ) * D_ + col] = o0;
        *(float2*)&out[base + (size_t)(q0 + wm + g + 8) * D_ + col] = o1;
    }
}

// ---------------- launch -----------------------------------------------------
extern "C" void kernel_launch(void* const* d_in, const int* in_sizes, int n_in,
                              void* d_out, int out_size) {
    const int*   x       = (const int*)  d_in[0];
    const float* tok_emb = (const float*)d_in[1];
    const float* pos_emb = (const float*)d_in[2];
    const float* wq      = (const float*)d_in[3];
    const float* bq      = (const float*)d_in[4];
    const float* wk      = (const float*)d_in[5];
    const float* bk      = (const float*)d_in[6];
    const float* wv      = (const float*)d_in[7];
    const float* bv      = (const float*)d_in[8];
    const float* wo      = (const float*)d_in[9];
    const float* bo      = (const float*)d_in[10];
    const float* ln1_w   = (const float*)d_in[11];
    const float* ln1_b   = (const float*)d_in[12];
    const float* ln2_w   = (const float*)d_in[13];
    const float* ln2_b   = (const float*)d_in[14];
    const float* ffn_w1  = (const float*)d_in[15];
    const float* ffn_b1  = (const float*)d_in[16];
    const float* ffn_w2  = (const float*)d_in[17];
    const float* ffn_b2  = (const float*)d_in[18];
    const float* lnf_w   = (const float*)d_in[19];
    const float* lnf_b   = (const float*)d_in[20];
    const float* proj_w  = (const float*)d_in[21];
    const float* proj_b  = (const float*)d_in[22];
    float* logits = (float*)d_out;

    float *h, *ln, *q, *kt, *v, *attn, *mid, *part;
    float *cwq, *cwk, *cwv, *cwo, *cw1, *cw2, *cpj;
    cudaGetSymbolAddress((void**)&h,    g_h);
    cudaGetSymbolAddress((void**)&ln,   g_ln);
    cudaGetSymbolAddress((void**)&q,    g_q);
    cudaGetSymbolAddress((void**)&kt,   g_kt);
    cudaGetSymbolAddress((void**)&v,    g_v);
    cudaGetSymbolAddress((void**)&attn, g_attn);
    cudaGetSymbolAddress((void**)&mid,  g_mid);
    cudaGetSymbolAddress((void**)&part, g_part);
    cudaGetSymbolAddress((void**)&cwq,  g_cwq);
    cudaGetSymbolAddress((void**)&cwk,  g_cwk);
    cudaGetSymbolAddress((void**)&cwv,  g_cwv);
    cudaGetSymbolAddress((void**)&cwo,  g_cwo);
    cudaGetSymbolAddress((void**)&cw1,  g_cw1);
    cudaGetSymbolAddress((void**)&cw2,  g_cw2);
    cudaGetSymbolAddress((void**)&cpj,  g_cpj);

    const int SMEM128 = 3 * (128 * 36 + 32 * 136) * 4;   // 107520 B
    const int SMEM64  = 3 * (128 * 36 + 32 * 72)  * 4;   // 82944 B
    cudaFuncSetAttribute(tgemm_sk,        cudaFuncAttributeMaxDynamicSharedMemorySize, SMEM64);
    cudaFuncSetAttribute(tgemm_s<1,128,0>,cudaFuncAttributeMaxDynamicSharedMemorySize, SMEM128);
    cudaFuncSetAttribute(tgemm_s<0,128,1>,cudaFuncAttributeMaxDynamicSharedMemorySize, SMEM128);
    cudaFuncSetAttribute(tgemm_qkv,       cudaFuncAttributeMaxDynamicSharedMemorySize, SMEM128);
    cudaFuncSetAttribute(flash_attn,      cudaFuncAttributeMaxDynamicSharedMemorySize, SMEM_ATT);

    dim3 gQKV(D_ / 128, M_ / 128, 3);        // (8,16,3)
    dim3 gWO(D_ / 64, M_ / 128, 2);          // (16,16,2) split-K=2
    dim3 gFF1(M_ / 128, FF_ / 128);          // (16,32)  bm-fastest
    dim3 gFF2(D_ / 64, M_ / 128, 4);         // (16,16,4) split-K=4
    dim3 gPRJ(M_ / 128, VP_ / 128);          // (16,393) bm-fastest
    dim3 gAT(T_ / QT, H_, B_);               // (8,16,2)

    // Launch order: our #4 is flash_attn (ncu -s 5 lands on our 4th launch).
    conv_all<<<dim3(1024, 7), 256>>>(                                         // 1
        (const float4*)wq, (const float4*)wk, (const float4*)wv,
        (const float4*)wo, (const float4*)ffn_w1, (const float4*)ffn_w2,
        proj_w,
        (float4*)cwq, (float4*)cwk, (float4*)cwv,
        (float4*)cwo, (float4*)cw1, (float4*)cw2, cpj);
    embed_ln<<<M_, 256>>>(x, tok_emb, pos_emb, ln1_w, ln1_b, h, ln);          // 2

    for (int l = 0; l < L_; l++) {
        float* cwq_l = cwq + (size_t)l * D_ * D_;
        float* cwk_l = cwk + (size_t)l * D_ * D_;
        float* cwv_l = cwv + (size_t)l * D_ * D_;
        float* cwo_l = cwo + (size_t)l * D_ * D_;
        float* cw1_l = cw1 + (size_t)l * D_ * FF_;
        float* cw2_l = cw2 + (size_t)l * FF_ * D_;

        if (l > 0)
            ln_kernel<<<M_, 256>>>(h, ln1_w + l * D_, ln1_b + l * D_, ln);

        tgemm_qkv<<<gQKV, 256, SMEM128>>>(ln, cwq_l, cwk_l, cwv_l,
                                          bq + l * D_, bk + l * D_, bv + l * D_,
                                          q, kt, v);                          // 3 (l=0)

        flash_attn<<<gAT, 256, SMEM_ATT>>>(q, kt, v, attn);                   // 4 (l=0) <- profiled

        tgemm_sk<<<gWO, 256, SMEM64>>>(attn, cwo_l, part, D_, D_ / 2, D_);
        reduce_add<<<M_, 256>>>(h, bo + l * D_, part, 2);

        ln_kernel<<<M_, 256>>>(h, ln2_w + l * D_, ln2_b + l * D_, ln);

        tgemm_s<1,128,0><<<gFF1, 256, SMEM128>>>(ln, cw1_l, ffn_b1 + l * FF_,
                                                 nullptr, mid, D_, FF_, FF_);

        tgemm_sk<<<gFF2, 256, SMEM64>>>(mid, cw2_l, part, FF_, FF_ / 4, D_);
        reduce_add<<<M_, 256>>>(h, ffn_b2 + l * D_, part, 4);
    }

    ln_kernel<<<M_, 256>>>(h, lnf_w, lnf_b, ln);
    tgemm_s<0,128,1><<<gPRJ, 256, SMEM128>>>(ln, cpj, proj_b, nullptr, logits,
                                             D_, V_, VP_);
}

// round 14
// speedup vs baseline: 2.4975x; 1.0492x over previous
#include <cuda_runtime.h>
#include <math.h>

#define B_  2
#define T_  1024
#define D_  1024
#define H_  16
#define HD_ 64
#define FF_ 4096
#define L_  6
#define V_  50257
#define M_  (B_*T_)        // 2048 rows
#define VP_ 50304          // V padded to 128
#define SML (B_*H_*T_)     // 32768 (m/l scratch stride)

// ---------------- scratch (static device globals; no allocation) -------------
__device__ float g_h   [M_*D_];
__device__ float g_ln  [M_*D_];
__device__ float g_q   [M_*D_];
__device__ float g_kt  [M_*D_];          // K stored TRANSPOSED: [(b*D + hd)*T + t]
__device__ float g_v   [M_*D_];
__device__ float g_attn[M_*D_];
__device__ float g_mid [M_*FF_];
__device__ float g_part[4*M_*D_];        // split-K partials / flash O partials
__device__ float g_ml  [4*SML];          // flash (m,l) partials: [(s*2+p)][b][h][t]
// tf32-preconverted weights (row-major [K][N])
__device__ float g_cwq [L_*D_*D_];
__device__ float g_cwk [L_*D_*D_];
__device__ float g_cwv [L_*D_*D_];
__device__ float g_cwo [L_*D_*D_];
__device__ float g_cw1 [L_*D_*FF_];
__device__ float g_cw2 [L_*FF_*D_];
__device__ float g_cpj [(size_t)D_*VP_];

__device__ __forceinline__ float f2tf(float x) {
    unsigned u;
    asm("cvt.rna.tf32.f32 %0, %1;" : "=r"(u) : "f"(x));
    return __uint_as_float(u);
}

// ---------------- single fused weight conversion -------------------------------
__global__ void conv_all(const float4* __restrict__ wq, const float4* __restrict__ wk,
                         const float4* __restrict__ wv, const float4* __restrict__ wo,
                         const float4* __restrict__ w1, const float4* __restrict__ w2,
                         const float*  __restrict__ pj,
                         float4* __restrict__ cwq, float4* __restrict__ cwk,
                         float4* __restrict__ cwv, float4* __restrict__ cwo,
                         float4* __restrict__ cw1, float4* __restrict__ cw2,
                         float*  __restrict__ cpj) {
    const int seg = blockIdx.y;
    if (seg < 6) {
        const float4* s; float4* d; int n4;
        switch (seg) {
            case 0: s = wq; d = cwq; n4 = L_*D_*D_/4;  break;
            case 1: s = wk; d = cwk; n4 = L_*D_*D_/4;  break;
            case 2: s = wv; d = cwv; n4 = L_*D_*D_/4;  break;
            case 3: s = wo; d = cwo; n4 = L_*D_*D_/4;  break;
            case 4: s = w1; d = cw1; n4 = L_*D_*FF_/4; break;
            default:s = w2; d = cw2; n4 = L_*D_*FF_/4; break;
        }
        for (int i = blockIdx.x * blockDim.x + threadIdx.x; i < n4;
             i += gridDim.x * blockDim.x) {
            float4 v = s[i];
            d[i] = make_float4(f2tf(v.x), f2tf(v.y), f2tf(v.z), f2tf(v.w));
        }
    } else {
        const long long total = (long long)D_ * VP_;
        for (long long i = (long long)blockIdx.x * blockDim.x + threadIdx.x; i < total;
             i += (long long)gridDim.x * blockDim.x) {
            int row = (int)(i / VP_), col = (int)(i - (long long)row * VP_);
            cpj[i] = (col < V_) ? f2tf(pj[(size_t)row * V_ + col]) : 0.f;
        }
    }
}

// ---------------- fused embedding + layer-0 LN1 --------------------------------
__global__ void embed_ln(const int* __restrict__ x,
                         const float* __restrict__ tok,
                         const float* __restrict__ pos,
                         const float* __restrict__ w,
                         const float* __restrict__ b,
                         float* __restrict__ h, float* __restrict__ lnout) {
    const int row  = blockIdx.x;
    const int tid  = threadIdx.x;
    const int lane = tid & 31;
    const int warp = tid >> 5;
    const int t    = row % T_;
    const int id   = x[row];
    const float* te = tok + (size_t)id * D_;
    const float* pe = pos + (size_t)t  * D_;

    float e[4];
    float s = 0.f, sq = 0.f;
    #pragma unroll
    for (int i = 0; i < 4; i++) {
        int d = tid + i * 256;
        e[i] = te[d] + pe[d];
        s += e[i]; sq += e[i] * e[i];
        h[(size_t)row * D_ + d] = e[i];
    }
    #pragma unroll
    for (int off = 16; off > 0; off >>= 1) {
        s  += __shfl_xor_sync(0xffffffffu, s,  off);
        sq += __shfl_xor_sync(0xffffffffu, sq, off);
    }
    __shared__ float ws[8], wq2[8];
    if (lane == 0) { ws[warp] = s; wq2[warp] = sq; }
    __syncthreads();
    if (warp == 0) {
        float a = (lane < 8) ? ws[lane]  : 0.f;
        float c = (lane < 8) ? wq2[lane] : 0.f;
        #pragma unroll
        for (int off = 4; off > 0; off >>= 1) {
            a += __shfl_xor_sync(0xffffffffu, a, off);
            c += __shfl_xor_sync(0xffffffffu, c, off);
        }
        if (lane == 0) { ws[0] = a; wq2[0] = c; }
    }
    __syncthreads();
    float mu  = ws[0] * (1.f / D_);
    float var = wq2[0] * (1.f / D_) - mu * mu;
    float inv = rsqrtf(var + 1e-5f);
    #pragma unroll
    for (int i = 0; i < 4; i++) {
        int d = tid + i * 256;
        lnout[(size_t)row * D_ + d] = f2tf((e[i] - mu) * inv * w[d] + b[d]);
    }
}

// ---------------- layernorm (used only standalone if ever needed) -------------
__global__ void ln_kernel(const float* __restrict__ in,
                          const float* __restrict__ w,
                          const float* __restrict__ b,
                          float* __restrict__ out) {
    const int row  = blockIdx.x;
    const int tid  = threadIdx.x;
    const int lane = tid & 31;
    const int warp = tid >> 5;
    const float* xr = in + (size_t)row * D_;

    float s = 0.f, sq = 0.f;
    for (int d = tid; d < D_; d += 256) {
        float v = xr[d];
        s += v; sq += v * v;
    }
    #pragma unroll
    for (int off = 16; off > 0; off >>= 1) {
        s  += __shfl_xor_sync(0xffffffffu, s,  off);
        sq += __shfl_xor_sync(0xffffffffu, sq, off);
    }
    __shared__ float ws[8], wq2[8];
    if (lane == 0) { ws[warp] = s; wq2[warp] = sq; }
    __syncthreads();
    if (warp == 0) {
        float a = (lane < 8) ? ws[lane]  : 0.f;
        float c = (lane < 8) ? wq2[lane] : 0.f;
        #pragma unroll
        for (int off = 4; off > 0; off >>= 1) {
            a += __shfl_xor_sync(0xffffffffu, a, off);
            c += __shfl_xor_sync(0xffffffffu, c, off);
        }
        if (lane == 0) { ws[0] = a; wq2[0] = c; }
    }
    __syncthreads();
    float mu  = ws[0] * (1.f / D_);
    float var = wq2[0] * (1.f / D_) - mu * mu;
    float inv = rsqrtf(var + 1e-5f);
    float* o = out + (size_t)row * D_;
    for (int d = tid; d < D_; d += 256)
        o[d] = f2tf((xr[d] - mu) * inv * w[d] + b[d]);
}

// ---------------- fused split-K reduce + LayerNorm ----------------------------
// h += bias + sum(parts); lnout = f2tf(LN(h) * w + b2)
__global__ void reduce_ln(float* __restrict__ h, const float* __restrict__ bias,
                          const float* __restrict__ part, int nsplit,
                          const float* __restrict__ w, const float* __restrict__ b2,
                          float* __restrict__ lnout) {
    const int row  = blockIdx.x;
    const int tid  = threadIdx.x;
    const int lane = tid & 31;
    const int warp = tid >> 5;
    const int c4   = tid * 4;

    float4 acc = *(float4*)&h[(size_t)row * D_ + c4];
    float4 bv  = *(const float4*)&bias[c4];
    acc.x += bv.x; acc.y += bv.y; acc.z += bv.z; acc.w += bv.w;
    for (int s = 0; s < nsplit; s++) {
        float4 p = *(const float4*)&part[(size_t)s * M_ * D_ + (size_t)row * D_ + c4];
        acc.x += p.x; acc.y += p.y; acc.z += p.z; acc.w += p.w;
    }
    *(float4*)&h[(size_t)row * D_ + c4] = acc;

    float s = acc.x + acc.y + acc.z + acc.w;
    float sq = acc.x*acc.x + acc.y*acc.y + acc.z*acc.z + acc.w*acc.w;
    #pragma unroll
    for (int off = 16; off > 0; off >>= 1) {
        s  += __shfl_xor_sync(0xffffffffu, s,  off);
        sq += __shfl_xor_sync(0xffffffffu, sq, off);
    }
    __shared__ float ws[8], wq2[8];
    if (lane == 0) { ws[warp] = s; wq2[warp] = sq; }
    __syncthreads();
    if (warp == 0) {
        float a = (lane < 8) ? ws[lane]  : 0.f;
        float c = (lane < 8) ? wq2[lane] : 0.f;
        #pragma unroll
        for (int off = 4; off > 0; off >>= 1) {
            a += __shfl_xor_sync(0xffffffffu, a, off);
            c += __shfl_xor_sync(0xffffffffu, c, off);
        }
        if (lane == 0) { ws[0] = a; wq2[0] = c; }
    }
    __syncthreads();
    float mu  = ws[0] * (1.f / D_);
    float var = wq2[0] * (1.f / D_) - mu * mu;
    float inv = rsqrtf(var + 1e-5f);
    float4 wv4 = *(const float4*)&w[c4];
    float4 b24 = *(const float4*)&b2[c4];
    float4 o;
    o.x = f2tf((acc.x - mu) * inv * wv4.x + b24.x);
    o.y = f2tf((acc.y - mu) * inv * wv4.y + b24.y);
    o.z = f2tf((acc.z - mu) * inv * wv4.z + b24.z);
    o.w = f2tf((acc.w - mu) * inv * wv4.w + b24.w);
    *(float4*)&lnout[(size_t)row * D_ + c4] = o;
}

// ---------------- common GEMM helpers ------------------------------------------
#define CPA16(dst_u32, src_ptr) \
    asm volatile("cp.async.cg.shared.global [%0], [%1], 16;" :: "r"(dst_u32), "l"(src_ptr))

__device__ __forceinline__ unsigned smem_u32(const void* p) {
    return (unsigned)__cvta_generic_to_shared(p);
}

__device__ __forceinline__ void mma8(float c[4], const unsigned a[4], const unsigned b[2]) {
    asm volatile(
        "mma.sync.aligned.m16n8k8.row.col.f32.tf32.tf32.f32 "
        "{%0,%1,%2,%3}, {%4,%5,%6,%7}, {%8,%9}, {%0,%1,%2,%3};\n"
        : "+f"(c[0]), "+f"(c[1]), "+f"(c[2]), "+f"(c[3])
        : "r"(a[0]), "r"(a[1]), "r"(a[2]), "r"(a[3]), "r"(b[0]), "r"(b[1]));
}

// ---------------- standard GEMM body: 128 x BN_, 3-stage cp.async -------------
// MODE 0:+bias 1:f2tf(relu(+bias)) 2:+bias+residual 3:raw 5:f2tf(+bias)
// MODE 6: f2tf(+bias), store TRANSPOSED to kt[(b*D+col)*T + t]
template <int BN_>
__device__ __forceinline__ void issue_stage(
    float* As, float* Bs, const float* A, const float* W,
    int lda, int Npad, int bm0, int bn0, int k0, int tid)
{
    constexpr int SB = BN_ + 8;
    #pragma unroll
    for (int j = 0; j < 4; j++) {
        int f = tid + j * 256;
        int row = f >> 3, c4 = (f & 7) << 2;
        CPA16(smem_u32(As + row * 36 + c4), A + (size_t)(bm0 + row) * lda + k0 + c4);
    }
    #pragma unroll
    for (int j = 0; j < BN_ / 32; j++) {
        int f = tid + j * 256;
        int row = (BN_ == 128) ? (f >> 5) : (f >> 4);
        int c4  = (BN_ == 128) ? ((f & 31) << 2) : ((f & 15) << 2);
        CPA16(smem_u32(Bs + row * SB + c4), W + (size_t)(k0 + row) * Npad + bn0 + c4);
    }
    asm volatile("cp.async.commit_group;");
}

template <int MODE, int BN_, int GUARD>
__device__ __forceinline__ void tgemm_body(
    const float* __restrict__ A, const float* __restrict__ W,
    const float* __restrict__ bias, const float* __restrict__ R,
    float* __restrict__ C, int lda, int KL, int N, int Npad, int bm0, int bn0)
{
    constexpr int SB  = BN_ + 8;
    constexpr int ASZ = 128 * 36;
    constexpr int BSZ = 32 * SB;
    constexpr int NI  = BN_ / 32;

    extern __shared__ float sm[];
    float* As = sm;
    float* Bs = sm + 3 * ASZ;

    const int tid  = threadIdx.x;
    const int lane = tid & 31;
    const int warp = tid >> 5;
    const int g    = lane >> 2;
    const int tg   = lane & 3;
    const int wm0  = (warp >> 2) * 64;
    const int wn0  = (warp & 3) * (BN_ / 4);

    float acc[4][NI][4];
    #pragma unroll
    for (int mi = 0; mi < 4; mi++)
        #pragma unroll
        for (int ni = 0; ni < NI; ni++)
            #pragma unroll
            for (int r = 0; r < 4; r++) acc[mi][ni][r] = 0.f;

    const int nIter = KL / 32;
    issue_stage<BN_>(As, Bs, A, W, lda, Npad, bm0, bn0, 0, tid);
    issue_stage<BN_>(As + ASZ, Bs + BSZ, A, W, lda, Npad, bm0, bn0, 32, tid);

    int st = 0, stw = 2;
    for (int t = 0; t < nIter; t++) {
        if (t + 1 < nIter) asm volatile("cp.async.wait_group 1;");
        else               asm volatile("cp.async.wait_group 0;");
        __syncthreads();

        const float* Ast = As + st * ASZ;
        const float* Bst = Bs + st * BSZ;
        #pragma unroll
        for (int kk = 0; kk < 32; kk += 8) {
            unsigned a[4][4], b[NI][2];
            #pragma unroll
            for (int mi = 0; mi < 4; mi++) {
                int r0 = wm0 + mi * 16 + g;
                a[mi][0] = __float_as_uint(Ast[(r0    ) * 36 + kk + tg]);
                a[mi][1] = __float_as_uint(Ast[(r0 + 8) * 36 + kk + tg]);
                a[mi][2] = __float_as_uint(Ast[(r0    ) * 36 + kk + tg + 4]);
                a[mi][3] = __float_as_uint(Ast[(r0 + 8) * 36 + kk + tg + 4]);
            }
            #pragma unroll
            for (int ni = 0; ni < NI; ni++) {
                int c = wn0 + ni * 8 + g;
                b[ni][0] = __float_as_uint(Bst[(kk + tg    ) * SB + c]);
                b[ni][1] = __float_as_uint(Bst[(kk + tg + 4) * SB + c]);
            }
            #pragma unroll
            for (int mi = 0; mi < 4; mi++)
                #pragma unroll
                for (int ni = 0; ni < NI; ni++)
                    mma8(acc[mi][ni], a[mi], b[ni]);
        }

        if (t + 2 < nIter) {
            issue_stage<BN_>(As + stw * ASZ, Bs + stw * BSZ, A, W, lda, Npad, bm0, bn0,
                             (t + 2) * 32, tid);
            stw = (stw == 2) ? 0 : stw + 1;
        }
        st = (st == 2) ? 0 : st + 1;
    }

    #pragma unroll
    for (int mi = 0; mi < 4; mi++) {
        #pragma unroll
        for (int ni = 0; ni < NI; ni++) {
            int row0 = bm0 + wm0 + mi * 16 + g;
            int col0 = bn0 + wn0 + ni * 8 + 2 * tg;
            #pragma unroll
            for (int rr = 0; rr < 2; rr++) {
                int row = row0 + rr * 8;
                #pragma unroll
                for (int cc = 0; cc < 2; cc++) {
                    int col = col0 + cc;
                    if (!GUARD || col < N) {
                        float v = acc[mi][ni][rr * 2 + cc];
                        if (MODE != 3) v += bias[col];
                        if (MODE == 1) v = f2tf(fmaxf(v, 0.f));
                        if (MODE == 2) v += R[(size_t)row * N + col];
                        if (MODE == 5) v = f2tf(v);
                        if (MODE == 6) {
                            C[((size_t)(row >> 10) * D_ + col) * T_ + (row & (T_ - 1))]
                                = f2tf(v);
                        } else {
                            C[(size_t)row * N + col] = v;
                        }
                    }
                }
            }
        }
    }
}

// bm-fastest grid (B-tile reuse; for N >> M GEMMs)
template <int MODE, int BN_, int GUARD>
__global__ __launch_bounds__(256, 2)
void tgemm_s(const float* __restrict__ A, const float* __restrict__ W,
             const float* __restrict__ bias, const float* __restrict__ R,
             float* __restrict__ C, int K, int N, int Npad) {
    tgemm_body<MODE, BN_, GUARD>(A, W, bias, R, C, K, K, N, Npad,
                                 blockIdx.x * 128, blockIdx.y * BN_);
}

__global__ __launch_bounds__(256, 2)
void tgemm_qkv(const float* __restrict__ A,
               const float* __restrict__ wq, const float* __restrict__ wk,
               const float* __restrict__ wv,
               const float* __restrict__ bq, const float* __restrict__ bk,
               const float* __restrict__ bv,
               float* __restrict__ q, float* __restrict__ kt, float* __restrict__ v) {
    int z = blockIdx.z;
    if (z == 0) {
        tgemm_body<5, 128, 0>(A, wq, bq, nullptr, q, D_, D_, D_, D_,
                              blockIdx.y * 128, blockIdx.x * 128);
    } else if (z == 1) {
        tgemm_body<6, 128, 0>(A, wk, bk, nullptr, kt, D_, D_, D_, D_,
                              blockIdx.y * 128, blockIdx.x * 128);
    } else {
        tgemm_body<5, 128, 0>(A, wv, bv, nullptr, v, D_, D_, D_, D_,
                              blockIdx.y * 128, blockIdx.x * 128);
    }
}

// split-K GEMM: blockIdx.z = split; raw partials to part[z][M][N]
__global__ __launch_bounds__(256, 2)
void tgemm_sk(const float* __restrict__ A, const float* __restrict__ W,
              float* __restrict__ part, int K, int KL, int N) {
    const int s = blockIdx.z;
    tgemm_body<3, 64, 0>(A + (size_t)s * KL,
                         W + (size_t)s * KL * N,
                         nullptr, nullptr,
                         part + (size_t)s * M_ * N,
                         K, KL, N, N,
                         blockIdx.y * 128, blockIdx.x * 64);
}

// ---------------- flash attention v5: tensor-core + split-KV -------------------
// grid (T/QT, H, B*2): z = b*2 + s. Split s handles half the causal KV range,
// writes partial O (unnormalized) + (m,l) to scratch; attn_combine merges.
#define QT 128
#define KT 32
#define FQ  0
#define FKT (QT*68)
#define FVV (FKT + 2*64*36)
#define FPP (FVV + 2*KT*68)
#define SMEM_ATT ((FPP + QT*36) * 4)    // 89088 B

__global__ __launch_bounds__(256)
void flash_attn(const float* __restrict__ q,
                const float* __restrict__ kt,
                const float* __restrict__ v,
                float* __restrict__ part, float* __restrict__ ml) {
    extern __shared__ float sm[];
    float* Qs = sm + FQ;
    float* Kt = sm + FKT;
    float* Vs = sm + FVV;
    float* Ps = sm + FPP;

    const int q0   = (gridDim.x - 1 - blockIdx.x) * QT;  // longest first
    const int h    = blockIdx.y;
    const int b    = blockIdx.z >> 1;
    const int s    = blockIdx.z & 1;
    const int tid  = threadIdx.x;
    const int lane = tid & 31;
    const int warp = tid >> 5;
    const int g    = lane >> 2;
    const int tg   = lane & 3;
    const int wm   = warp * 16;

    const size_t base   = ((size_t)b * T_) * D_ + (size_t)h * HD_;
    const size_t base_k = ((size_t)b * D_ + (size_t)h * HD_) * T_;

    const int half = (q0 + QT) / 2;        // multiple of 64
    const int kvs  = s * half;             // this split's kv start
    const int nTiles = half / KT;

    #pragma unroll
    for (int i = tid; i < QT * 16; i += 256) {
        int r = i >> 4, c4 = (i & 15) << 2;
        *(float4*)&Qs[r * 68 + c4] = *(const float4*)&q[base + (size_t)(q0 + r) * D_ + c4];
    }

    float oa[8][4];
    #pragma unroll
    for (int ni = 0; ni < 8; ni++)
        #pragma unroll
        for (int r = 0; r < 4; r++) oa[ni][r] = 0.f;
    float m0 = -1e30f, m1 = -1e30f, l0 = 0.f, l1 = 0.f;

    // prologue: first tile of this split -> stage 0
    #pragma unroll
    for (int j = 0; j < 2; j++) {
        int f = tid + j * 256;
        int rd = f >> 3, chd = (f & 7) << 2;
        CPA16(smem_u32(Kt + rd * 36 + chd), kt + base_k + (size_t)rd * T_ + kvs + chd);
        int rv = f >> 4, chv = (f & 15) << 2;
        CPA16(smem_u32(Vs + rv * 68 + chv), v + base + (size_t)(kvs + rv) * D_ + chv);
    }
    asm volatile("cp.async.commit_group;");

    for (int t0 = 0; t0 < nTiles; t0++) {
        const int s0  = kvs + t0 * KT;
        const int buf = t0 & 1;
        asm volatile("cp.async.wait_group 0;");
        __syncthreads();

        if (t0 + 1 < nTiles) {
            const int nb  = buf ^ 1;
            const int ns0 = s0 + KT;
            #pragma unroll
            for (int j = 0; j < 2; j++) {
                int f = tid + j * 256;
                int rd = f >> 3, chd = (f & 7) << 2;
                CPA16(smem_u32(Kt + nb * 64 * 36 + rd * 36 + chd),
                      kt + base_k + (size_t)rd * T_ + ns0 + chd);
                int rv = f >> 4, chv = (f & 15) << 2;
                CPA16(smem_u32(Vs + nb * KT * 68 + rv * 68 + chv),
                      v + base + (size_t)(ns0 + rv) * D_ + chv);
            }
            asm volatile("cp.async.commit_group;");
        }

        const float* Ktb = Kt + buf * 64 * 36;
        const float* Vb  = Vs + buf * KT * 68;

        float sf[4][4];
        #pragma unroll
        for (int ni = 0; ni < 4; ni++)
            #pragma unroll
            for (int r = 0; r < 4; r++) sf[ni][r] = 0.f;
        #pragma unroll
        for (int kk = 0; kk < 64; kk += 8) {
            unsigned a[4], bfr[4][2];
            a[0] = __float_as_uint(Qs[(wm + g    ) * 68 + kk + tg]);
            a[1] = __float_as_uint(Qs[(wm + g + 8) * 68 + kk + tg]);
            a[2] = __float_as_uint(Qs[(wm + g    ) * 68 + kk + tg + 4]);
            a[3] = __float_as_uint(Qs[(wm + g + 8) * 68 + kk + tg + 4]);
            #pragma unroll
            for (int ni = 0; ni < 4; ni++) {
                int c = ni * 8 + g;
                bfr[ni][0] = __float_as_uint(Ktb[(kk + tg    ) * 36 + c]);
                bfr[ni][1] = __float_as_uint(Ktb[(kk + tg + 4) * 36 + c]);
            }
            #pragma unroll
            for (int ni = 0; ni < 4; ni++)
                mma8(sf[ni], a, bfr[ni]);
        }

        const int r0 = q0 + wm + g;
        const int r1 = r0 + 8;
        #pragma unroll
        for (int ni = 0; ni < 4; ni++) {
            int col = s0 + ni * 8 + 2 * tg;
            sf[ni][0] = (col     <= r0) ? sf[ni][0] * 0.125f : -1e30f;
            sf[ni][1] = (col + 1 <= r0) ? sf[ni][1] * 0.125f : -1e30f;
            sf[ni][2] = (col     <= r1) ? sf[ni][2] * 0.125f : -1e30f;
            sf[ni][3] = (col + 1 <= r1) ? sf[ni][3] * 0.125f : -1e30f;
        }
        float tm0 = -1e30f, tm1 = -1e30f;
        #pragma unroll
        for (int ni = 0; ni < 4; ni++) {
            tm0 = fmaxf(tm0, fmaxf(sf[ni][0], sf[ni][1]));
            tm1 = fmaxf(tm1, fmaxf(sf[ni][2], sf[ni][3]));
        }
        tm0 = fmaxf(tm0, __shfl_xor_sync(0xffffffffu, tm0, 1));
        tm0 = fmaxf(tm0, __shfl_xor_sync(0xffffffffu, tm0, 2));
        tm1 = fmaxf(tm1, __shfl_xor_sync(0xffffffffu, tm1, 1));
        tm1 = fmaxf(tm1, __shfl_xor_sync(0xffffffffu, tm1, 2));
        float m0n = fmaxf(m0, tm0), m1n = fmaxf(m1, tm1);
        float sc0 = __expf(m0 - m0n), sc1 = __expf(m1 - m1n);
        float ps0 = 0.f, ps1 = 0.f;
        #pragma unroll
        for (int ni = 0; ni < 4; ni++) {
            sf[ni][0] = __expf(sf[ni][0] - m0n); ps0 += sf[ni][0];
            sf[ni][1] = __expf(sf[ni][1] - m0n); ps0 += sf[ni][1];
            sf[ni][2] = __expf(sf[ni][2] - m1n); ps1 += sf[ni][2];
            sf[ni][3] = __expf(sf[ni][3] - m1n); ps1 += sf[ni][3];
        }
        ps0 += __shfl_xor_sync(0xffffffffu, ps0, 1);
        ps0 += __shfl_xor_sync(0xffffffffu, ps0, 2);
        ps1 += __shfl_xor_sync(0xffffffffu, ps1, 1);
        ps1 += __shfl_xor_sync(0xffffffffu, ps1, 2);
        l0 = l0 * sc0 + ps0;  l1 = l1 * sc1 + ps1;
        m0 = m0n;  m1 = m1n;
        #pragma unroll
        for (int ni = 0; ni < 8; ni++) {
            oa[ni][0] *= sc0; oa[ni][1] *= sc0;
            oa[ni][2] *= sc1; oa[ni][3] *= sc1;
        }

        #pragma unroll
        for (int ni = 0; ni < 4; ni++) {
            int cb = ni * 8 + 2 * tg;
            Ps[(wm + g    ) * 36 + cb    ] = f2tf(sf[ni][0]);
            Ps[(wm + g    ) * 36 + cb + 1] = f2tf(sf[ni][1]);
            Ps[(wm + g + 8) * 36 + cb    ] = f2tf(sf[ni][2]);
            Ps[(wm + g + 8) * 36 + cb + 1] = f2tf(sf[ni][3]);
        }
        __syncwarp();

        #pragma unroll
        for (int kk = 0; kk < KT; kk += 8) {
            unsigned a2[4], b2[2];
            a2[0] = __float_as_uint(Ps[(wm + g    ) * 36 + kk + tg]);
            a2[1] = __float_as_uint(Ps[(wm + g + 8) * 36 + kk + tg]);
            a2[2] = __float_as_uint(Ps[(wm + g    ) * 36 + kk + tg + 4]);
            a2[3] = __float_as_uint(Ps[(wm + g + 8) * 36 + kk + tg + 4]);
            #pragma unroll
            for (int ni = 0; ni < 8; ni++) {
                int c = ni * 8 + g;
                b2[0] = __float_as_uint(Vb[(kk + tg    ) * 68 + c]);
                b2[1] = __float_as_uint(Vb[(kk + tg + 4) * 68 + c]);
                mma8(oa[ni], a2, b2);
            }
        }
    }

    // ---- epilogue: write raw partial O + (m,l) ----
    float* po = part + (size_t)s * M_ * D_;
    const int r0 = q0 + wm + g;
    const int r1 = r0 + 8;
    if (tg == 0) {
        size_t mlrow0 = ((size_t)b * H_ + h) * T_ + r0;
        size_t mlrow1 = ((size_t)b * H_ + h) * T_ + r1;
        ml[(s * 2 + 0) * SML + mlrow0] = m0;
        ml[(s * 2 + 1) * SML + mlrow0] = l0;
        ml[(s * 2 + 0) * SML + mlrow1] = m1;
        ml[(s * 2 + 1) * SML + mlrow1] = l1;
    }
    #pragma unroll
    for (int ni = 0; ni < 8; ni++) {
        int col = ni * 8 + 2 * tg;
        *(float2*)&po[base + (size_t)r0 * D_ + col] = make_float2(oa[ni][0], oa[ni][1]);
        *(float2*)&po[base + (size_t)r1 * D_ + col] = make_float2(oa[ni][2], oa[ni][3]);
    }
}

// combine the two KV-splits: O = (O0*e^{m0-m} + O1*e^{m1-m}) / l
__global__ void attn_combine(const float* __restrict__ part,
                             const float* __restrict__ ml,
                             float* __restrict__ attn) {
    const int row = blockIdx.x;           // b*T + t
    const int b   = row >> 10;
    const int t   = row & (T_ - 1);
    const int c4  = threadIdx.x * 4;
    const int h   = c4 >> 6;

    size_t mlrow = ((size_t)b * H_ + h) * T_ + t;
    float m0 = ml[0 * SML + mlrow], l0 = ml[1 * SML + mlrow];
    float m1 = ml[2 * SML + mlrow], l1 = ml[3 * SML + mlrow];
    float m  = fmaxf(m0, m1);
    float w0 = __expf(m0 - m), w1 = __expf(m1 - m);
    float li = 1.f / (l0 * w0 + l1 * w1);

    float4 o0 = *(const float4*)&part[(size_t)row * D_ + c4];
    float4 o1 = *(const float4*)&part[(size_t)M_ * D_ + (size_t)row * D_ + c4];
    float4 o;
    o.x = f2tf((o0.x * w0 + o1.x * w1) * li);
    o.y = f2tf((o0.y * w0 + o1.y * w1) * li);
    o.z = f2tf((o0.z * w0 + o1.z * w1) * li);
    o.w = f2tf((o0.w * w0 + o1.w * w1) * li);
    *(float4*)&attn[(size_t)row * D_ + c4] = o;
}

// ---------------- launch -----------------------------------------------------
extern "C" void kernel_launch(void* const* d_in, const int* in_sizes, int n_in,
                              void* d_out, int out_size) {
    const int*   x       = (const int*)  d_in[0];
    const float* tok_emb = (const float*)d_in[1];
    const float* pos_emb = (const float*)d_in[2];
    const float* wq      = (const float*)d_in[3];
    const float* bq      = (const float*)d_in[4];
    const float* wk      = (const float*)d_in[5];
    const float* bk      = (const float*)d_in[6];
    const float* wv      = (const float*)d_in[7];
    const float* bv      = (const float*)d_in[8];
    const float* wo      = (const float*)d_in[9];
    const float* bo      = (const float*)d_in[10];
    const float* ln1_w   = (const float*)d_in[11];
    const float* ln1_b   = (const float*)d_in[12];
    const float* ln2_w   = (const float*)d_in[13];
    const float* ln2_b   = (const float*)d_in[14];
    const float* ffn_w1  = (const float*)d_in[15];
    const float* ffn_b1  = (const float*)d_in[16];
    const float* ffn_w2  = (const float*)d_in[17];
    const float* ffn_b2  = (const float*)d_in[18];
    const float* lnf_w   = (const float*)d_in[19];
    const float* lnf_b   = (const float*)d_in[20];
    const float* proj_w  = (const float*)d_in[21];
    const float* proj_b  = (const float*)d_in[22];
    float* logits = (float*)d_out;

    float *h, *ln, *q, *kt, *v, *attn, *mid, *part, *ml;
    float *cwq, *cwk, *cwv, *cwo, *cw1, *cw2, *cpj;
    cudaGetSymbolAddress((void**)&h,    g_h);
    cudaGetSymbolAddress((void**)&ln,   g_ln);
    cudaGetSymbolAddress((void**)&q,    g_q);
    cudaGetSymbolAddress((void**)&kt,   g_kt);
    cudaGetSymbolAddress((void**)&v,    g_v);
    cudaGetSymbolAddress((void**)&attn, g_attn);
    cudaGetSymbolAddress((void**)&mid,  g_mid);
    cudaGetSymbolAddress((void**)&part, g_part);
    cudaGetSymbolAddress((void**)&ml,   g_ml);
    cudaGetSymbolAddress((void**)&cwq,  g_cwq);
    cudaGetSymbolAddress((void**)&cwk,  g_cwk);
    cudaGetSymbolAddress((void**)&cwv,  g_cwv);
    cudaGetSymbolAddress((void**)&cwo,  g_cwo);
    cudaGetSymbolAddress((void**)&cw1,  g_cw1);
    cudaGetSymbolAddress((void**)&cw2,  g_cw2);
    cudaGetSymbolAddress((void**)&cpj,  g_cpj);

    const int SMEM128 = 3 * (128 * 36 + 32 * 136) * 4;   // 107520 B
    const int SMEM64  = 3 * (128 * 36 + 32 * 72)  * 4;   // 82944 B
    cudaFuncSetAttribute(tgemm_sk,        cudaFuncAttributeMaxDynamicSharedMemorySize, SMEM64);
    cudaFuncSetAttribute(tgemm_s<1,128,0>,cudaFuncAttributeMaxDynamicSharedMemorySize, SMEM128);
    cudaFuncSetAttribute(tgemm_s<0,128,1>,cudaFuncAttributeMaxDynamicSharedMemorySize, SMEM128);
    cudaFuncSetAttribute(tgemm_qkv,       cudaFuncAttributeMaxDynamicSharedMemorySize, SMEM128);
    cudaFuncSetAttribute(flash_attn,      cudaFuncAttributeMaxDynamicSharedMemorySize, SMEM_ATT);

    dim3 gQKV(D_ / 128, M_ / 128, 3);        // (8,16,3)
    dim3 gWO(D_ / 64, M_ / 128, 2);          // (16,16,2) split-K=2
    dim3 gFF1(M_ / 128, FF_ / 128);          // (16,32)  bm-fastest
    dim3 gFF2(D_ / 64, M_ / 128, 4);         // (16,16,4) split-K=4
    dim3 gPRJ(M_ / 128, VP_ / 128);          // (16,393) bm-fastest
    dim3 gAT(T_ / QT, H_, B_ * 2);           // (8,16,4) split-KV=2

    // Launch order: our #4 is flash_attn (ncu -s 5 lands on our 4th launch).
    conv_all<<<dim3(1024, 7), 256>>>(                                         // 1
        (const float4*)wq, (const float4*)wk, (const float4*)wv,
        (const float4*)wo, (const float4*)ffn_w1, (const float4*)ffn_w2,
        proj_w,
        (float4*)cwq, (float4*)cwk, (float4*)cwv,
        (float4*)cwo, (float4*)cw1, (float4*)cw2, cpj);
    embed_ln<<<M_, 256>>>(x, tok_emb, pos_emb, ln1_w, ln1_b, h, ln);          // 2

    for (int l = 0; l < L_; l++) {
        float* cwq_l = cwq + (size_t)l * D_ * D_;
        float* cwk_l = cwk + (size_t)l * D_ * D_;
        float* cwv_l = cwv + (size_t)l * D_ * D_;
        float* cwo_l = cwo + (size_t)l * D_ * D_;
        float* cw1_l = cw1 + (size_t)l * D_ * FF_;
        float* cw2_l = cw2 + (size_t)l * FF_ * D_;

        tgemm_qkv<<<gQKV, 256, SMEM128>>>(ln, cwq_l, cwk_l, cwv_l,
                                          bq + l * D_, bk + l * D_, bv + l * D_,
                                          q, kt, v);                          // 3 (l=0)

        flash_attn<<<gAT, 256, SMEM_ATT>>>(q, kt, v, part, ml);               // 4 (l=0)
        attn_combine<<<M_, 256>>>(part, ml, attn);

        tgemm_sk<<<gWO, 256, SMEM64>>>(attn, cwo_l, part, D_, D_ / 2, D_);
        reduce_ln<<<M_, 256>>>(h, bo + l * D_, part, 2,
                               ln2_w + l * D_, ln2_b + l * D_, ln);

        tgemm_s<1,128,0><<<gFF1, 256, SMEM128>>>(ln, cw1_l, ffn_b1 + l * FF_,
                                                 nullptr, mid, D_, FF_, FF_);

        tgemm_sk<<<gFF2, 256, SMEM64>>>(mid, cw2_l, part, FF_, FF_ / 4, D_);
        if (l + 1 < L_)
            reduce_ln<<<M_, 256>>>(h, ffn_b2 + l * D_, part, 4,
                                   ln1_w + (l + 1) * D_, ln1_b + (l + 1) * D_, ln);
        else
            reduce_ln<<<M_, 256>>>(h, ffn_b2 + l * D_, part, 4, lnf_w, lnf_b, ln);
    }

    tgemm_s<0,128,1><<<gPRJ, 256, SMEM128>>>(ln, cpj, proj_b, nullptr, logits,
                                             D_, V_, VP_);
}

// round 15
// speedup vs baseline: 2.4994x; 1.0007x over previous
#include <cuda_runtime.h>
#include <math.h>

#define B_  2
#define T_  1024
#define D_  1024
#define H_  16
#define HD_ 64
#define FF_ 4096
#define L_  6
#define V_  50257
#define M_  (B_*T_)        // 2048 rows
#define VP_ 50304          // V padded to 128
#define SML (B_*H_*T_)     // 32768 (m/l scratch stride)

// ---------------- scratch (static device globals; no allocation) -------------
__device__ float g_h   [M_*D_];
__device__ float g_ln  [M_*D_];
__device__ float g_q   [M_*D_];
__device__ float g_kt  [M_*D_];          // K stored TRANSPOSED: [(b*D + hd)*T + t]
__device__ float g_v   [M_*D_];
__device__ float g_attn[M_*D_];
__device__ float g_mid [M_*FF_];
__device__ float g_part[4*M_*D_];        // split-K partials / flash O partials
__device__ float g_ml  [4*SML];          // flash (m,l) partials: [(s*2+p)][b][h][t]
// tf32-preconverted weights (row-major [K][N])
__device__ float g_cwq [L_*D_*D_];
__device__ float g_cwk [L_*D_*D_];
__device__ float g_cwv [L_*D_*D_];
__device__ float g_cwo [L_*D_*D_];
__device__ float g_cw1 [L_*D_*FF_];
__device__ float g_cw2 [L_*FF_*D_];
__device__ float g_cpj [(size_t)D_*VP_];

__device__ __forceinline__ float f2tf(float x) {
    unsigned u;
    asm("cvt.rna.tf32.f32 %0, %1;" : "=r"(u) : "f"(x));
    return __uint_as_float(u);
}

// ---------------- single fused weight conversion -------------------------------
__global__ void conv_all(const float4* __restrict__ wq, const float4* __restrict__ wk,
                         const float4* __restrict__ wv, const float4* __restrict__ wo,
                         const float4* __restrict__ w1, const float4* __restrict__ w2,
                         const float*  __restrict__ pj,
                         float4* __restrict__ cwq, float4* __restrict__ cwk,
                         float4* __restrict__ cwv, float4* __restrict__ cwo,
                         float4* __restrict__ cw1, float4* __restrict__ cw2,
                         float*  __restrict__ cpj) {
    const int seg = blockIdx.y;
    if (seg < 6) {
        const float4* s; float4* d; int n4;
        switch (seg) {
            case 0: s = wq; d = cwq; n4 = L_*D_*D_/4;  break;
            case 1: s = wk; d = cwk; n4 = L_*D_*D_/4;  break;
            case 2: s = wv; d = cwv; n4 = L_*D_*D_/4;  break;
            case 3: s = wo; d = cwo; n4 = L_*D_*D_/4;  break;
            case 4: s = w1; d = cw1; n4 = L_*D_*FF_/4; break;
            default:s = w2; d = cw2; n4 = L_*D_*FF_/4; break;
        }
        for (int i = blockIdx.x * blockDim.x + threadIdx.x; i < n4;
             i += gridDim.x * blockDim.x) {
            float4 v = s[i];
            d[i] = make_float4(f2tf(v.x), f2tf(v.y), f2tf(v.z), f2tf(v.w));
        }
    } else {
        const long long total = (long long)D_ * VP_;
        for (long long i = (long long)blockIdx.x * blockDim.x + threadIdx.x; i < total;
             i += (long long)gridDim.x * blockDim.x) {
            int row = (int)(i / VP_), col = (int)(i - (long long)row * VP_);
            cpj[i] = (col < V_) ? f2tf(pj[(size_t)row * V_ + col]) : 0.f;
        }
    }
}

// ---------------- fused embedding + layer-0 LN1 --------------------------------
__global__ void embed_ln(const int* __restrict__ x,
                         const float* __restrict__ tok,
                         const float* __restrict__ pos,
                         const float* __restrict__ w,
                         const float* __restrict__ b,
                         float* __restrict__ h, float* __restrict__ lnout) {
    const int row  = blockIdx.x;
    const int tid  = threadIdx.x;
    const int lane = tid & 31;
    const int warp = tid >> 5;
    const int t    = row % T_;
    const int id   = x[row];
    const float* te = tok + (size_t)id * D_;
    const float* pe = pos + (size_t)t  * D_;

    float e[4];
    float s = 0.f, sq = 0.f;
    #pragma unroll
    for (int i = 0; i < 4; i++) {
        int d = tid + i * 256;
        e[i] = te[d] + pe[d];
        s += e[i]; sq += e[i] * e[i];
        h[(size_t)row * D_ + d] = e[i];
    }
    #pragma unroll
    for (int off = 16; off > 0; off >>= 1) {
        s  += __shfl_xor_sync(0xffffffffu, s,  off);
        sq += __shfl_xor_sync(0xffffffffu, sq, off);
    }
    __shared__ float ws[8], wq2[8];
    if (lane == 0) { ws[warp] = s; wq2[warp] = sq; }
    __syncthreads();
    if (warp == 0) {
        float a = (lane < 8) ? ws[lane]  : 0.f;
        float c = (lane < 8) ? wq2[lane] : 0.f;
        #pragma unroll
        for (int off = 4; off > 0; off >>= 1) {
            a += __shfl_xor_sync(0xffffffffu, a, off);
            c += __shfl_xor_sync(0xffffffffu, c, off);
        }
        if (lane == 0) { ws[0] = a; wq2[0] = c; }
    }
    __syncthreads();
    float mu  = ws[0] * (1.f / D_);
    float var = wq2[0] * (1.f / D_) - mu * mu;
    float inv = rsqrtf(var + 1e-5f);
    #pragma unroll
    for (int i = 0; i < 4; i++) {
        int d = tid + i * 256;
        lnout[(size_t)row * D_ + d] = f2tf((e[i] - mu) * inv * w[d] + b[d]);
    }
}

// ---------------- layernorm (used only standalone if ever needed) -------------
__global__ void ln_kernel(const float* __restrict__ in,
                          const float* __restrict__ w,
                          const float* __restrict__ b,
                          float* __restrict__ out) {
    const int row  = blockIdx.x;
    const int tid  = threadIdx.x;
    const int lane = tid & 31;
    const int warp = tid >> 5;
    const float* xr = in + (size_t)row * D_;

    float s = 0.f, sq = 0.f;
    for (int d = tid; d < D_; d += 256) {
        float v = xr[d];
        s += v; sq += v * v;
    }
    #pragma unroll
    for (int off = 16; off > 0; off >>= 1) {
        s  += __shfl_xor_sync(0xffffffffu, s,  off);
        sq += __shfl_xor_sync(0xffffffffu, sq, off);
    }
    __shared__ float ws[8], wq2[8];
    if (lane == 0) { ws[warp] = s; wq2[warp] = sq; }
    __syncthreads();
    if (warp == 0) {
        float a = (lane < 8) ? ws[lane]  : 0.f;
        float c = (lane < 8) ? wq2[lane] : 0.f;
        #pragma unroll
        for (int off = 4; off > 0; off >>= 1) {
            a += __shfl_xor_sync(0xffffffffu, a, off);
            c += __shfl_xor_sync(0xffffffffu, c, off);
        }
        if (lane == 0) { ws[0] = a; wq2[0] = c; }
    }
    __syncthreads();
    float mu  = ws[0] * (1.f / D_);
    float var = wq2[0] * (1.f / D_) - mu * mu;
    float inv = rsqrtf(var + 1e-5f);
    float* o = out + (size_t)row * D_;
    for (int d = tid; d < D_; d += 256)
        o[d] = f2tf((xr[d] - mu) * inv * w[d] + b[d]);
}

// ---------------- fused split-K reduce + LayerNorm ----------------------------
// h += bias + sum(parts); lnout = f2tf(LN(h) * w + b2)
__global__ void reduce_ln(float* __restrict__ h, const float* __restrict__ bias,
                          const float* __restrict__ part, int nsplit,
                          const float* __restrict__ w, const float* __restrict__ b2,
                          float* __restrict__ lnout) {
    const int row  = blockIdx.x;
    const int tid  = threadIdx.x;
    const int lane = tid & 31;
    const int warp = tid >> 5;
    const int c4   = tid * 4;

    float4 acc = *(float4*)&h[(size_t)row * D_ + c4];
    float4 bv  = *(const float4*)&bias[c4];
    acc.x += bv.x; acc.y += bv.y; acc.z += bv.z; acc.w += bv.w;
    for (int s = 0; s < nsplit; s++) {
        float4 p = *(const float4*)&part[(size_t)s * M_ * D_ + (size_t)row * D_ + c4];
        acc.x += p.x; acc.y += p.y; acc.z += p.z; acc.w += p.w;
    }
    *(float4*)&h[(size_t)row * D_ + c4] = acc;

    float s = acc.x + acc.y + acc.z + acc.w;
    float sq = acc.x*acc.x + acc.y*acc.y + acc.z*acc.z + acc.w*acc.w;
    #pragma unroll
    for (int off = 16; off > 0; off >>= 1) {
        s  += __shfl_xor_sync(0xffffffffu, s,  off);
        sq += __shfl_xor_sync(0xffffffffu, sq, off);
    }
    __shared__ float ws[8], wq2[8];
    if (lane == 0) { ws[warp] = s; wq2[warp] = sq; }
    __syncthreads();
    if (warp == 0) {
        float a = (lane < 8) ? ws[lane]  : 0.f;
        float c = (lane < 8) ? wq2[lane] : 0.f;
        #pragma unroll
        for (int off = 4; off > 0; off >>= 1) {
            a += __shfl_xor_sync(0xffffffffu, a, off);
            c += __shfl_xor_sync(0xffffffffu, c, off);
        }
        if (lane == 0) { ws[0] = a; wq2[0] = c; }
    }
    __syncthreads();
    float mu  = ws[0] * (1.f / D_);
    float var = wq2[0] * (1.f / D_) - mu * mu;
    float inv = rsqrtf(var + 1e-5f);
    float4 wv4 = *(const float4*)&w[c4];
    float4 b24 = *(const float4*)&b2[c4];
    float4 o;
    o.x = f2tf((acc.x - mu) * inv * wv4.x + b24.x);
    o.y = f2tf((acc.y - mu) * inv * wv4.y + b24.y);
    o.z = f2tf((acc.z - mu) * inv * wv4.z + b24.z);
    o.w = f2tf((acc.w - mu) * inv * wv4.w + b24.w);
    *(float4*)&lnout[(size_t)row * D_ + c4] = o;
}

// ---------------- common GEMM helpers ------------------------------------------
#define CPA16(dst_u32, src_ptr) \
    asm volatile("cp.async.cg.shared.global [%0], [%1], 16;" :: "r"(dst_u32), "l"(src_ptr))

__device__ __forceinline__ unsigned smem_u32(const void* p) {
    return (unsigned)__cvta_generic_to_shared(p);
}

__device__ __forceinline__ void mma8(float c[4], const unsigned a[4], const unsigned b[2]) {
    asm volatile(
        "mma.sync.aligned.m16n8k8.row.col.f32.tf32.tf32.f32 "
        "{%0,%1,%2,%3}, {%4,%5,%6,%7}, {%8,%9}, {%0,%1,%2,%3};\n"
        : "+f"(c[0]), "+f"(c[1]), "+f"(c[2]), "+f"(c[3])
        : "r"(a[0]), "r"(a[1]), "r"(a[2]), "r"(a[3]), "r"(b[0]), "r"(b[1]));
}

// ---------------- standard GEMM body: 128 x BN_, 3-stage cp.async -------------
// MODE 0:+bias 1:f2tf(relu(+bias)) 2:+bias+residual 3:raw 5:f2tf(+bias)
// MODE 6: f2tf(+bias), store TRANSPOSED to kt[(b*D+col)*T + t]
template <int BN_>
__device__ __forceinline__ void issue_stage(
    float* As, float* Bs, const float* A, const float* W,
    int lda, int Npad, int bm0, int bn0, int k0, int tid)
{
    constexpr int SB = BN_ + 8;
    #pragma unroll
    for (int j = 0; j < 4; j++) {
        int f = tid + j * 256;
        int row = f >> 3, c4 = (f & 7) << 2;
        CPA16(smem_u32(As + row * 36 + c4), A + (size_t)(bm0 + row) * lda + k0 + c4);
    }
    #pragma unroll
    for (int j = 0; j < BN_ / 32; j++) {
        int f = tid + j * 256;
        int row = (BN_ == 128) ? (f >> 5) : (f >> 4);
        int c4  = (BN_ == 128) ? ((f & 31) << 2) : ((f & 15) << 2);
        CPA16(smem_u32(Bs + row * SB + c4), W + (size_t)(k0 + row) * Npad + bn0 + c4);
    }
    asm volatile("cp.async.commit_group;");
}

template <int MODE, int BN_, int GUARD>
__device__ __forceinline__ void tgemm_body(
    const float* __restrict__ A, const float* __restrict__ W,
    const float* __restrict__ bias, const float* __restrict__ R,
    float* __restrict__ C, int lda, int KL, int N, int Npad, int bm0, int bn0)
{
    constexpr int SB  = BN_ + 8;
    constexpr int ASZ = 128 * 36;
    constexpr int BSZ = 32 * SB;
    constexpr int NI  = BN_ / 32;

    extern __shared__ float sm[];
    float* As = sm;
    float* Bs = sm + 3 * ASZ;

    const int tid  = threadIdx.x;
    const int lane = tid & 31;
    const int warp = tid >> 5;
    const int g    = lane >> 2;
    const int tg   = lane & 3;
    const int wm0  = (warp >> 2) * 64;
    const int wn0  = (warp & 3) * (BN_ / 4);

    float acc[4][NI][4];
    #pragma unroll
    for (int mi = 0; mi < 4; mi++)
        #pragma unroll
        for (int ni = 0; ni < NI; ni++)
            #pragma unroll
            for (int r = 0; r < 4; r++) acc[mi][ni][r] = 0.f;

    const int nIter = KL / 32;
    issue_stage<BN_>(As, Bs, A, W, lda, Npad, bm0, bn0, 0, tid);
    issue_stage<BN_>(As + ASZ, Bs + BSZ, A, W, lda, Npad, bm0, bn0, 32, tid);

    int st = 0, stw = 2;
    for (int t = 0; t < nIter; t++) {
        if (t + 1 < nIter) asm volatile("cp.async.wait_group 1;");
        else               asm volatile("cp.async.wait_group 0;");
        __syncthreads();

        const float* Ast = As + st * ASZ;
        const float* Bst = Bs + st * BSZ;
        #pragma unroll
        for (int kk = 0; kk < 32; kk += 8) {
            unsigned a[4][4], b[NI][2];
            #pragma unroll
            for (int mi = 0; mi < 4; mi++) {
                int r0 = wm0 + mi * 16 + g;
                a[mi][0] = __float_as_uint(Ast[(r0    ) * 36 + kk + tg]);
                a[mi][1] = __float_as_uint(Ast[(r0 + 8) * 36 + kk + tg]);
                a[mi][2] = __float_as_uint(Ast[(r0    ) * 36 + kk + tg + 4]);
                a[mi][3] = __float_as_uint(Ast[(r0 + 8) * 36 + kk + tg + 4]);
            }
            #pragma unroll
            for (int ni = 0; ni < NI; ni++) {
                int c = wn0 + ni * 8 + g;
                b[ni][0] = __float_as_uint(Bst[(kk + tg    ) * SB + c]);
                b[ni][1] = __float_as_uint(Bst[(kk + tg + 4) * SB + c]);
            }
            #pragma unroll
            for (int mi = 0; mi < 4; mi++)
                #pragma unroll
                for (int ni = 0; ni < NI; ni++)
                    mma8(acc[mi][ni], a[mi], b[ni]);
        }

        if (t + 2 < nIter) {
            issue_stage<BN_>(As + stw * ASZ, Bs + stw * BSZ, A, W, lda, Npad, bm0, bn0,
                             (t + 2) * 32, tid);
            stw = (stw == 2) ? 0 : stw + 1;
        }
        st = (st == 2) ? 0 : st + 1;
    }

    #pragma unroll
    for (int mi = 0; mi < 4; mi++) {
        #pragma unroll
        for (int ni = 0; ni < NI; ni++) {
            int row0 = bm0 + wm0 + mi * 16 + g;
            int col0 = bn0 + wn0 + ni * 8 + 2 * tg;
            #pragma unroll
            for (int rr = 0; rr < 2; rr++) {
                int row = row0 + rr * 8;
                #pragma unroll
                for (int cc = 0; cc < 2; cc++) {
                    int col = col0 + cc;
                    if (!GUARD || col < N) {
                        float v = acc[mi][ni][rr * 2 + cc];
                        if (MODE != 3) v += bias[col];
                        if (MODE == 1) v = f2tf(fmaxf(v, 0.f));
                        if (MODE == 2) v += R[(size_t)row * N + col];
                        if (MODE == 5) v = f2tf(v);
                        if (MODE == 6) {
                            C[((size_t)(row >> 10) * D_ + col) * T_ + (row & (T_ - 1))]
                                = f2tf(v);
                        } else {
                            C[(size_t)row * N + col] = v;
                        }
                    }
                }
            }
        }
    }
}

// bm-fastest grid (B-tile reuse; for N >> M GEMMs)
template <int MODE, int BN_, int GUARD>
__global__ __launch_bounds__(256, 2)
void tgemm_s(const float* __restrict__ A, const float* __restrict__ W,
             const float* __restrict__ bias, const float* __restrict__ R,
             float* __restrict__ C, int K, int N, int Npad) {
    tgemm_body<MODE, BN_, GUARD>(A, W, bias, R, C, K, K, N, Npad,
                                 blockIdx.x * 128, blockIdx.y * BN_);
}

__global__ __launch_bounds__(256, 2)
void tgemm_qkv(const float* __restrict__ A,
               const float* __restrict__ wq, const float* __restrict__ wk,
               const float* __restrict__ wv,
               const float* __restrict__ bq, const float* __restrict__ bk,
               const float* __restrict__ bv,
               float* __restrict__ q, float* __restrict__ kt, float* __restrict__ v) {
    int z = blockIdx.z;
    if (z == 0) {
        tgemm_body<5, 128, 0>(A, wq, bq, nullptr, q, D_, D_, D_, D_,
                              blockIdx.y * 128, blockIdx.x * 128);
    } else if (z == 1) {
        tgemm_body<6, 128, 0>(A, wk, bk, nullptr, kt, D_, D_, D_, D_,
                              blockIdx.y * 128, blockIdx.x * 128);
    } else {
        tgemm_body<5, 128, 0>(A, wv, bv, nullptr, v, D_, D_, D_, D_,
                              blockIdx.y * 128, blockIdx.x * 128);
    }
}

// split-K GEMM: blockIdx.z = split; raw partials to part[z][M][N]
__global__ __launch_bounds__(256, 2)
void tgemm_sk(const float* __restrict__ A, const float* __restrict__ W,
              float* __restrict__ part, int K, int KL, int N) {
    const int s = blockIdx.z;
    tgemm_body<3, 64, 0>(A + (size_t)s * KL,
                         W + (size_t)s * KL * N,
                         nullptr, nullptr,
                         part + (size_t)s * M_ * N,
                         K, KL, N, N,
                         blockIdx.y * 128, blockIdx.x * 64);
}

// ---------------- flash attention v5: tensor-core + split-KV -------------------
// grid (T/QT, H, B*2): z = b*2 + s. Split s handles half the causal KV range,
// writes partial O (unnormalized) + (m,l) to scratch; attn_combine merges.
#define QT 128
#define KT 32
#define FQ  0
#define FKT (QT*68)
#define FVV (FKT + 2*64*36)
#define FPP (FVV + 2*KT*68)
#define SMEM_ATT ((FPP + QT*36) * 4)    // 89088 B

__global__ __launch_bounds__(256)
void flash_attn(const float* __restrict__ q,
                const float* __restrict__ kt,
                const float* __restrict__ v,
                float* __restrict__ part, float* __restrict__ ml) {
    extern __shared__ float sm[];
    float* Qs = sm + FQ;
    float* Kt = sm + FKT;
    float* Vs = sm + FVV;
    float* Ps = sm + FPP;

    const int q0   = (gridDim.x - 1 - blockIdx.x) * QT;  // longest first
    const int h    = blockIdx.y;
    const int b    = blockIdx.z >> 1;
    const int s    = blockIdx.z & 1;
    const int tid  = threadIdx.x;
    const int lane = tid & 31;
    const int warp = tid >> 5;
    const int g    = lane >> 2;
    const int tg   = lane & 3;
    const int wm   = warp * 16;

    const size_t base   = ((size_t)b * T_) * D_ + (size_t)h * HD_;
    const size_t base_k = ((size_t)b * D_ + (size_t)h * HD_) * T_;

    const int half = (q0 + QT) / 2;        // multiple of 64
    const int kvs  = s * half;             // this split's kv start
    const int nTiles = half / KT;

    #pragma unroll
    for (int i = tid; i < QT * 16; i += 256) {
        int r = i >> 4, c4 = (i & 15) << 2;
        *(float4*)&Qs[r * 68 + c4] = *(const float4*)&q[base + (size_t)(q0 + r) * D_ + c4];
    }

    float oa[8][4];
    #pragma unroll
    for (int ni = 0; ni < 8; ni++)
        #pragma unroll
        for (int r = 0; r < 4; r++) oa[ni][r] = 0.f;
    float m0 = -1e30f, m1 = -1e30f, l0 = 0.f, l1 = 0.f;

    // prologue: first tile of this split -> stage 0
    #pragma unroll
    for (int j = 0; j < 2; j++) {
        int f = tid + j * 256;
        int rd = f >> 3, chd = (f & 7) << 2;
        CPA16(smem_u32(Kt + rd * 36 + chd), kt + base_k + (size_t)rd * T_ + kvs + chd);
        int rv = f >> 4, chv = (f & 15) << 2;
        CPA16(smem_u32(Vs + rv * 68 + chv), v + base + (size_t)(kvs + rv) * D_ + chv);
    }
    asm volatile("cp.async.commit_group;");

    for (int t0 = 0; t0 < nTiles; t0++) {
        const int s0  = kvs + t0 * KT;
        const int buf = t0 & 1;
        asm volatile("cp.async.wait_group 0;");
        __syncthreads();

        if (t0 + 1 < nTiles) {
            const int nb  = buf ^ 1;
            const int ns0 = s0 + KT;
            #pragma unroll
            for (int j = 0; j < 2; j++) {
                int f = tid + j * 256;
                int rd = f >> 3, chd = (f & 7) << 2;
                CPA16(smem_u32(Kt + nb * 64 * 36 + rd * 36 + chd),
                      kt + base_k + (size_t)rd * T_ + ns0 + chd);
                int rv = f >> 4, chv = (f & 15) << 2;
                CPA16(smem_u32(Vs + nb * KT * 68 + rv * 68 + chv),
                      v + base + (size_t)(ns0 + rv) * D_ + chv);
            }
            asm volatile("cp.async.commit_group;");
        }

        const float* Ktb = Kt + buf * 64 * 36;
        const float* Vb  = Vs + buf * KT * 68;

        float sf[4][4];
        #pragma unroll
        for (int ni = 0; ni < 4; ni++)
            #pragma unroll
            for (int r = 0; r < 4; r++) sf[ni][r] = 0.f;
        #pragma unroll
        for (int kk = 0; kk < 64; kk += 8) {
            unsigned a[4], bfr[4][2];
            a[0] = __float_as_uint(Qs[(wm + g    ) * 68 + kk + tg]);
            a[1] = __float_as_uint(Qs[(wm + g + 8) * 68 + kk + tg]);
            a[2] = __float_as_uint(Qs[(wm + g    ) * 68 + kk + tg + 4]);
            a[3] = __float_as_uint(Qs[(wm + g + 8) * 68 + kk + tg + 4]);
            #pragma unroll
            for (int ni = 0; ni < 4; ni++) {
                int c = ni * 8 + g;
                bfr[ni][0] = __float_as_uint(Ktb[(kk + tg    ) * 36 + c]);
                bfr[ni][1] = __float_as_uint(Ktb[(kk + tg + 4) * 36 + c]);
            }
            #pragma unroll
            for (int ni = 0; ni < 4; ni++)
                mma8(sf[ni], a, bfr[ni]);
        }

        const int r0 = q0 + wm + g;
        const int r1 = r0 + 8;
        #pragma unroll
        for (int ni = 0; ni < 4; ni++) {
            int col = s0 + ni * 8 + 2 * tg;
            sf[ni][0] = (col     <= r0) ? sf[ni][0] * 0.125f : -1e30f;
            sf[ni][1] = (col + 1 <= r0) ? sf[ni][1] * 0.125f : -1e30f;
            sf[ni][2] = (col     <= r1) ? sf[ni][2] * 0.125f : -1e30f;
            sf[ni][3] = (col + 1 <= r1) ? sf[ni][3] * 0.125f : -1e30f;
        }
        float tm0 = -1e30f, tm1 = -1e30f;
        #pragma unroll
        for (int ni = 0; ni < 4; ni++) {
            tm0 = fmaxf(tm0, fmaxf(sf[ni][0], sf[ni][1]));
            tm1 = fmaxf(tm1, fmaxf(sf[ni][2], sf[ni][3]));
        }
        tm0 = fmaxf(tm0, __shfl_xor_sync(0xffffffffu, tm0, 1));
        tm0 = fmaxf(tm0, __shfl_xor_sync(0xffffffffu, tm0, 2));
        tm1 = fmaxf(tm1, __shfl_xor_sync(0xffffffffu, tm1, 1));
        tm1 = fmaxf(tm1, __shfl_xor_sync(0xffffffffu, tm1, 2));
        float m0n = fmaxf(m0, tm0), m1n = fmaxf(m1, tm1);
        float sc0 = __expf(m0 - m0n), sc1 = __expf(m1 - m1n);
        float ps0 = 0.f, ps1 = 0.f;
        #pragma unroll
        for (int ni = 0; ni < 4; ni++) {
            sf[ni][0] = __expf(sf[ni][0] - m0n); ps0 += sf[ni][0];
            sf[ni][1] = __expf(sf[ni][1] - m0n); ps0 += sf[ni][1];
            sf[ni][2] = __expf(sf[ni][2] - m1n); ps1 += sf[ni][2];
            sf[ni][3] = __expf(sf[ni][3] - m1n); ps1 += sf[ni][3];
        }
        ps0 += __shfl_xor_sync(0xffffffffu, ps0, 1);
        ps0 += __shfl_xor_sync(0xffffffffu, ps0, 2);
        ps1 += __shfl_xor_sync(0xffffffffu, ps1, 1);
        ps1 += __shfl_xor_sync(0xffffffffu, ps1, 2);
        l0 = l0 * sc0 + ps0;  l1 = l1 * sc1 + ps1;
        m0 = m0n;  m1 = m1n;
        #pragma unroll
        for (int ni = 0; ni < 8; ni++) {
            oa[ni][0] *= sc0; oa[ni][1] *= sc0;
            oa[ni][2] *= sc1; oa[ni][3] *= sc1;
        }

        #pragma unroll
        for (int ni = 0; ni < 4; ni++) {
            int cb = ni * 8 + 2 * tg;
            Ps[(wm + g    ) * 36 + cb    ] = f2tf(sf[ni][0]);
            Ps[(wm + g    ) * 36 + cb + 1] = f2tf(sf[ni][1]);
            Ps[(wm + g + 8) * 36 + cb    ] = f2tf(sf[ni][2]);
            Ps[(wm + g + 8) * 36 + cb + 1] = f2tf(sf[ni][3]);
        }
        __syncwarp();

        #pragma unroll
        for (int kk = 0; kk < KT; kk += 8) {
            unsigned a2[4], b2[2];
            a2[0] = __float_as_uint(Ps[(wm + g    ) * 36 + kk + tg]);
            a2[1] = __float_as_uint(Ps[(wm + g + 8) * 36 + kk + tg]);
            a2[2] = __float_as_uint(Ps[(wm + g    ) * 36 + kk + tg + 4]);
            a2[3] = __float_as_uint(Ps[(wm + g + 8) * 36 + kk + tg + 4]);
            #pragma unroll
            for (int ni = 0; ni < 8; ni++) {
                int c = ni * 8 + g;
                b2[0] = __float_as_uint(Vb[(kk + tg    ) * 68 + c]);
                b2[1] = __float_as_uint(Vb[(kk + tg + 4) * 68 + c]);
                mma8(oa[ni], a2, b2);
            }
        }
    }

    // ---- epilogue: write raw partial O + (m,l) ----
    float* po = part + (size_t)s * M_ * D_;
    const int r0 = q0 + wm + g;
    const int r1 = r0 + 8;
    if (tg == 0) {
        size_t mlrow0 = ((size_t)b * H_ + h) * T_ + r0;
        size_t mlrow1 = ((size_t)b * H_ + h) * T_ + r1;
        ml[(s * 2 + 0) * SML + mlrow0] = m0;
        ml[(s * 2 + 1) * SML + mlrow0] = l0;
        ml[(s * 2 + 0) * SML + mlrow1] = m1;
        ml[(s * 2 + 1) * SML + mlrow1] = l1;
    }
    #pragma unroll
    for (int ni = 0; ni < 8; ni++) {
        int col = ni * 8 + 2 * tg;
        *(float2*)&po[base + (size_t)r0 * D_ + col] = make_float2(oa[ni][0], oa[ni][1]);
        *(float2*)&po[base + (size_t)r1 * D_ + col] = make_float2(oa[ni][2], oa[ni][3]);
    }
}

// combine the two KV-splits: O = (O0*e^{m0-m} + O1*e^{m1-m}) / l
__global__ void attn_combine(const float* __restrict__ part,
                             const float* __restrict__ ml,
                             float* __restrict__ attn) {
    const int row = blockIdx.x;           // b*T + t
    const int b   = row >> 10;
    const int t   = row & (T_ - 1);
    const int c4  = threadIdx.x * 4;
    const int h   = c4 >> 6;

    size_t mlrow = ((size_t)b * H_ + h) * T_ + t;
    float m0 = ml[0 * SML + mlrow], l0 = ml[1 * SML + mlrow];
    float m1 = ml[2 * SML + mlrow], l1 = ml[3 * SML + mlrow];
    float m  = fmaxf(m0, m1);
    float w0 = __expf(m0 - m), w1 = __expf(m1 - m);
    float li = 1.f / (l0 * w0 + l1 * w1);

    float4 o0 = *(const float4*)&part[(size_t)row * D_ + c4];
    float4 o1 = *(const float4*)&part[(size_t)M_ * D_ + (size_t)row * D_ + c4];
    float4 o;
    o.x = f2tf((o0.x * w0 + o1.x * w1) * li);
    o.y = f2tf((o0.y * w0 + o1.y * w1) * li);
    o.z = f2tf((o0.z * w0 + o1.z * w1) * li);
    o.w = f2tf((o0.w * w0 + o1.w * w1) * li);
    *(float4*)&attn[(size_t)row * D_ + c4] = o;
}

// ---------------- launch -----------------------------------------------------
extern "C" void kernel_launch(void* const* d_in, const int* in_sizes, int n_in,
                              void* d_out, int out_size) {
    const int*   x       = (const int*)  d_in[0];
    const float* tok_emb = (const float*)d_in[1];
    const float* pos_emb = (const float*)d_in[2];
    const float* wq      = (const float*)d_in[3];
    const float* bq      = (const float*)d_in[4];
    const float* wk      = (const float*)d_in[5];
    const float* bk      = (const float*)d_in[6];
    const float* wv      = (const float*)d_in[7];
    const float* bv      = (const float*)d_in[8];
    const float* wo      = (const float*)d_in[9];
    const float* bo      = (const float*)d_in[10];
    const float* ln1_w   = (const float*)d_in[11];
    const float* ln1_b   = (const float*)d_in[12];
    const float* ln2_w   = (const float*)d_in[13];
    const float* ln2_b   = (const float*)d_in[14];
    const float* ffn_w1  = (const float*)d_in[15];
    const float* ffn_b1  = (const float*)d_in[16];
    const float* ffn_w2  = (const float*)d_in[17];
    const float* ffn_b2  = (const float*)d_in[18];
    const float* lnf_w   = (const float*)d_in[19];
    const float* lnf_b   = (const float*)d_in[20];
    const float* proj_w  = (const float*)d_in[21];
    const float* proj_b  = (const float*)d_in[22];
    float* logits = (float*)d_out;

    float *h, *ln, *q, *kt, *v, *attn, *mid, *part, *ml;
    float *cwq, *cwk, *cwv, *cwo, *cw1, *cw2, *cpj;
    cudaGetSymbolAddress((void**)&h,    g_h);
    cudaGetSymbolAddress((void**)&ln,   g_ln);
    cudaGetSymbolAddress((void**)&q,    g_q);
    cudaGetSymbolAddress((void**)&kt,   g_kt);
    cudaGetSymbolAddress((void**)&v,    g_v);
    cudaGetSymbolAddress((void**)&attn, g_attn);
    cudaGetSymbolAddress((void**)&mid,  g_mid);
    cudaGetSymbolAddress((void**)&part, g_part);
    cudaGetSymbolAddress((void**)&ml,   g_ml);
    cudaGetSymbolAddress((void**)&cwq,  g_cwq);
    cudaGetSymbolAddress((void**)&cwk,  g_cwk);
    cudaGetSymbolAddress((void**)&cwv,  g_cwv);
    cudaGetSymbolAddress((void**)&cwo,  g_cwo);
    cudaGetSymbolAddress((void**)&cw1,  g_cw1);
    cudaGetSymbolAddress((void**)&cw2,  g_cw2);
    cudaGetSymbolAddress((void**)&cpj,  g_cpj);

    const int SMEM128 = 3 * (128 * 36 + 32 * 136) * 4;   // 107520 B
    const int SMEM64  = 3 * (128 * 36 + 32 * 72)  * 4;   // 82944 B
    cudaFuncSetAttribute(tgemm_sk,        cudaFuncAttributeMaxDynamicSharedMemorySize, SMEM64);
    cudaFuncSetAttribute(tgemm_s<1,128,0>,cudaFuncAttributeMaxDynamicSharedMemorySize, SMEM128);
    cudaFuncSetAttribute(tgemm_s<0,128,1>,cudaFuncAttributeMaxDynamicSharedMemorySize, SMEM128);
    cudaFuncSetAttribute(tgemm_qkv,       cudaFuncAttributeMaxDynamicSharedMemorySize, SMEM128);
    cudaFuncSetAttribute(flash_attn,      cudaFuncAttributeMaxDynamicSharedMemorySize, SMEM_ATT);

    dim3 gQKV(D_ / 128, M_ / 128, 3);        // (8,16,3)
    dim3 gWO(D_ / 64, M_ / 128, 2);          // (16,16,2) split-K=2
    dim3 gFF1(M_ / 128, FF_ / 128);          // (16,32)  bm-fastest
    dim3 gFF2(D_ / 64, M_ / 128, 4);         // (16,16,4) split-K=4
    dim3 gPRJ(M_ / 128, VP_ / 128);          // (16,393) bm-fastest
    dim3 gAT(T_ / QT, H_, B_ * 2);           // (8,16,4) split-KV=2

    // Launch order: our #4 is flash_attn (ncu -s 5 lands on our 4th launch).
    conv_all<<<dim3(1024, 7), 256>>>(                                         // 1
        (const float4*)wq, (const float4*)wk, (const float4*)wv,
        (const float4*)wo, (const float4*)ffn_w1, (const float4*)ffn_w2,
        proj_w,
        (float4*)cwq, (float4*)cwk, (float4*)cwv,
        (float4*)cwo, (float4*)cw1, (float4*)cw2, cpj);
    embed_ln<<<M_, 256>>>(x, tok_emb, pos_emb, ln1_w, ln1_b, h, ln);          // 2

    for (int l = 0; l < L_; l++) {
        float* cwq_l = cwq + (size_t)l * D_ * D_;
        float* cwk_l = cwk + (size_t)l * D_ * D_;
        float* cwv_l = cwv + (size_t)l * D_ * D_;
        float* cwo_l = cwo + (size_t)l * D_ * D_;
        float* cw1_l = cw1 + (size_t)l * D_ * FF_;
        float* cw2_l = cw2 + (size_t)l * FF_ * D_;

        tgemm_qkv<<<gQKV, 256, SMEM128>>>(ln, cwq_l, cwk_l, cwv_l,
                                          bq + l * D_, bk + l * D_, bv + l * D_,
                                          q, kt, v);                          // 3 (l=0)

        flash_attn<<<gAT, 256, SMEM_ATT>>>(q, kt, v, part, ml);               // 4 (l=0)
        attn_combine<<<M_, 256>>>(part, ml, attn);

        tgemm_sk<<<gWO, 256, SMEM64>>>(attn, cwo_l, part, D_, D_ / 2, D_);
        reduce_ln<<<M_, 256>>>(h, bo + l * D_, part, 2,
                               ln2_w + l * D_, ln2_b + l * D_, ln);

        tgemm_s<1,128,0><<<gFF1, 256, SMEM128>>>(ln, cw1_l, ffn_b1 + l * FF_,
                                                 nullptr, mid, D_, FF_, FF_);

        tgemm_sk<<<gFF2, 256, SMEM64>>>(mid, cw2_l, part, FF_, FF_ / 4, D_);
        if (l + 1 < L_)
            reduce_ln<<<M_, 256>>>(h, ffn_b2 + l * D_, part, 4,
                                   ln1_w + (l + 1) * D_, ln1_b + (l + 1) * D_, ln);
        else
            reduce_ln<<<M_, 256>>>(h, ffn_b2 + l * D_, part, 4, lnf_w, lnf_b, ln);
    }

    tgemm_s<0,128,1><<<gPRJ, 256, SMEM128>>>(ln, cpj, proj_b, nullptr, logits,
                                             D_, V_, VP_);
}

// round 16
// speedup vs baseline: 2.5030x; 1.0015x over previous
#include <cuda_runtime.h>
#include <math.h>

#define B_  2
#define T_  1024
#define D_  1024
#define H_  16
#define HD_ 64
#define FF_ 4096
#define L_  6
#define V_  50257
#define M_  (B_*T_)        // 2048 rows
#define VP_ 50304          // V padded to 128
#define SML (B_*H_*T_)     // 32768 (m/l scratch stride)

// ---------------- scratch (static device globals; no allocation) -------------
__device__ float g_h   [M_*D_];
__device__ float g_ln  [M_*D_];
__device__ float g_q   [M_*D_];
__device__ float g_kt  [M_*D_];          // K stored TRANSPOSED: [(b*D + hd)*T + t]
__device__ float g_v   [M_*D_];
__device__ float g_attn[M_*D_];
__device__ float g_mid [M_*FF_];
__device__ float g_part[4*M_*D_];        // split-K partials / flash O partials
__device__ float g_ml  [4*SML];          // flash (m,l) partials: [(s*2+p)][b][h][t]
// tf32-preconverted weights (row-major [K][N])
__device__ float g_cwq [L_*D_*D_];
__device__ float g_cwk [L_*D_*D_];
__device__ float g_cwv [L_*D_*D_];
__device__ float g_cwo [L_*D_*D_];
__device__ float g_cw1 [L_*D_*FF_];
__device__ float g_cw2 [L_*FF_*D_];
__device__ float g_cpj [(size_t)D_*VP_];

__device__ __forceinline__ float f2tf(float x) {
    unsigned u;
    asm("cvt.rna.tf32.f32 %0, %1;" : "=r"(u) : "f"(x));
    return __uint_as_float(u);
}

// ---------------- single fused weight conversion -------------------------------
__global__ void conv_all(const float4* __restrict__ wq, const float4* __restrict__ wk,
                         const float4* __restrict__ wv, const float4* __restrict__ wo,
                         const float4* __restrict__ w1, const float4* __restrict__ w2,
                         const float*  __restrict__ pj,
                         float4* __restrict__ cwq, float4* __restrict__ cwk,
                         float4* __restrict__ cwv, float4* __restrict__ cwo,
                         float4* __restrict__ cw1, float4* __restrict__ cw2,
                         float*  __restrict__ cpj) {
    const int seg = blockIdx.y;
    if (seg < 6) {
        const float4* s; float4* d; int n4;
        switch (seg) {
            case 0: s = wq; d = cwq; n4 = L_*D_*D_/4;  break;
            case 1: s = wk; d = cwk; n4 = L_*D_*D_/4;  break;
            case 2: s = wv; d = cwv; n4 = L_*D_*D_/4;  break;
            case 3: s = wo; d = cwo; n4 = L_*D_*D_/4;  break;
            case 4: s = w1; d = cw1; n4 = L_*D_*FF_/4; break;
            default:s = w2; d = cw2; n4 = L_*D_*FF_/4; break;
        }
        for (int i = blockIdx.x * blockDim.x + threadIdx.x; i < n4;
             i += gridDim.x * blockDim.x) {
            float4 v = s[i];
            d[i] = make_float4(f2tf(v.x), f2tf(v.y), f2tf(v.z), f2tf(v.w));
        }
    } else {
        const long long total = (long long)D_ * VP_;
        for (long long i = (long long)blockIdx.x * blockDim.x + threadIdx.x; i < total;
             i += (long long)gridDim.x * blockDim.x) {
            int row = (int)(i / VP_), col = (int)(i - (long long)row * VP_);
            cpj[i] = (col < V_) ? f2tf(pj[(size_t)row * V_ + col]) : 0.f;
        }
    }
}

// ---------------- fused embedding + layer-0 LN1 --------------------------------
__global__ void embed_ln(const int* __restrict__ x,
                         const float* __restrict__ tok,
                         const float* __restrict__ pos,
                         const float* __restrict__ w,
                         const float* __restrict__ b,
                         float* __restrict__ h, float* __restrict__ lnout) {
    const int row  = blockIdx.x;
    const int tid  = threadIdx.x;
    const int lane = tid & 31;
    const int warp = tid >> 5;
    const int t    = row % T_;
    const int id   = x[row];
    const float* te = tok + (size_t)id * D_;
    const float* pe = pos + (size_t)t  * D_;

    float e[4];
    float s = 0.f, sq = 0.f;
    #pragma unroll
    for (int i = 0; i < 4; i++) {
        int d = tid + i * 256;
        e[i] = te[d] + pe[d];
        s += e[i]; sq += e[i] * e[i];
        h[(size_t)row * D_ + d] = e[i];
    }
    #pragma unroll
    for (int off = 16; off > 0; off >>= 1) {
        s  += __shfl_xor_sync(0xffffffffu, s,  off);
        sq += __shfl_xor_sync(0xffffffffu, sq, off);
    }
    __shared__ float ws[8], wq2[8];
    if (lane == 0) { ws[warp] = s; wq2[warp] = sq; }
    __syncthreads();
    if (warp == 0) {
        float a = (lane < 8) ? ws[lane]  : 0.f;
        float c = (lane < 8) ? wq2[lane] : 0.f;
        #pragma unroll
        for (int off = 4; off > 0; off >>= 1) {
            a += __shfl_xor_sync(0xffffffffu, a, off);
            c += __shfl_xor_sync(0xffffffffu, c, off);
        }
        if (lane == 0) { ws[0] = a; wq2[0] = c; }
    }
    __syncthreads();
    float mu  = ws[0] * (1.f / D_);
    float var = wq2[0] * (1.f / D_) - mu * mu;
    float inv = rsqrtf(var + 1e-5f);
    #pragma unroll
    for (int i = 0; i < 4; i++) {
        int d = tid + i * 256;
        lnout[(size_t)row * D_ + d] = f2tf((e[i] - mu) * inv * w[d] + b[d]);
    }
}

// ---------------- layernorm (used only standalone if ever needed) -------------
__global__ void ln_kernel(const float* __restrict__ in,
                          const float* __restrict__ w,
                          const float* __restrict__ b,
                          float* __restrict__ out) {
    const int row  = blockIdx.x;
    const int tid  = threadIdx.x;
    const int lane = tid & 31;
    const int warp = tid >> 5;
    const float* xr = in + (size_t)row * D_;

    float s = 0.f, sq = 0.f;
    for (int d = tid; d < D_; d += 256) {
        float v = xr[d];
        s += v; sq += v * v;
    }
    #pragma unroll
    for (int off = 16; off > 0; off >>= 1) {
        s  += __shfl_xor_sync(0xffffffffu, s,  off);
        sq += __shfl_xor_sync(0xffffffffu, sq, off);
    }
    __shared__ float ws[8], wq2[8];
    if (lane == 0) { ws[warp] = s; wq2[warp] = sq; }
    __syncthreads();
    if (warp == 0) {
        float a = (lane < 8) ? ws[lane]  : 0.f;
        float c = (lane < 8) ? wq2[lane] : 0.f;
        #pragma unroll
        for (int off = 4; off > 0; off >>= 1) {
            a += __shfl_xor_sync(0xffffffffu, a, off);
            c += __shfl_xor_sync(0xffffffffu, c, off);
        }
        if (lane == 0) { ws[0] = a; wq2[0] = c; }
    }
    __syncthreads();
    float mu  = ws[0] * (1.f / D_);
    float var = wq2[0] * (1.f / D_) - mu * mu;
    float inv = rsqrtf(var + 1e-5f);
    float* o = out + (size_t)row * D_;
    for (int d = tid; d < D_; d += 256)
        o[d] = f2tf((xr[d] - mu) * inv * w[d] + b[d]);
}

// ---------------- fused split-K reduce + LayerNorm ----------------------------
// h += bias + sum(parts); lnout = f2tf(LN(h) * w + b2)
__global__ void reduce_ln(float* __restrict__ h, const float* __restrict__ bias,
                          const float* __restrict__ part, int nsplit,
                          const float* __restrict__ w, const float* __restrict__ b2,
                          float* __restrict__ lnout) {
    const int row  = blockIdx.x;
    const int tid  = threadIdx.x;
    const int lane = tid & 31;
    const int warp = tid >> 5;
    const int c4   = tid * 4;

    float4 acc = *(float4*)&h[(size_t)row * D_ + c4];
    float4 bv  = *(const float4*)&bias[c4];
    acc.x += bv.x; acc.y += bv.y; acc.z += bv.z; acc.w += bv.w;
    for (int s = 0; s < nsplit; s++) {
        float4 p = *(const float4*)&part[(size_t)s * M_ * D_ + (size_t)row * D_ + c4];
        acc.x += p.x; acc.y += p.y; acc.z += p.z; acc.w += p.w;
    }
    *(float4*)&h[(size_t)row * D_ + c4] = acc;

    float s = acc.x + acc.y + acc.z + acc.w;
    float sq = acc.x*acc.x + acc.y*acc.y + acc.z*acc.z + acc.w*acc.w;
    #pragma unroll
    for (int off = 16; off > 0; off >>= 1) {
        s  += __shfl_xor_sync(0xffffffffu, s,  off);
        sq += __shfl_xor_sync(0xffffffffu, sq, off);
    }
    __shared__ float ws[8], wq2[8];
    if (lane == 0) { ws[warp] = s; wq2[warp] = sq; }
    __syncthreads();
    if (warp == 0) {
        float a = (lane < 8) ? ws[lane]  : 0.f;
        float c = (lane < 8) ? wq2[lane] : 0.f;
        #pragma unroll
        for (int off = 4; off > 0; off >>= 1) {
            a += __shfl_xor_sync(0xffffffffu, a, off);
            c += __shfl_xor_sync(0xffffffffu, c, off);
        }
        if (lane == 0) { ws[0] = a; wq2[0] = c; }
    }
    __syncthreads();
    float mu  = ws[0] * (1.f / D_);
    float var = wq2[0] * (1.f / D_) - mu * mu;
    float inv = rsqrtf(var + 1e-5f);
    float4 wv4 = *(const float4*)&w[c4];
    float4 b24 = *(const float4*)&b2[c4];
    float4 o;
    o.x = f2tf((acc.x - mu) * inv * wv4.x + b24.x);
    o.y = f2tf((acc.y - mu) * inv * wv4.y + b24.y);
    o.z = f2tf((acc.z - mu) * inv * wv4.z + b24.z);
    o.w = f2tf((acc.w - mu) * inv * wv4.w + b24.w);
    *(float4*)&lnout[(size_t)row * D_ + c4] = o;
}

// ---------------- common GEMM helpers ------------------------------------------
#define CPA16(dst_u32, src_ptr) \
    asm volatile("cp.async.cg.shared.global [%0], [%1], 16;" :: "r"(dst_u32), "l"(src_ptr))

__device__ __forceinline__ unsigned smem_u32(const void* p) {
    return (unsigned)__cvta_generic_to_shared(p);
}

__device__ __forceinline__ void mma8(float c[4], const unsigned a[4], const unsigned b[2]) {
    asm volatile(
        "mma.sync.aligned.m16n8k8.row.col.f32.tf32.tf32.f32 "
        "{%0,%1,%2,%3}, {%4,%5,%6,%7}, {%8,%9}, {%0,%1,%2,%3};\n"
        : "+f"(c[0]), "+f"(c[1]), "+f"(c[2]), "+f"(c[3])
        : "r"(a[0]), "r"(a[1]), "r"(a[2]), "r"(a[3]), "r"(b[0]), "r"(b[1]));
}

// ---------------- standard GEMM body: 128 x BN_, 3-stage cp.async -------------
// MODE 0:+bias 1:f2tf(relu(+bias)) 2:+bias+residual 3:raw 5:f2tf(+bias)
// MODE 6: f2tf(+bias), store TRANSPOSED to kt[(b*D+col)*T + t]
template <int BN_>
__device__ __forceinline__ void issue_stage(
    float* As, float* Bs, const float* A, const float* W,
    int lda, int Npad, int bm0, int bn0, int k0, int tid)
{
    constexpr int SB = BN_ + 8;
    #pragma unroll
    for (int j = 0; j < 4; j++) {
        int f = tid + j * 256;
        int row = f >> 3, c4 = (f & 7) << 2;
        CPA16(smem_u32(As + row * 36 + c4), A + (size_t)(bm0 + row) * lda + k0 + c4);
    }
    #pragma unroll
    for (int j = 0; j < BN_ / 32; j++) {
        int f = tid + j * 256;
        int row = (BN_ == 128) ? (f >> 5) : (f >> 4);
        int c4  = (BN_ == 128) ? ((f & 31) << 2) : ((f & 15) << 2);
        CPA16(smem_u32(Bs + row * SB + c4), W + (size_t)(k0 + row) * Npad + bn0 + c4);
    }
    asm volatile("cp.async.commit_group;");
}

template <int MODE, int BN_, int GUARD>
__device__ __forceinline__ void tgemm_body(
    const float* __restrict__ A, const float* __restrict__ W,
    const float* __restrict__ bias, const float* __restrict__ R,
    float* __restrict__ C, int lda, int KL, int N, int Npad, int bm0, int bn0)
{
    constexpr int SB  = BN_ + 8;
    constexpr int ASZ = 128 * 36;
    constexpr int BSZ = 32 * SB;
    constexpr int NI  = BN_ / 32;

    extern __shared__ float sm[];
    float* As = sm;
    float* Bs = sm + 3 * ASZ;

    const int tid  = threadIdx.x;
    const int lane = tid & 31;
    const int warp = tid >> 5;
    const int g    = lane >> 2;
    const int tg   = lane & 3;
    const int wm0  = (warp >> 2) * 64;
    const int wn0  = (warp & 3) * (BN_ / 4);

    float acc[4][NI][4];
    #pragma unroll
    for (int mi = 0; mi < 4; mi++)
        #pragma unroll
        for (int ni = 0; ni < NI; ni++)
            #pragma unroll
            for (int r = 0; r < 4; r++) acc[mi][ni][r] = 0.f;

    const int nIter = KL / 32;
    issue_stage<BN_>(As, Bs, A, W, lda, Npad, bm0, bn0, 0, tid);
    issue_stage<BN_>(As + ASZ, Bs + BSZ, A, W, lda, Npad, bm0, bn0, 32, tid);

    int st = 0, stw = 2;
    for (int t = 0; t < nIter; t++) {
        if (t + 1 < nIter) asm volatile("cp.async.wait_group 1;");
        else               asm volatile("cp.async.wait_group 0;");
        __syncthreads();

        const float* Ast = As + st * ASZ;
        const float* Bst = Bs + st * BSZ;
        #pragma unroll
        for (int kk = 0; kk < 32; kk += 8) {
            unsigned a[4][4], b[NI][2];
            #pragma unroll
            for (int mi = 0; mi < 4; mi++) {
                int r0 = wm0 + mi * 16 + g;
                a[mi][0] = __float_as_uint(Ast[(r0    ) * 36 + kk + tg]);
                a[mi][1] = __float_as_uint(Ast[(r0 + 8) * 36 + kk + tg]);
                a[mi][2] = __float_as_uint(Ast[(r0    ) * 36 + kk + tg + 4]);
                a[mi][3] = __float_as_uint(Ast[(r0 + 8) * 36 + kk + tg + 4]);
            }
            #pragma unroll
            for (int ni = 0; ni < NI; ni++) {
                int c = wn0 + ni * 8 + g;
                b[ni][0] = __float_as_uint(Bst[(kk + tg    ) * SB + c]);
                b[ni][1] = __float_as_uint(Bst[(kk + tg + 4) * SB + c]);
            }
            #pragma unroll
            for (int mi = 0; mi < 4; mi++)
                #pragma unroll
                for (int ni = 0; ni < NI; ni++)
                    mma8(acc[mi][ni], a[mi], b[ni]);
        }

        if (t + 2 < nIter) {
            issue_stage<BN_>(As + stw * ASZ, Bs + stw * BSZ, A, W, lda, Npad, bm0, bn0,
                             (t + 2) * 32, tid);
            stw = (stw == 2) ? 0 : stw + 1;
        }
        st = (st == 2) ? 0 : st + 1;
    }

    #pragma unroll
    for (int mi = 0; mi < 4; mi++) {
        #pragma unroll
        for (int ni = 0; ni < NI; ni++) {
            int row0 = bm0 + wm0 + mi * 16 + g;
            int col0 = bn0 + wn0 + ni * 8 + 2 * tg;
            #pragma unroll
            for (int rr = 0; rr < 2; rr++) {
                int row = row0 + rr * 8;
                #pragma unroll
                for (int cc = 0; cc < 2; cc++) {
                    int col = col0 + cc;
                    if (!GUARD || col < N) {
                        float v = acc[mi][ni][rr * 2 + cc];
                        if (MODE != 3) v += bias[col];
                        if (MODE == 1) v = f2tf(fmaxf(v, 0.f));
                        if (MODE == 2) v += R[(size_t)row * N + col];
                        if (MODE == 5) v = f2tf(v);
                        if (MODE == 6) {
                            C[((size_t)(row >> 10) * D_ + col) * T_ + (row & (T_ - 1))]
                                = f2tf(v);
                        } else {
                            C[(size_t)row * N + col] = v;
                        }
                    }
                }
            }
        }
    }
}

// bm-fastest grid (B-tile reuse; for N >> M GEMMs)
template <int MODE, int BN_, int GUARD>
__global__ __launch_bounds__(256, 2)
void tgemm_s(const float* __restrict__ A, const float* __restrict__ W,
             const float* __restrict__ bias, const float* __restrict__ R,
             float* __restrict__ C, int K, int N, int Npad) {
    tgemm_body<MODE, BN_, GUARD>(A, W, bias, R, C, K, K, N, Npad,
                                 blockIdx.x * 128, blockIdx.y * BN_);
}

__global__ __launch_bounds__(256, 2)
void tgemm_qkv(const float* __restrict__ A,
               const float* __restrict__ wq, const float* __restrict__ wk,
               const float* __restrict__ wv,
               const float* __restrict__ bq, const float* __restrict__ bk,
               const float* __restrict__ bv,
               float* __restrict__ q, float* __restrict__ kt, float* __restrict__ v) {
    int z = blockIdx.z;
    if (z == 0) {
        tgemm_body<5, 128, 0>(A, wq, bq, nullptr, q, D_, D_, D_, D_,
                              blockIdx.y * 128, blockIdx.x * 128);
    } else if (z == 1) {
        tgemm_body<6, 128, 0>(A, wk, bk, nullptr, kt, D_, D_, D_, D_,
                              blockIdx.y * 128, blockIdx.x * 128);
    } else {
        tgemm_body<5, 128, 0>(A, wv, bv, nullptr, v, D_, D_, D_, D_,
                              blockIdx.y * 128, blockIdx.x * 128);
    }
}

// split-K GEMM: blockIdx.z = split; raw partials to part[z][M][N]
__global__ __launch_bounds__(256, 2)
void tgemm_sk(const float* __restrict__ A, const float* __restrict__ W,
              float* __restrict__ part, int K, int KL, int N) {
    const int s = blockIdx.z;
    tgemm_body<3, 64, 0>(A + (size_t)s * KL,
                         W + (size_t)s * KL * N,
                         nullptr, nullptr,
                         part + (size_t)s * M_ * N,
                         K, KL, N, N,
                         blockIdx.y * 128, blockIdx.x * 64);
}

// ---------------- flash attention v5: tensor-core + split-KV -------------------
// grid (T/QT, H, B*2): z = b*2 + s. Split s handles half the causal KV range,
// writes partial O (unnormalized) + (m,l) to scratch; attn_combine merges.
#define QT 128
#define KT 32
#define FQ  0
#define FKT (QT*68)
#define FVV (FKT + 2*64*36)
#define FPP (FVV + 2*KT*68)
#define SMEM_ATT ((FPP + QT*36) * 4)    // 89088 B

__global__ __launch_bounds__(256)
void flash_attn(const float* __restrict__ q,
                const float* __restrict__ kt,
                const float* __restrict__ v,
                float* __restrict__ part, float* __restrict__ ml) {
    extern __shared__ float sm[];
    float* Qs = sm + FQ;
    float* Kt = sm + FKT;
    float* Vs = sm + FVV;
    float* Ps = sm + FPP;

    const int q0   = (gridDim.x - 1 - blockIdx.x) * QT;  // longest first
    const int h    = blockIdx.y;
    const int b    = blockIdx.z >> 1;
    const int s    = blockIdx.z & 1;
    const int tid  = threadIdx.x;
    const int lane = tid & 31;
    const int warp = tid >> 5;
    const int g    = lane >> 2;
    const int tg   = lane & 3;
    const int wm   = warp * 16;

    const size_t base   = ((size_t)b * T_) * D_ + (size_t)h * HD_;
    const size_t base_k = ((size_t)b * D_ + (size_t)h * HD_) * T_;

    const int half = (q0 + QT) / 2;        // multiple of 64
    const int kvs  = s * half;             // this split's kv start
    const int nTiles = half / KT;

    #pragma unroll
    for (int i = tid; i < QT * 16; i += 256) {
        int r = i >> 4, c4 = (i & 15) << 2;
        *(float4*)&Qs[r * 68 + c4] = *(const float4*)&q[base + (size_t)(q0 + r) * D_ + c4];
    }

    float oa[8][4];
    #pragma unroll
    for (int ni = 0; ni < 8; ni++)
        #pragma unroll
        for (int r = 0; r < 4; r++) oa[ni][r] = 0.f;
    float m0 = -1e30f, m1 = -1e30f, l0 = 0.f, l1 = 0.f;

    // prologue: first tile of this split -> stage 0
    #pragma unroll
    for (int j = 0; j < 2; j++) {
        int f = tid + j * 256;
        int rd = f >> 3, chd = (f & 7) << 2;
        CPA16(smem_u32(Kt + rd * 36 + chd), kt + base_k + (size_t)rd * T_ + kvs + chd);
        int rv = f >> 4, chv = (f & 15) << 2;
        CPA16(smem_u32(Vs + rv * 68 + chv), v + base + (size_t)(kvs + rv) * D_ + chv);
    }
    asm volatile("cp.async.commit_group;");

    for (int t0 = 0; t0 < nTiles; t0++) {
        const int s0  = kvs + t0 * KT;
        const int buf = t0 & 1;
        asm volatile("cp.async.wait_group 0;");
        __syncthreads();

        if (t0 + 1 < nTiles) {
            const int nb  = buf ^ 1;
            const int ns0 = s0 + KT;
            #pragma unroll
            for (int j = 0; j < 2; j++) {
                int f = tid + j * 256;
                int rd = f >> 3, chd = (f & 7) << 2;
                CPA16(smem_u32(Kt + nb * 64 * 36 + rd * 36 + chd),
                      kt + base_k + (size_t)rd * T_ + ns0 + chd);
                int rv = f >> 4, chv = (f & 15) << 2;
                CPA16(smem_u32(Vs + nb * KT * 68 + rv * 68 + chv),
                      v + base + (size_t)(ns0 + rv) * D_ + chv);
            }
            asm volatile("cp.async.commit_group;");
        }

        const float* Ktb = Kt + buf * 64 * 36;
        const float* Vb  = Vs + buf * KT * 68;

        float sf[4][4];
        #pragma unroll
        for (int ni = 0; ni < 4; ni++)
            #pragma unroll
            for (int r = 0; r < 4; r++) sf[ni][r] = 0.f;
        #pragma unroll
        for (int kk = 0; kk < 64; kk += 8) {
            unsigned a[4], bfr[4][2];
            a[0] = __float_as_uint(Qs[(wm + g    ) * 68 + kk + tg]);
            a[1] = __float_as_uint(Qs[(wm + g + 8) * 68 + kk + tg]);
            a[2] = __float_as_uint(Qs[(wm + g    ) * 68 + kk + tg + 4]);
            a[3] = __float_as_uint(Qs[(wm + g + 8) * 68 + kk + tg + 4]);
            #pragma unroll
            for (int ni = 0; ni < 4; ni++) {
                int c = ni * 8 + g;
                bfr[ni][0] = __float_as_uint(Ktb[(kk + tg    ) * 36 + c]);
                bfr[ni][1] = __float_as_uint(Ktb[(kk + tg + 4) * 36 + c]);
            }
            #pragma unroll
            for (int ni = 0; ni < 4; ni++)
                mma8(sf[ni], a, bfr[ni]);
        }

        const int r0 = q0 + wm + g;
        const int r1 = r0 + 8;
        #pragma unroll
        for (int ni = 0; ni < 4; ni++) {
            int col = s0 + ni * 8 + 2 * tg;
            sf[ni][0] = (col     <= r0) ? sf[ni][0] * 0.125f : -1e30f;
            sf[ni][1] = (col + 1 <= r0) ? sf[ni][1] * 0.125f : -1e30f;
            sf[ni][2] = (col     <= r1) ? sf[ni][2] * 0.125f : -1e30f;
            sf[ni][3] = (col + 1 <= r1) ? sf[ni][3] * 0.125f : -1e30f;
        }
        float tm0 = -1e30f, tm1 = -1e30f;
        #pragma unroll
        for (int ni = 0; ni < 4; ni++) {
            tm0 = fmaxf(tm0, fmaxf(sf[ni][0], sf[ni][1]));
            tm1 = fmaxf(tm1, fmaxf(sf[ni][2], sf[ni][3]));
        }
        tm0 = fmaxf(tm0, __shfl_xor_sync(0xffffffffu, tm0, 1));
        tm0 = fmaxf(tm0, __shfl_xor_sync(0xffffffffu, tm0, 2));
        tm1 = fmaxf(tm1, __shfl_xor_sync(0xffffffffu, tm1, 1));
        tm1 = fmaxf(tm1, __shfl_xor_sync(0xffffffffu, tm1, 2));
        float m0n = fmaxf(m0, tm0), m1n = fmaxf(m1, tm1);
        float sc0 = __expf(m0 - m0n), sc1 = __expf(m1 - m1n);
        float ps0 = 0.f, ps1 = 0.f;
        #pragma unroll
        for (int ni = 0; ni < 4; ni++) {
            sf[ni][0] = __expf(sf[ni][0] - m0n); ps0 += sf[ni][0];
            sf[ni][1] = __expf(sf[ni][1] - m0n); ps0 += sf[ni][1];
            sf[ni][2] = __expf(sf[ni][2] - m1n); ps1 += sf[ni][2];
            sf[ni][3] = __expf(sf[ni][3] - m1n); ps1 += sf[ni][3];
        }
        ps0 += __shfl_xor_sync(0xffffffffu, ps0, 1);
        ps0 += __shfl_xor_sync(0xffffffffu, ps0, 2);
        ps1 += __shfl_xor_sync(0xffffffffu, ps1, 1);
        ps1 += __shfl_xor_sync(0xffffffffu, ps1, 2);
        l0 = l0 * sc0 + ps0;  l1 = l1 * sc1 + ps1;
        m0 = m0n;  m1 = m1n;
        #pragma unroll
        for (int ni = 0; ni < 8; ni++) {
            oa[ni][0] *= sc0; oa[ni][1] *= sc0;
            oa[ni][2] *= sc1; oa[ni][3] *= sc1;
        }

        #pragma unroll
        for (int ni = 0; ni < 4; ni++) {
            int cb = ni * 8 + 2 * tg;
            Ps[(wm + g    ) * 36 + cb    ] = f2tf(sf[ni][0]);
            Ps[(wm + g    ) * 36 + cb + 1] = f2tf(sf[ni][1]);
            Ps[(wm + g + 8) * 36 + cb    ] = f2tf(sf[ni][2]);
            Ps[(wm + g + 8) * 36 + cb + 1] = f2tf(sf[ni][3]);
        }
        __syncwarp();

        #pragma unroll
        for (int kk = 0; kk < KT; kk += 8) {
            unsigned a2[4], b2[2];
            a2[0] = __float_as_uint(Ps[(wm + g    ) * 36 + kk + tg]);
            a2[1] = __float_as_uint(Ps[(wm + g + 8) * 36 + kk + tg]);
            a2[2] = __float_as_uint(Ps[(wm + g    ) * 36 + kk + tg + 4]);
            a2[3] = __float_as_uint(Ps[(wm + g + 8) * 36 + kk + tg + 4]);
            #pragma unroll
            for (int ni = 0; ni < 8; ni++) {
                int c = ni * 8 + g;
                b2[0] = __float_as_uint(Vb[(kk + tg    ) * 68 + c]);
                b2[1] = __float_as_uint(Vb[(kk + tg + 4) * 68 + c]);
                mma8(oa[ni], a2, b2);
            }
        }
    }

    // ---- epilogue: write raw partial O + (m,l) ----
    float* po = part + (size_t)s * M_ * D_;
    const int r0 = q0 + wm + g;
    const int r1 = r0 + 8;
    if (tg == 0) {
        size_t mlrow0 = ((size_t)b * H_ + h) * T_ + r0;
        size_t mlrow1 = ((size_t)b * H_ + h) * T_ + r1;
        ml[(s * 2 + 0) * SML + mlrow0] = m0;
        ml[(s * 2 + 1) * SML + mlrow0] = l0;
        ml[(s * 2 + 0) * SML + mlrow1] = m1;
        ml[(s * 2 + 1) * SML + mlrow1] = l1;
    }
    #pragma unroll
    for (int ni = 0; ni < 8; ni++) {
        int col = ni * 8 + 2 * tg;
        *(float2*)&po[base + (size_t)r0 * D_ + col] = make_float2(oa[ni][0], oa[ni][1]);
        *(float2*)&po[base + (size_t)r1 * D_ + col] = make_float2(oa[ni][2], oa[ni][3]);
    }
}

// combine the two KV-splits: O = (O0*e^{m0-m} + O1*e^{m1-m}) / l
__global__ void attn_combine(const float* __restrict__ part,
                             const float* __restrict__ ml,
                             float* __restrict__ attn) {
    const int row = blockIdx.x;           // b*T + t
    const int b   = row >> 10;
    const int t   = row & (T_ - 1);
    const int c4  = threadIdx.x * 4;
    const int h   = c4 >> 6;

    size_t mlrow = ((size_t)b * H_ + h) * T_ + t;
    float m0 = ml[0 * SML + mlrow], l0 = ml[1 * SML + mlrow];
    float m1 = ml[2 * SML + mlrow], l1 = ml[3 * SML + mlrow];
    float m  = fmaxf(m0, m1);
    float w0 = __expf(m0 - m), w1 = __expf(m1 - m);
    float li = 1.f / (l0 * w0 + l1 * w1);

    float4 o0 = *(const float4*)&part[(size_t)row * D_ + c4];
    float4 o1 = *(const float4*)&part[(size_t)M_ * D_ + (size_t)row * D_ + c4];
    float4 o;
    o.x = f2tf((o0.x * w0 + o1.x * w1) * li);
    o.y = f2tf((o0.y * w0 + o1.y * w1) * li);
    o.z = f2tf((o0.z * w0 + o1.z * w1) * li);
    o.w = f2tf((o0.w * w0 + o1.w * w1) * li);
    *(float4*)&attn[(size_t)row * D_ + c4] = o;
}

// ---------------- launch -----------------------------------------------------
extern "C" void kernel_launch(void* const* d_in, const int* in_sizes, int n_in,
                              void* d_out, int out_size) {
    const int*   x       = (const int*)  d_in[0];
    const float* tok_emb = (const float*)d_in[1];
    const float* pos_emb = (const float*)d_in[2];
    const float* wq      = (const float*)d_in[3];
    const float* bq      = (const float*)d_in[4];
    const float* wk      = (const float*)d_in[5];
    const float* bk      = (const float*)d_in[6];
    const float* wv      = (const float*)d_in[7];
    const float* bv      = (const float*)d_in[8];
    const float* wo      = (const float*)d_in[9];
    const float* bo      = (const float*)d_in[10];
    const float* ln1_w   = (const float*)d_in[11];
    const float* ln1_b   = (const float*)d_in[12];
    const float* ln2_w   = (const float*)d_in[13];
    const float* ln2_b   = (const float*)d_in[14];
    const float* ffn_w1  = (const float*)d_in[15];
    const float* ffn_b1  = (const float*)d_in[16];
    const float* ffn_w2  = (const float*)d_in[17];
    const float* ffn_b2  = (const float*)d_in[18];
    const float* lnf_w   = (const float*)d_in[19];
    const float* lnf_b   = (const float*)d_in[20];
    const float* proj_w  = (const float*)d_in[21];
    const float* proj_b  = (const float*)d_in[22];
    float* logits = (float*)d_out;

    float *h, *ln, *q, *kt, *v, *attn, *mid, *part, *ml;
    float *cwq, *cwk, *cwv, *cwo, *cw1, *cw2, *cpj;
    cudaGetSymbolAddress((void**)&h,    g_h);
    cudaGetSymbolAddress((void**)&ln,   g_ln);
    cudaGetSymbolAddress((void**)&q,    g_q);
    cudaGetSymbolAddress((void**)&kt,   g_kt);
    cudaGetSymbolAddress((void**)&v,    g_v);
    cudaGetSymbolAddress((void**)&attn, g_attn);
    cudaGetSymbolAddress((void**)&mid,  g_mid);
    cudaGetSymbolAddress((void**)&part, g_part);
    cudaGetSymbolAddress((void**)&ml,   g_ml);
    cudaGetSymbolAddress((void**)&cwq,  g_cwq);
    cudaGetSymbolAddress((void**)&cwk,  g_cwk);
    cudaGetSymbolAddress((void**)&cwv,  g_cwv);
    cudaGetSymbolAddress((void**)&cwo,  g_cwo);
    cudaGetSymbolAddress((void**)&cw1,  g_cw1);
    cudaGetSymbolAddress((void**)&cw2,  g_cw2);
    cudaGetSymbolAddress((void**)&cpj,  g_cpj);

    const int SMEM128 = 3 * (128 * 36 + 32 * 136) * 4;   // 107520 B
    const int SMEM64  = 3 * (128 * 36 + 32 * 72)  * 4;   // 82944 B
    cudaFuncSetAttribute(tgemm_sk,        cudaFuncAttributeMaxDynamicSharedMemorySize, SMEM64);
    cudaFuncSetAttribute(tgemm_s<1,128,0>,cudaFuncAttributeMaxDynamicSharedMemorySize, SMEM128);
    cudaFuncSetAttribute(tgemm_s<0,128,1>,cudaFuncAttributeMaxDynamicSharedMemorySize, SMEM128);
    cudaFuncSetAttribute(tgemm_qkv,       cudaFuncAttributeMaxDynamicSharedMemorySize, SMEM128);
    cudaFuncSetAttribute(flash_attn,      cudaFuncAttributeMaxDynamicSharedMemorySize, SMEM_ATT);

    dim3 gQKV(D_ / 128, M_ / 128, 3);        // (8,16,3)
    dim3 gWO(D_ / 64, M_ / 128, 2);          // (16,16,2) split-K=2
    dim3 gFF1(M_ / 128, FF_ / 128);          // (16,32)  bm-fastest
    dim3 gFF2(D_ / 64, M_ / 128, 4);         // (16,16,4) split-K=4
    dim3 gPRJ(M_ / 128, VP_ / 128);          // (16,393) bm-fastest
    dim3 gAT(T_ / QT, H_, B_ * 2);           // (8,16,4) split-KV=2

    // Launch order: our #4 is flash_attn (ncu -s 5 lands on our 4th launch).
    conv_all<<<dim3(1024, 7), 256>>>(                                         // 1
        (const float4*)wq, (const float4*)wk, (const float4*)wv,
        (const float4*)wo, (const float4*)ffn_w1, (const float4*)ffn_w2,
        proj_w,
        (float4*)cwq, (float4*)cwk, (float4*)cwv,
        (float4*)cwo, (float4*)cw1, (float4*)cw2, cpj);
    embed_ln<<<M_, 256>>>(x, tok_emb, pos_emb, ln1_w, ln1_b, h, ln);          // 2

    for (int l = 0; l < L_; l++) {
        float* cwq_l = cwq + (size_t)l * D_ * D_;
        float* cwk_l = cwk + (size_t)l * D_ * D_;
        float* cwv_l = cwv + (size_t)l * D_ * D_;
        float* cwo_l = cwo + (size_t)l * D_ * D_;
        float* cw1_l = cw1 + (size_t)l * D_ * FF_;
        float* cw2_l = cw2 + (size_t)l * FF_ * D_;

        tgemm_qkv<<<gQKV, 256, SMEM128>>>(ln, cwq_l, cwk_l, cwv_l,
                                          bq + l * D_, bk + l * D_, bv + l * D_,
                                          q, kt, v);                          // 3 (l=0)

        flash_attn<<<gAT, 256, SMEM_ATT>>>(q, kt, v, part, ml);               // 4 (l=0)
        attn_combine<<<M_, 256>>>(part, ml, attn);

        tgemm_sk<<<gWO, 256, SMEM64>>>(attn, cwo_l, part, D_, D_ / 2, D_);
        reduce_ln<<<M_, 256>>>(h, bo + l * D_, part, 2,
                               ln2_w + l * D_, ln2_b + l * D_, ln);

        tgemm_s<1,128,0><<<gFF1, 256, SMEM128>>>(ln, cw1_l, ffn_b1 + l * FF_,
                                                 nullptr, mid, D_, FF_, FF_);

        tgemm_sk<<<gFF2, 256, SMEM64>>>(mid, cw2_l, part, FF_, FF_ / 4, D_);
        if (l + 1 < L_)
            reduce_ln<<<M_, 256>>>(h, ffn_b2 + l * D_, part, 4,
                                   ln1_w + (l + 1) * D_, ln1_b + (l + 1) * D_, ln);
        else
            reduce_ln<<<M_, 256>>>(h, ffn_b2 + l * D_, part, 4, lnf_w, lnf_b, ln);
    }

    tgemm_s<0,128,1><<<gPRJ, 256, SMEM128>>>(ln, cpj, proj_b, nullptr, logits,
                                             D_, V_, VP_);
}

// round 17
// speedup vs baseline: 2.5576x; 1.0218x over previous
#include <cuda_runtime.h>
#include <math.h>

#define B_  2
#define T_  1024
#define D_  1024
#define H_  16
#define HD_ 64
#define FF_ 4096
#define L_  6
#define V_  50257
#define M_  (B_*T_)        // 2048 rows
#define VP_ 50304          // V padded to 128
#define SML (B_*H_*T_)     // 32768 (m/l scratch stride)

// ---------------- scratch (static device globals; no allocation) -------------
__device__ float g_h   [M_*D_];
__device__ float g_ln  [M_*D_];
__device__ float g_q   [M_*D_];
__device__ float g_kt  [M_*D_];          // K stored TRANSPOSED: [(b*D + hd)*T + t]
__device__ float g_v   [M_*D_];
__device__ float g_attn[M_*D_];
__device__ float g_mid [M_*FF_];
__device__ float g_part[4*M_*D_];        // split-K partials / flash O partials
__device__ float g_ml  [4*SML];          // flash (m,l) partials
// tf32-preconverted weights (row-major [K][N])
__device__ float g_cwq [L_*D_*D_];
__device__ float g_cwk [L_*D_*D_];
__device__ float g_cwv [L_*D_*D_];
__device__ float g_cwo [L_*D_*D_];
__device__ float g_cw1 [L_*D_*FF_];
__device__ float g_cw2 [L_*FF_*D_];
__device__ float g_cpj [(size_t)D_*VP_];

__device__ __forceinline__ float f2tf(float x) {
    unsigned u;
    asm("cvt.rna.tf32.f32 %0, %1;" : "=r"(u) : "f"(x));
    return __uint_as_float(u);
}

// ---------------- single fused weight conversion -------------------------------
__global__ void conv_all(const float4* __restrict__ wq, const float4* __restrict__ wk,
                         const float4* __restrict__ wv, const float4* __restrict__ wo,
                         const float4* __restrict__ w1, const float4* __restrict__ w2,
                         const float*  __restrict__ pj,
                         float4* __restrict__ cwq, float4* __restrict__ cwk,
                         float4* __restrict__ cwv, float4* __restrict__ cwo,
                         float4* __restrict__ cw1, float4* __restrict__ cw2,
                         float*  __restrict__ cpj) {
    const int seg = blockIdx.y;
    if (seg < 6) {
        const float4* s; float4* d; int n4;
        switch (seg) {
            case 0: s = wq; d = cwq; n4 = L_*D_*D_/4;  break;
            case 1: s = wk; d = cwk; n4 = L_*D_*D_/4;  break;
            case 2: s = wv; d = cwv; n4 = L_*D_*D_/4;  break;
            case 3: s = wo; d = cwo; n4 = L_*D_*D_/4;  break;
            case 4: s = w1; d = cw1; n4 = L_*D_*FF_/4; break;
            default:s = w2; d = cw2; n4 = L_*D_*FF_/4; break;
        }
        for (int i = blockIdx.x * blockDim.x + threadIdx.x; i < n4;
             i += gridDim.x * blockDim.x) {
            float4 v = s[i];
            d[i] = make_float4(f2tf(v.x), f2tf(v.y), f2tf(v.z), f2tf(v.w));
        }
    } else {
        const long long total = (long long)D_ * VP_;
        for (long long i = (long long)blockIdx.x * blockDim.x + threadIdx.x; i < total;
             i += (long long)gridDim.x * blockDim.x) {
            int row = (int)(i / VP_), col = (int)(i - (long long)row * VP_);
            cpj[i] = (col < V_) ? f2tf(pj[(size_t)row * V_ + col]) : 0.f;
        }
    }
}

// ---------------- fused embedding + layer-0 LN1 --------------------------------
__global__ void embed_ln(const int* __restrict__ x,
                         const float* __restrict__ tok,
                         const float* __restrict__ pos,
                         const float* __restrict__ w,
                         const float* __restrict__ b,
                         float* __restrict__ h, float* __restrict__ lnout) {
    const int row  = blockIdx.x;
    const int tid  = threadIdx.x;
    const int lane = tid & 31;
    const int warp = tid >> 5;
    const int t    = row % T_;
    const int id   = x[row];
    const float* te = tok + (size_t)id * D_;
    const float* pe = pos + (size_t)t  * D_;

    float e[4];
    float s = 0.f, sq = 0.f;
    #pragma unroll
    for (int i = 0; i < 4; i++) {
        int d = tid + i * 256;
        e[i] = te[d] + pe[d];
        s += e[i]; sq += e[i] * e[i];
        h[(size_t)row * D_ + d] = e[i];
    }
    #pragma unroll
    for (int off = 16; off > 0; off >>= 1) {
        s  += __shfl_xor_sync(0xffffffffu, s,  off);
        sq += __shfl_xor_sync(0xffffffffu, sq, off);
    }
    __shared__ float ws[8], wq2[8];
    if (lane == 0) { ws[warp] = s; wq2[warp] = sq; }
    __syncthreads();
    if (warp == 0) {
        float a = (lane < 8) ? ws[lane]  : 0.f;
        float c = (lane < 8) ? wq2[lane] : 0.f;
        #pragma unroll
        for (int off = 4; off > 0; off >>= 1) {
            a += __shfl_xor_sync(0xffffffffu, a, off);
            c += __shfl_xor_sync(0xffffffffu, c, off);
        }
        if (lane == 0) { ws[0] = a; wq2[0] = c; }
    }
    __syncthreads();
    float mu  = ws[0] * (1.f / D_);
    float var = wq2[0] * (1.f / D_) - mu * mu;
    float inv = rsqrtf(var + 1e-5f);
    #pragma unroll
    for (int i = 0; i < 4; i++) {
        int d = tid + i * 256;
        lnout[(size_t)row * D_ + d] = f2tf((e[i] - mu) * inv * w[d] + b[d]);
    }
}

// ---------------- fused split-K reduce + LayerNorm ----------------------------
__global__ void reduce_ln(float* __restrict__ h, const float* __restrict__ bias,
                          const float* __restrict__ part, int nsplit,
                          const float* __restrict__ w, const float* __restrict__ b2,
                          float* __restrict__ lnout) {
    const int row  = blockIdx.x;
    const int tid  = threadIdx.x;
    const int lane = tid & 31;
    const int warp = tid >> 5;
    const int c4   = tid * 4;

    float4 acc = *(float4*)&h[(size_t)row * D_ + c4];
    float4 bv  = *(const float4*)&bias[c4];
    acc.x += bv.x; acc.y += bv.y; acc.z += bv.z; acc.w += bv.w;
    for (int s = 0; s < nsplit; s++) {
        float4 p = *(const float4*)&part[(size_t)s * M_ * D_ + (size_t)row * D_ + c4];
        acc.x += p.x; acc.y += p.y; acc.z += p.z; acc.w += p.w;
    }
    *(float4*)&h[(size_t)row * D_ + c4] = acc;

    float s = acc.x + acc.y + acc.z + acc.w;
    float sq = acc.x*acc.x + acc.y*acc.y + acc.z*acc.z + acc.w*acc.w;
    #pragma unroll
    for (int off = 16; off > 0; off >>= 1) {
        s  += __shfl_xor_sync(0xffffffffu, s,  off);
        sq += __shfl_xor_sync(0xffffffffu, sq, off);
    }
    __shared__ float ws[8], wq2[8];
    if (lane == 0) { ws[warp] = s; wq2[warp] = sq; }
    __syncthreads();
    if (warp == 0) {
        float a = (lane < 8) ? ws[lane]  : 0.f;
        float c = (lane < 8) ? wq2[lane] : 0.f;
        #pragma unroll
        for (int off = 4; off > 0; off >>= 1) {
            a += __shfl_xor_sync(0xffffffffu, a, off);
            c += __shfl_xor_sync(0xffffffffu, c, off);
        }
        if (lane == 0) { ws[0] = a; wq2[0] = c; }
    }
    __syncthreads();
    float mu  = ws[0] * (1.f / D_);
    float var = wq2[0] * (1.f / D_) - mu * mu;
    float inv = rsqrtf(var + 1e-5f);
    float4 wv4 = *(const float4*)&w[c4];
    float4 b24 = *(const float4*)&b2[c4];
    float4 o;
    o.x = f2tf((acc.x - mu) * inv * wv4.x + b24.x);
    o.y = f2tf((acc.y - mu) * inv * wv4.y + b24.y);
    o.z = f2tf((acc.z - mu) * inv * wv4.z + b24.z);
    o.w = f2tf((acc.w - mu) * inv * wv4.w + b24.w);
    *(float4*)&lnout[(size_t)row * D_ + c4] = o;
}

// ---------------- common GEMM helpers ------------------------------------------
#define CPA16(dst_u32, src_ptr) \
    asm volatile("cp.async.cg.shared.global [%0], [%1], 16;" :: "r"(dst_u32), "l"(src_ptr))

__device__ __forceinline__ unsigned smem_u32(const void* p) {
    return (unsigned)__cvta_generic_to_shared(p);
}

__device__ __forceinline__ void mma8(float c[4], const unsigned a[4], const unsigned b[2]) {
    asm volatile(
        "mma.sync.aligned.m16n8k8.row.col.f32.tf32.tf32.f32 "
        "{%0,%1,%2,%3}, {%4,%5,%6,%7}, {%8,%9}, {%0,%1,%2,%3};\n"
        : "+f"(c[0]), "+f"(c[1]), "+f"(c[2]), "+f"(c[3])
        : "r"(a[0]), "r"(a[1]), "r"(a[2]), "r"(a[3]), "r"(b[0]), "r"(b[1]));
}

// ---------------- standard GEMM body: 128 x 128, 3-stage cp.async -------------
// MODE 0:+bias 1:f2tf(relu(+bias)) 2:+bias+residual 3:raw 5:f2tf(+bias)
// MODE 6: f2tf(+bias), store TRANSPOSED to kt[(b*D+col)*T + t]
template <int BN_>
__device__ __forceinline__ void issue_stage(
    float* As, float* Bs, const float* A, const float* W,
    int lda, int Npad, int bm0, int bn0, int k0, int tid)
{
    constexpr int SB = BN_ + 8;
    #pragma unroll
    for (int j = 0; j < 4; j++) {
        int f = tid + j * 256;
        int row = f >> 3, c4 = (f & 7) << 2;
        CPA16(smem_u32(As + row * 36 + c4), A + (size_t)(bm0 + row) * lda + k0 + c4);
    }
    #pragma unroll
    for (int j = 0; j < BN_ / 32; j++) {
        int f = tid + j * 256;
        int row = (BN_ == 128) ? (f >> 5) : (f >> 4);
        int c4  = (BN_ == 128) ? ((f & 31) << 2) : ((f & 15) << 2);
        CPA16(smem_u32(Bs + row * SB + c4), W + (size_t)(k0 + row) * Npad + bn0 + c4);
    }
    asm volatile("cp.async.commit_group;");
}

template <int MODE, int BN_, int GUARD>
__device__ __forceinline__ void tgemm_body(
    const float* __restrict__ A, const float* __restrict__ W,
    const float* __restrict__ bias, const float* __restrict__ R,
    float* __restrict__ C, int lda, int KL, int N, int Npad, int bm0, int bn0)
{
    constexpr int SB  = BN_ + 8;
    constexpr int ASZ = 128 * 36;
    constexpr int BSZ = 32 * SB;
    constexpr int NI  = BN_ / 32;

    extern __shared__ float sm[];
    float* As = sm;
    float* Bs = sm + 3 * ASZ;

    const int tid  = threadIdx.x;
    const int lane = tid & 31;
    const int warp = tid >> 5;
    const int g    = lane >> 2;
    const int tg   = lane & 3;
    const int wm0  = (warp >> 2) * 64;
    const int wn0  = (warp & 3) * (BN_ / 4);

    float acc[4][NI][4];
    #pragma unroll
    for (int mi = 0; mi < 4; mi++)
        #pragma unroll
        for (int ni = 0; ni < NI; ni++)
            #pragma unroll
            for (int r = 0; r < 4; r++) acc[mi][ni][r] = 0.f;

    const int nIter = KL / 32;
    issue_stage<BN_>(As, Bs, A, W, lda, Npad, bm0, bn0, 0, tid);
    issue_stage<BN_>(As + ASZ, Bs + BSZ, A, W, lda, Npad, bm0, bn0, 32, tid);

    int st = 0, stw = 2;
    for (int t = 0; t < nIter; t++) {
        if (t + 1 < nIter) asm volatile("cp.async.wait_group 1;");
        else               asm volatile("cp.async.wait_group 0;");
        __syncthreads();

        const float* Ast = As + st * ASZ;
        const float* Bst = Bs + st * BSZ;
        #pragma unroll
        for (int kk = 0; kk < 32; kk += 8) {
            unsigned a[4][4], b[NI][2];
            #pragma unroll
            for (int mi = 0; mi < 4; mi++) {
                int r0 = wm0 + mi * 16 + g;
                a[mi][0] = __float_as_uint(Ast[(r0    ) * 36 + kk + tg]);
                a[mi][1] = __float_as_uint(Ast[(r0 + 8) * 36 + kk + tg]);
                a[mi][2] = __float_as_uint(Ast[(r0    ) * 36 + kk + tg + 4]);
                a[mi][3] = __float_as_uint(Ast[(r0 + 8) * 36 + kk + tg + 4]);
            }
            #pragma unroll
            for (int ni = 0; ni < NI; ni++) {
                int c = wn0 + ni * 8 + g;
                b[ni][0] = __float_as_uint(Bst[(kk + tg    ) * SB + c]);
                b[ni][1] = __float_as_uint(Bst[(kk + tg + 4) * SB + c]);
            }
            #pragma unroll
            for (int mi = 0; mi < 4; mi++)
                #pragma unroll
                for (int ni = 0; ni < NI; ni++)
                    mma8(acc[mi][ni], a[mi], b[ni]);
        }

        if (t + 2 < nIter) {
            issue_stage<BN_>(As + stw * ASZ, Bs + stw * BSZ, A, W, lda, Npad, bm0, bn0,
                             (t + 2) * 32, tid);
            stw = (stw == 2) ? 0 : stw + 1;
        }
        st = (st == 2) ? 0 : st + 1;
    }

    #pragma unroll
    for (int mi = 0; mi < 4; mi++) {
        #pragma unroll
        for (int ni = 0; ni < NI; ni++) {
            int row0 = bm0 + wm0 + mi * 16 + g;
            int col0 = bn0 + wn0 + ni * 8 + 2 * tg;
            #pragma unroll
            for (int rr = 0; rr < 2; rr++) {
                int row = row0 + rr * 8;
                #pragma unroll
                for (int cc = 0; cc < 2; cc++) {
                    int col = col0 + cc;
                    if (!GUARD || col < N) {
                        float v = acc[mi][ni][rr * 2 + cc];
                        if (MODE != 3) v += bias[col];
                        if (MODE == 1) v = f2tf(fmaxf(v, 0.f));
                        if (MODE == 2) v += R[(size_t)row * N + col];
                        if (MODE == 5) v = f2tf(v);
                        if (MODE == 6) {
                            C[((size_t)(row >> 10) * D_ + col) * T_ + (row & (T_ - 1))]
                                = f2tf(v);
                        } else {
                            C[(size_t)row * N + col] = v;
                        }
                    }
                }
            }
        }
    }
}

// bm-fastest grid (B-tile reuse; for N >> M GEMMs)
template <int MODE, int BN_, int GUARD>
__global__ __launch_bounds__(256, 2)
void tgemm_s(const float* __restrict__ A, const float* __restrict__ W,
             const float* __restrict__ bias, const float* __restrict__ R,
             float* __restrict__ C, int K, int N, int Npad) {
    tgemm_body<MODE, BN_, GUARD>(A, W, bias, R, C, K, K, N, Npad,
                                 blockIdx.x * 128, blockIdx.y * BN_);
}

__global__ __launch_bounds__(256, 2)
void tgemm_qkv(const float* __restrict__ A,
               const float* __restrict__ wq, const float* __restrict__ wk,
               const float* __restrict__ wv,
               const float* __restrict__ bq, const float* __restrict__ bk,
               const float* __restrict__ bv,
               float* __restrict__ q, float* __restrict__ kt, float* __restrict__ v) {
    int z = blockIdx.z;
    if (z == 0) {
        tgemm_body<5, 128, 0>(A, wq, bq, nullptr, q, D_, D_, D_, D_,
                              blockIdx.y * 128, blockIdx.x * 128);
    } else if (z == 1) {
        tgemm_body<6, 128, 0>(A, wk, bk, nullptr, kt, D_, D_, D_, D_,
                              blockIdx.y * 128, blockIdx.x * 128);
    } else {
        tgemm_body<5, 128, 0>(A, wv, bv, nullptr, v, D_, D_, D_, D_,
                              blockIdx.y * 128, blockIdx.x * 128);
    }
}

// ---------------- split-K GEMM, 2-stage, BN=64, 3 CTAs/SM ----------------------
#define SK2_ASZ (128*36)
#define SK2_BSZ (32*72)
#define SMEM_SK2 (2*(SK2_ASZ + SK2_BSZ)*4)   // 55296 B

__device__ __forceinline__ void sk2_issue(
    float* As, float* Bs, const float* A, const float* W,
    int lda, int N, int bm0, int bn0, int k0, int tid)
{
    #pragma unroll
    for (int j = 0; j < 4; j++) {
        int f = tid + j * 256;
        int row = f >> 3, c4 = (f & 7) << 2;
        CPA16(smem_u32(As + row * 36 + c4), A + (size_t)(bm0 + row) * lda + k0 + c4);
    }
    #pragma unroll
    for (int j = 0; j < 2; j++) {
        int f = tid + j * 256;
        int row = f >> 4, c4 = (f & 15) << 2;
        CPA16(smem_u32(Bs + row * 72 + c4), W + (size_t)(k0 + row) * N + bn0 + c4);
    }
    asm volatile("cp.async.commit_group;");
}

__global__ __launch_bounds__(256, 3)
void tgemm_sk2(const float* __restrict__ A, const float* __restrict__ W,
               float* __restrict__ part, int K, int KL, int N) {
    const int sp = blockIdx.z;
    A += (size_t)sp * KL;
    W += (size_t)sp * KL * N;
    float* C = part + (size_t)sp * M_ * N;

    extern __shared__ float sm[];
    float* As = sm;                    // [2][128][36]
    float* Bs = sm + 2 * SK2_ASZ;      // [2][32][72]

    const int tid  = threadIdx.x;
    const int lane = tid & 31;
    const int warp = tid >> 5;
    const int g    = lane >> 2;
    const int tg   = lane & 3;
    const int wm0  = (warp >> 2) * 64;
    const int wn0  = (warp & 3) * 16;
    const int bm0  = blockIdx.y * 128;
    const int bn0  = blockIdx.x * 64;

    float acc[4][2][4];
    #pragma unroll
    for (int mi = 0; mi < 4; mi++)
        #pragma unroll
        for (int ni = 0; ni < 2; ni++)
            #pragma unroll
            for (int r = 0; r < 4; r++) acc[mi][ni][r] = 0.f;

    const int nIter = KL / 32;
    sk2_issue(As, Bs, A, W, K, N, bm0, bn0, 0, tid);

    for (int t = 0; t < nIter; t++) {
        asm volatile("cp.async.wait_group 0;");
        __syncthreads();
        if (t + 1 < nIter) {
            int nb = (t + 1) & 1;
            sk2_issue(As + nb * SK2_ASZ, Bs + nb * SK2_BSZ, A, W, K, N,
                      bm0, bn0, (t + 1) * 32, tid);
        }
        const float* Ast = As + (t & 1) * SK2_ASZ;
        const float* Bst = Bs + (t & 1) * SK2_BSZ;
        #pragma unroll
        for (int kk = 0; kk < 32; kk += 8) {
            unsigned a[4][4], b[2][2];
            #pragma unroll
            for (int mi = 0; mi < 4; mi++) {
                int r0 = wm0 + mi * 16 + g;
                a[mi][0] = __float_as_uint(Ast[(r0    ) * 36 + kk + tg]);
                a[mi][1] = __float_as_uint(Ast[(r0 + 8) * 36 + kk + tg]);
                a[mi][2] = __float_as_uint(Ast[(r0    ) * 36 + kk + tg + 4]);
                a[mi][3] = __float_as_uint(Ast[(r0 + 8) * 36 + kk + tg + 4]);
            }
            #pragma unroll
            for (int ni = 0; ni < 2; ni++) {
                int c = wn0 + ni * 8 + g;
                b[ni][0] = __float_as_uint(Bst[(kk + tg    ) * 72 + c]);
                b[ni][1] = __float_as_uint(Bst[(kk + tg + 4) * 72 + c]);
            }
            #pragma unroll
            for (int mi = 0; mi < 4; mi++)
                #pragma unroll
                for (int ni = 0; ni < 2; ni++)
                    mma8(acc[mi][ni], a[mi], b[ni]);
        }
    }

    #pragma unroll
    for (int mi = 0; mi < 4; mi++) {
        #pragma unroll
        for (int ni = 0; ni < 2; ni++) {
            int row0 = bm0 + wm0 + mi * 16 + g;
            int col0 = bn0 + wn0 + ni * 8 + 2 * tg;
            #pragma unroll
            for (int rr = 0; rr < 2; rr++) {
                int row = row0 + rr * 8;
                *(float2*)&C[(size_t)row * N + col0] =
                    make_float2(acc[mi][ni][rr * 2 + 0], acc[mi][ni][rr * 2 + 1]);
            }
        }
    }
}

// ---------------- flash attention v6: 3 CTAs/SM, split commit groups -----------
// Single K buffer (stride 40) and single V buffer (stride 72), both conflict-free
// (stride = 8 mod 32 for B-operand frag reads). K(t+1) load overlaps PV(t);
// V(t+1) load overlaps scores(t+1).
#define QT 128
#define KT 32
#define FQ  0
#define FKT (QT*68)                    // Qs: 8704 floats
#define FVV (FKT + 64*40)              // Kt: 2560 floats
#define FPP (FVV + 32*72)              // Vs: 2304 floats
#define SMEM_ATT ((FPP + QT*36) * 4)   // + Ps 4608 -> 72704 B

__global__ __launch_bounds__(256, 3)
void flash_attn(const float* __restrict__ q,
                const float* __restrict__ kt,
                const float* __restrict__ v,
                float* __restrict__ part, float* __restrict__ ml) {
    extern __shared__ float sm[];
    float* Qs = sm + FQ;
    float* Kt = sm + FKT;
    float* Vs = sm + FVV;
    float* Ps = sm + FPP;

    const int q0   = (gridDim.x - 1 - blockIdx.x) * QT;  // longest first
    const int h    = blockIdx.y;
    const int b    = blockIdx.z >> 1;
    const int s    = blockIdx.z & 1;
    const int tid  = threadIdx.x;
    const int lane = tid & 31;
    const int warp = tid >> 5;
    const int g    = lane >> 2;
    const int tg   = lane & 3;
    const int wm   = warp * 16;

    const size_t base   = ((size_t)b * T_) * D_ + (size_t)h * HD_;
    const size_t base_k = ((size_t)b * D_ + (size_t)h * HD_) * T_;

    const int half = (q0 + QT) / 2;
    const int kvs  = s * half;
    const int nTiles = half / KT;

    #pragma unroll
    for (int i = tid; i < QT * 16; i += 256) {
        int r = i >> 4, c4 = (i & 15) << 2;
        *(float4*)&Qs[r * 68 + c4] = *(const float4*)&q[base + (size_t)(q0 + r) * D_ + c4];
    }

    float oa[8][4];
    #pragma unroll
    for (int ni = 0; ni < 8; ni++)
        #pragma unroll
        for (int r = 0; r < 4; r++) oa[ni][r] = 0.f;
    float m0 = -1e30f, m1 = -1e30f, l0 = 0.f, l1 = 0.f;

    // prologue: K0 (group A), V0 (group B)
    #pragma unroll
    for (int j = 0; j < 2; j++) {
        int f = tid + j * 256;
        int rd = f >> 3, chd = (f & 7) << 2;
        CPA16(smem_u32(Kt + rd * 40 + chd), kt + base_k + (size_t)rd * T_ + kvs + chd);
    }
    asm volatile("cp.async.commit_group;");
    #pragma unroll
    for (int j = 0; j < 2; j++) {
        int f = tid + j * 256;
        int rv = f >> 4, chv = (f & 15) << 2;
        CPA16(smem_u32(Vs + rv * 72 + chv), v + base + (size_t)(kvs + rv) * D_ + chv);
    }
    asm volatile("cp.async.commit_group;");

    for (int t0 = 0; t0 < nTiles; t0++) {
        const int s0 = kvs + t0 * KT;
        // pending: [K(t), V(t)] -> wait K
        asm volatile("cp.async.wait_group 1;");
        __syncthreads();                               // B1: K visible, V buf free

        // ---- scores: m16 n32 k64 ----
        float sf[4][4];
        #pragma unroll
        for (int ni = 0; ni < 4; ni++)
            #pragma unroll
            for (int r = 0; r < 4; r++) sf[ni][r] = 0.f;
        #pragma unroll
        for (int kk = 0; kk < 64; kk += 8) {
            unsigned a[4], bfr[4][2];
            a[0] = __float_as_uint(Qs[(wm + g    ) * 68 + kk + tg]);
            a[1] = __float_as_uint(Qs[(wm + g + 8) * 68 + kk + tg]);
            a[2] = __float_as_uint(Qs[(wm + g    ) * 68 + kk + tg + 4]);
            a[3] = __float_as_uint(Qs[(wm + g + 8) * 68 + kk + tg + 4]);
            #pragma unroll
            for (int ni = 0; ni < 4; ni++) {
                int c = ni * 8 + g;
                bfr[ni][0] = __float_as_uint(Kt[(kk + tg    ) * 40 + c]);
                bfr[ni][1] = __float_as_uint(Kt[(kk + tg + 4) * 40 + c]);
            }
            #pragma unroll
            for (int ni = 0; ni < 4; ni++)
                mma8(sf[ni], a, bfr[ni]);
        }

        // ---- mask + register softmax ----
        const int r0 = q0 + wm + g;
        const int r1 = r0 + 8;
        #pragma unroll
        for (int ni = 0; ni < 4; ni++) {
            int col = s0 + ni * 8 + 2 * tg;
            sf[ni][0] = (col     <= r0) ? sf[ni][0] * 0.125f : -1e30f;
            sf[ni][1] = (col + 1 <= r0) ? sf[ni][1] * 0.125f : -1e30f;
            sf[ni][2] = (col     <= r1) ? sf[ni][2] * 0.125f : -1e30f;
            sf[ni][3] = (col + 1 <= r1) ? sf[ni][3] * 0.125f : -1e30f;
        }
        float tm0 = -1e30f, tm1 = -1e30f;
        #pragma unroll
        for (int ni = 0; ni < 4; ni++) {
            tm0 = fmaxf(tm0, fmaxf(sf[ni][0], sf[ni][1]));
            tm1 = fmaxf(tm1, fmaxf(sf[ni][2], sf[ni][3]));
        }
        tm0 = fmaxf(tm0, __shfl_xor_sync(0xffffffffu, tm0, 1));
        tm0 = fmaxf(tm0, __shfl_xor_sync(0xffffffffu, tm0, 2));
        tm1 = fmaxf(tm1, __shfl_xor_sync(0xffffffffu, tm1, 1));
        tm1 = fmaxf(tm1, __shfl_xor_sync(0xffffffffu, tm1, 2));
        float m0n = fmaxf(m0, tm0), m1n = fmaxf(m1, tm1);
        float sc0 = __expf(m0 - m0n), sc1 = __expf(m1 - m1n);
        float ps0 = 0.f, ps1 = 0.f;
        #pragma unroll
        for (int ni = 0; ni < 4; ni++) {
            sf[ni][0] = __expf(sf[ni][0] - m0n); ps0 += sf[ni][0];
            sf[ni][1] = __expf(sf[ni][1] - m0n); ps0 += sf[ni][1];
            sf[ni][2] = __expf(sf[ni][2] - m1n); ps1 += sf[ni][2];
            sf[ni][3] = __expf(sf[ni][3] - m1n); ps1 += sf[ni][3];
        }
        ps0 += __shfl_xor_sync(0xffffffffu, ps0, 1);
        ps0 += __shfl_xor_sync(0xffffffffu, ps0, 2);
        ps1 += __shfl_xor_sync(0xffffffffu, ps1, 1);
        ps1 += __shfl_xor_sync(0xffffffffu, ps1, 2);
        l0 = l0 * sc0 + ps0;  l1 = l1 * sc1 + ps1;
        m0 = m0n;  m1 = m1n;
        #pragma unroll
        for (int ni = 0; ni < 8; ni++) {
            oa[ni][0] *= sc0; oa[ni][1] *= sc0;
            oa[ni][2] *= sc1; oa[ni][3] *= sc1;
        }

        #pragma unroll
        for (int ni = 0; ni < 4; ni++) {
            int cb = ni * 8 + 2 * tg;
            Ps[(wm + g    ) * 36 + cb    ] = f2tf(sf[ni][0]);
            Ps[(wm + g    ) * 36 + cb + 1] = f2tf(sf[ni][1]);
            Ps[(wm + g + 8) * 36 + cb    ] = f2tf(sf[ni][2]);
            Ps[(wm + g + 8) * 36 + cb + 1] = f2tf(sf[ni][3]);
        }
        __syncwarp();

        // pending: [V(t)] -> wait V
        asm volatile("cp.async.wait_group 0;");
        __syncthreads();                               // B2: V visible, K consumed

        // prefetch K(t+1) (overlaps PV)
        if (t0 + 1 < nTiles) {
            const int ns0 = s0 + KT;
            #pragma unroll
            for (int j = 0; j < 2; j++) {
                int f = tid + j * 256;
                int rd = f >> 3, chd = (f & 7) << 2;
                CPA16(smem_u32(Kt + rd * 40 + chd),
                      kt + base_k + (size_t)rd * T_ + ns0 + chd);
            }
            asm volatile("cp.async.commit_group;");
        }

        // ---- P @ V: m16 n64 k32 ----
        #pragma unroll
        for (int kk = 0; kk < KT; kk += 8) {
            unsigned a2[4], b2[2];
            a2[0] = __float_as_uint(Ps[(wm + g    ) * 36 + kk + tg]);
            a2[1] = __float_as_uint(Ps[(wm + g + 8) * 36 + kk + tg]);
            a2[2] = __float_as_uint(Ps[(wm + g    ) * 36 + kk + tg + 4]);
            a2[3] = __float_as_uint(Ps[(wm + g + 8) * 36 + kk + tg + 4]);
            #pragma unroll
            for (int ni = 0; ni < 8; ni++) {
                int c = ni * 8 + g;
                b2[0] = __float_as_uint(Vs[(kk + tg    ) * 72 + c]);
                b2[1] = __float_as_uint(Vs[(kk + tg + 4) * 72 + c]);
                mma8(oa[ni], a2, b2);
            }
        }
        __syncthreads();                               // B3: V consumed

        // prefetch V(t+1) (overlaps next scores)
        if (t0 + 1 < nTiles) {
            const int ns0 = s0 + KT;
            #pragma unroll
            for (int j = 0; j < 2; j++) {
                int f = tid + j * 256;
                int rv = f >> 4, chv = (f & 15) << 2;
                CPA16(smem_u32(Vs + rv * 72 + chv),
                      v + base + (size_t)(ns0 + rv) * D_ + chv);
            }
            asm volatile("cp.async.commit_group;");
        }
    }

    // ---- epilogue: raw partial O + (m,l) ----
    float* po = part + (size_t)s * M_ * D_;
    const int r0 = q0 + wm + g;
    const int r1 = r0 + 8;
    if (tg == 0) {
        size_t mlrow0 = ((size_t)b * H_ + h) * T_ + r0;
        size_t mlrow1 = ((size_t)b * H_ + h) * T_ + r1;
        ml[(s * 2 + 0) * SML + mlrow0] = m0;
        ml[(s * 2 + 1) * SML + mlrow0] = l0;
        ml[(s * 2 + 0) * SML + mlrow1] = m1;
        ml[(s * 2 + 1) * SML + mlrow1] = l1;
    }
    #pragma unroll
    for (int ni = 0; ni < 8; ni++) {
        int col = ni * 8 + 2 * tg;
        *(float2*)&po[base + (size_t)r0 * D_ + col] = make_float2(oa[ni][0], oa[ni][1]);
        *(float2*)&po[base + (size_t)r1 * D_ + col] = make_float2(oa[ni][2], oa[ni][3]);
    }
}

// combine the two KV-splits: O = (O0*e^{m0-m} + O1*e^{m1-m}) / l
__global__ void attn_combine(const float* __restrict__ part,
                             const float* __restrict__ ml,
                             float* __restrict__ attn) {
    const int row = blockIdx.x;
    const int b   = row >> 10;
    const int t   = row & (T_ - 1);
    const int c4  = threadIdx.x * 4;
    const int h   = c4 >> 6;

    size_t mlrow = ((size_t)b * H_ + h) * T_ + t;
    float m0 = ml[0 * SML + mlrow], l0 = ml[1 * SML + mlrow];
    float m1 = ml[2 * SML + mlrow], l1 = ml[3 * SML + mlrow];
    float m  = fmaxf(m0, m1);
    float w0 = __expf(m0 - m), w1 = __expf(m1 - m);
    float li = 1.f / (l0 * w0 + l1 * w1);

    float4 o0 = *(const float4*)&part[(size_t)row * D_ + c4];
    float4 o1 = *(const float4*)&part[(size_t)M_ * D_ + (size_t)row * D_ + c4];
    float4 o;
    o.x = f2tf((o0.x * w0 + o1.x * w1) * li);
    o.y = f2tf((o0.y * w0 + o1.y * w1) * li);
    o.z = f2tf((o0.z * w0 + o1.z * w1) * li);
    o.w = f2tf((o0.w * w0 + o1.w * w1) * li);
    *(float4*)&attn[(size_t)row * D_ + c4] = o;
}

// ---------------- launch -----------------------------------------------------
extern "C" void kernel_launch(void* const* d_in, const int* in_sizes, int n_in,
                              void* d_out, int out_size) {
    const int*   x       = (const int*)  d_in[0];
    const float* tok_emb = (const float*)d_in[1];
    const float* pos_emb = (const float*)d_in[2];
    const float* wq      = (const float*)d_in[3];
    const float* bq      = (const float*)d_in[4];
    const float* wk      = (const float*)d_in[5];
    const float* bk      = (const float*)d_in[6];
    const float* wv      = (const float*)d_in[7];
    const float* bv      = (const float*)d_in[8];
    const float* wo      = (const float*)d_in[9];
    const float* bo      = (const float*)d_in[10];
    const float* ln1_w   = (const float*)d_in[11];
    const float* ln1_b   = (const float*)d_in[12];
    const float* ln2_w   = (const float*)d_in[13];
    const float* ln2_b   = (const float*)d_in[14];
    const float* ffn_w1  = (const float*)d_in[15];
    const float* ffn_b1  = (const float*)d_in[16];
    const float* ffn_w2  = (const float*)d_in[17];
    const float* ffn_b2  = (const float*)d_in[18];
    const float* lnf_w   = (const float*)d_in[19];
    const float* lnf_b   = (const float*)d_in[20];
    const float* proj_w  = (const float*)d_in[21];
    const float* proj_b  = (const float*)d_in[22];
    float* logits = (float*)d_out;

    float *h, *ln, *q, *kt, *v, *attn, *mid, *part, *ml;
    float *cwq, *cwk, *cwv, *cwo, *cw1, *cw2, *cpj;
    cudaGetSymbolAddress((void**)&h,    g_h);
    cudaGetSymbolAddress((void**)&ln,   g_ln);
    cudaGetSymbolAddress((void**)&q,    g_q);
    cudaGetSymbolAddress((void**)&kt,   g_kt);
    cudaGetSymbolAddress((void**)&v,    g_v);
    cudaGetSymbolAddress((void**)&attn, g_attn);
    cudaGetSymbolAddress((void**)&mid,  g_mid);
    cudaGetSymbolAddress((void**)&part, g_part);
    cudaGetSymbolAddress((void**)&ml,   g_ml);
    cudaGetSymbolAddress((void**)&cwq,  g_cwq);
    cudaGetSymbolAddress((void**)&cwk,  g_cwk);
    cudaGetSymbolAddress((void**)&cwv,  g_cwv);
    cudaGetSymbolAddress((void**)&cwo,  g_cwo);
    cudaGetSymbolAddress((void**)&cw1,  g_cw1);
    cudaGetSymbolAddress((void**)&cw2,  g_cw2);
    cudaGetSymbolAddress((void**)&cpj,  g_cpj);

    const int SMEM128 = 3 * (128 * 36 + 32 * 136) * 4;   // 107520 B
    cudaFuncSetAttribute(tgemm_sk2,       cudaFuncAttributeMaxDynamicSharedMemorySize, SMEM_SK2);
    cudaFuncSetAttribute(tgemm_s<1,128,0>,cudaFuncAttributeMaxDynamicSharedMemorySize, SMEM128);
    cudaFuncSetAttribute(tgemm_s<0,128,1>,cudaFuncAttributeMaxDynamicSharedMemorySize, SMEM128);
    cudaFuncSetAttribute(tgemm_qkv,       cudaFuncAttributeMaxDynamicSharedMemorySize, SMEM128);
    cudaFuncSetAttribute(flash_attn,      cudaFuncAttributeMaxDynamicSharedMemorySize, SMEM_ATT);

    dim3 gQKV(D_ / 128, M_ / 128, 3);        // (8,16,3)
    dim3 gWO(D_ / 64, M_ / 128, 2);          // (16,16,2) split-K=2
    dim3 gFF1(M_ / 128, FF_ / 128);          // (16,32)  bm-fastest
    dim3 gFF2(D_ / 64, M_ / 128, 4);         // (16,16,4) split-K=4
    dim3 gPRJ(M_ / 128, VP_ / 128);          // (16,393) bm-fastest
    dim3 gAT(T_ / QT, H_, B_ * 2);           // (8,16,4) split-KV=2

    // Launch order: our #4 is flash_attn (ncu -s 5 lands on our 4th launch).
    conv_all<<<dim3(1024, 7), 256>>>(                                         // 1
        (const float4*)wq, (const float4*)wk, (const float4*)wv,
        (const float4*)wo, (const float4*)ffn_w1, (const float4*)ffn_w2,
        proj_w,
        (float4*)cwq, (float4*)cwk, (float4*)cwv,
        (float4*)cwo, (float4*)cw1, (float4*)cw2, cpj);
    embed_ln<<<M_, 256>>>(x, tok_emb, pos_emb, ln1_w, ln1_b, h, ln);          // 2

    for (int l = 0; l < L_; l++) {
        float* cwq_l = cwq + (size_t)l * D_ * D_;
        float* cwk_l = cwk + (size_t)l * D_ * D_;
        float* cwv_l = cwv + (size_t)l * D_ * D_;
        float* cwo_l = cwo + (size_t)l * D_ * D_;
        float* cw1_l = cw1 + (size_t)l * D_ * FF_;
        float* cw2_l = cw2 + (size_t)l * FF_ * D_;

        tgemm_qkv<<<gQKV, 256, SMEM128>>>(ln, cwq_l, cwk_l, cwv_l,
                                          bq + l * D_, bk + l * D_, bv + l * D_,
                                          q, kt, v);                          // 3 (l=0)

        flash_attn<<<gAT, 256, SMEM_ATT>>>(q, kt, v, part, ml);               // 4 (l=0)
        attn_combine<<<M_, 256>>>(part, ml, attn);

        tgemm_sk2<<<gWO, 256, SMEM_SK2>>>(attn, cwo_l, part, D_, D_ / 2, D_);
        reduce_ln<<<M_, 256>>>(h, bo + l * D_, part, 2,
                               ln2_w + l * D_, ln2_b + l * D_, ln);

        tgemm_s<1,128,0><<<gFF1, 256, SMEM128>>>(ln, cw1_l, ffn_b1 + l * FF_,
                                                 nullptr, mid, D_, FF_, FF_);

        tgemm_sk2<<<gFF2, 256, SMEM_SK2>>>(mid, cw2_l, part, FF_, FF_ / 4, D_);
        if (l + 1 < L_)
            reduce_ln<<<M_, 256>>>(h, ffn_b2 + l * D_, part, 4,
                                   ln1_w + (l + 1) * D_, ln1_b + (l + 1) * D_, ln);
        else
            reduce_ln<<<M_, 256>>>(h, ffn_b2 + l * D_, part, 4, lnf_w, lnf_b, ln);
    }

    tgemm_s<0,128,1><<<gPRJ, 256, SMEM128>>>(ln, cpj, proj_b, nullptr, logits,
                                             D_, V_, VP_);
}